// round 6
// baseline (speedup 1.0000x reference)
#include <cuda_runtime.h>
#include <cstdint>
#include <math.h>

#define NB 2
#define CC 256
#define RCQ 32
#define HH 64
#define WW 64
#define HWP 4096
#define C2 512
#define KCOL 4608
#define MPROJ 320

// ---------------- scratch ----------------
__device__ float g_proj[(size_t)2 * NB * MPROJ * HWP];     // [mod][batch][320][4096]
__device__ float g_invZ[4 * HWP];                          // [attn*2+batch][4096]
__device__ float g_expS[(size_t)4 * HWP * HWP];            // [attn*2+batch][i][j], 268MB
__device__ float g_vz[(size_t)4 * CC * HWP];               // scaled V, packed [attn*2+batch]
__device__ float g_cat[(size_t)NB * C2 * HWP];
__device__ float g_fy[(size_t)NB * 1024 * HWP];            // rows 0-511 f, 512-1023 y2
__device__ float g_y1[(size_t)NB * C2 * HWP];
__device__ float g_col[(size_t)NB * KCOL * HWP];
// tf32 weights
__device__ float g_wR[MPROJ * CC];
__device__ float g_wD[MPROJ * CC];
__device__ float g_bR[MPROJ];
__device__ float g_bD[MPROJ];
__device__ float g_wGate[CC * C2];
__device__ float g_wF1[C2 * C2];
__device__ float g_wF2[C2 * KCOL];
__device__ float g_wHead[CC * 1024];
__device__ float g_bHead[CC];

// ---------------- helpers ----------------
__device__ __forceinline__ void cp16(uint32_t dst, const void* src, bool v) {
    int sz = v ? 16 : 0;
    asm volatile("cp.async.cg.shared.global [%0], [%1], 16, %2;\n"
                 :: "r"(dst), "l"(src), "r"(sz));
}
__device__ __forceinline__ uint32_t cvt_tf32(float x) {
    uint32_t r;
    asm("cvt.rna.tf32.f32 %0, %1;" : "=r"(r) : "f"(x));
    return r;
}
__device__ __forceinline__ float tf32f(float x) { return __uint_as_float(cvt_tf32(x)); }
__device__ __forceinline__ void mma8(float* c, const uint32_t* a, uint32_t b0, uint32_t b1) {
    asm volatile(
        "mma.sync.aligned.m16n8k8.row.col.f32.tf32.tf32.f32 "
        "{%0,%1,%2,%3}, {%4,%5,%6,%7}, {%8,%9}, {%0,%1,%2,%3};"
        : "+f"(c[0]), "+f"(c[1]), "+f"(c[2]), "+f"(c[3])
        : "r"(a[0]), "r"(a[1]), "r"(a[2]), "r"(a[3]), "r"(b0), "r"(b1));
}

// ---------------- single prep kernel: all weight cvt + concat + biases ----------------
struct PrepPtrs {
    const float *rq_w, *rk_w, *rv_w, *dq_w, *dk_w, *dv_w;
    const float *gate_w, *fus1_w, *fus2_w, *fus3_w, *skip_w;
    const float *rq_b, *rk_b, *rv_b, *dq_b, *dk_b, *dv_b, *fus3_b, *skip_b;
    float *wR, *wD, *wGate, *wF1, *wF2, *wHead, *bR, *bD, *bHead;
};
#define PREP_TOT 3179392
__global__ void __launch_bounds__(256) prep_k(PrepPtrs p) {
    int i = blockIdx.x * 256 + threadIdx.x;
    if (i >= PREP_TOT) return;
    if (i < 8192)            p.wR[i] = tf32f(p.rq_w[i]);
    else if (i < 16384)      p.wR[i] = tf32f(p.rk_w[i - 8192]);
    else if (i < 81920)      p.wR[i] = tf32f(p.rv_w[i - 16384]);
    else if (i < 90112)      p.wD[i - 81920] = tf32f(p.dq_w[i - 81920]);
    else if (i < 98304)      p.wD[i - 81920] = tf32f(p.dk_w[i - 90112]);
    else if (i < 163840)     p.wD[i - 81920] = tf32f(p.dv_w[i - 98304]);
    else if (i < 294912)     p.wGate[i - 163840] = tf32f(p.gate_w[i - 163840]);
    else if (i < 557056)     p.wF1[i - 294912] = tf32f(p.fus1_w[i - 294912]);
    else if (i < 2916352)    p.wF2[i - 557056] = tf32f(p.fus2_w[i - 557056]);
    else if (i < 3178496) {
        int j = i - 2916352;
        int m = j >> 10, k = j & 1023;
        float v = (k < 512) ? p.skip_w[m * 512 + k] : p.fus3_w[m * 512 + k - 512];
        p.wHead[j] = tf32f(v);
    } else if (i < 3178816) {
        int j = i - 3178496;
        p.bR[j] = (j < 32) ? p.rq_b[j] : (j < 64) ? p.rk_b[j - 32] : p.rv_b[j - 64];
    } else if (i < 3179136) {
        int j = i - 3178816;
        p.bD[j] = (j < 32) ? p.dq_b[j] : (j < 64) ? p.dk_b[j - 32] : p.dv_b[j - 64];
    } else {
        int j = i - 3179136;
        p.bHead[j] = p.fus3_b[j] + p.skip_b[j];
    }
}

// ---------------- TF32 GEMM ----------------
#define FL_ACC  1
#define FL_RELU 2
#define FL_RES  4
#define FL_BIAS 8
#define FL_GATE 16
#define FL_CVTO 32
#define FL_DUAL 64

#define ASTR 36
#define BSTR 136
#define ABUF (128 * ASTR)
#define BBUF (32 * BSTR)
#define SMEM_BYTES ((2 * ABUF + 2 * BBUF) * 4)   // 71680

template <int F>
__global__ void __launch_bounds__(256, 2) tgemm_k(
    const float* __restrict__ A, const float* __restrict__ A2, int lda, size_t sA,
    const float* __restrict__ B, const float* __restrict__ B2, int ldb, size_t sB,
    float* __restrict__ C, size_t sC, size_t cSelOff,
    const float* __restrict__ bias, const float* __restrict__ bias2,
    const float* __restrict__ res, const float* __restrict__ res2, size_t sRes,
    int M, int N, int K)
{
    extern __shared__ float sm[];
    const int bz = blockIdx.z;
    const int sel   = (F & FL_DUAL) ? (bz >> 1) : 0;
    const int batch = (F & FL_DUAL) ? (bz & 1) : bz;
    const float* Ap = (((F & FL_DUAL) && sel) ? A2 : A) + (size_t)batch * sA;
    const float* Bp = (((F & FL_DUAL) && sel) ? B2 : B) + (size_t)batch * sB;
    C += (size_t)batch * sC + (sel ? cSelOff : 0);
    const float* biasp = (((F & FL_DUAL) && sel) ? bias2 : bias);
    const float* resp = (((F & FL_DUAL) && sel) ? res2 : res);
    if (resp) resp += (size_t)batch * sRes;

    const int m0 = blockIdx.y * 128, n0 = blockIdx.x * 128;
    const int tid = threadIdx.x;
    const int lane = tid & 31, warp = tid >> 5;
    const int g = lane >> 2, t4 = lane & 3;
    const int wm = (warp >> 2) * 64;
    const int wn = (warp & 3) * 32;

    const uint32_t sbase = (uint32_t)__cvta_generic_to_shared(sm);

    float acc[4][4][4];
#pragma unroll
    for (int mt = 0; mt < 4; mt++)
#pragma unroll
        for (int nt = 0; nt < 4; nt++)
#pragma unroll
            for (int i = 0; i < 4; i++) acc[mt][nt][i] = 0.f;

    auto loadA = [&](int buf, int k0) {
#pragma unroll
        for (int i = 0; i < 4; i++) {
            int c = tid + i * 256;
            int m = c >> 3, kg = c & 7;
            bool v = (m0 + m) < M;
            int mm = v ? (m0 + m) : 0;
            const float* src = Ap + (size_t)mm * lda + k0 + kg * 4;
            uint32_t dst = sbase + (uint32_t)((buf * ABUF + m * ASTR + kg * 4) * 4);
            cp16(dst, src, v);
        }
    };
    auto loadB = [&](int buf, int k0) {
#pragma unroll
        for (int i = 0; i < 4; i++) {
            int c = tid + i * 256;
            int k = c >> 5, ng = c & 31;
            const float* src = Bp + (size_t)(k0 + k) * ldb + n0 + ng * 4;
            uint32_t dst = sbase + (uint32_t)((2 * ABUF + buf * BBUF + k * BSTR + ng * 4) * 4);
            cp16(dst, src, true);
        }
    };

    const int KT = K / 32;
    loadA(0, 0);
    loadB(0, 0);
    asm volatile("cp.async.commit_group;\n");

    int cur = 0;
    for (int kt = 0; kt < KT; kt++) {
        if (kt + 1 < KT) {
            loadA(cur ^ 1, (kt + 1) * 32);
            loadB(cur ^ 1, (kt + 1) * 32);
            asm volatile("cp.async.commit_group;\n");
            asm volatile("cp.async.wait_group 1;\n");
        } else {
            asm volatile("cp.async.wait_group 0;\n");
        }
        __syncthreads();

        const float* Ab = sm + cur * ABUF;
        const float* Bb = sm + 2 * ABUF + cur * BBUF;
#pragma unroll
        for (int ks = 0; ks < 4; ks++) {
            const int kk = ks * 8;
            uint32_t af[4][4];
#pragma unroll
            for (int mt = 0; mt < 4; mt++) {
                int r0 = wm + mt * 16 + g;
                af[mt][0] = __float_as_uint(Ab[r0 * ASTR + kk + t4]);
                af[mt][1] = __float_as_uint(Ab[(r0 + 8) * ASTR + kk + t4]);
                af[mt][2] = __float_as_uint(Ab[r0 * ASTR + kk + t4 + 4]);
                af[mt][3] = __float_as_uint(Ab[(r0 + 8) * ASTR + kk + t4 + 4]);
            }
#pragma unroll
            for (int nt = 0; nt < 4; nt++) {
                int cb = wn + nt * 8 + g;
                uint32_t b0 = __float_as_uint(Bb[(kk + t4) * BSTR + cb]);
                uint32_t b1 = __float_as_uint(Bb[(kk + t4 + 4) * BSTR + cb]);
#pragma unroll
                for (int mt = 0; mt < 4; mt++) mma8(acc[mt][nt], af[mt], b0, b1);
            }
        }
        __syncthreads();
        cur ^= 1;
    }

#pragma unroll
    for (int mt = 0; mt < 4; mt++) {
        int r0 = m0 + wm + mt * 16 + g;
#pragma unroll
        for (int nt = 0; nt < 4; nt++) {
            int cb = n0 + wn + nt * 8 + 2 * t4;
            const float* a4 = acc[mt][nt];
#pragma unroll
            for (int half = 0; half < 2; half++) {
                int r = r0 + half * 8;
                if (r >= M) continue;
                float bv = (F & FL_BIAS) ? biasp[r] : 0.f;
#pragma unroll
                for (int j = 0; j < 2; j++) {
                    size_t idx = (size_t)r * N + cb + j;
                    float v = a4[half * 2 + j] + bv;
                    if (F & FL_GATE) {
                        float a = resp[idx];
                        float b2 = resp[idx + (size_t)CC * N];
                        float gg = 1.f / (1.f + __expf(-v));
                        C[idx] = tf32f(a * gg + b2 * (1.f - gg));
                        C[idx + (size_t)CC * N] = tf32f(a * b2);
                    } else {
                        if (F & FL_RES) v += resp[idx];
                        if (F & FL_ACC) v += C[idx];
                        if (F & FL_RELU) v = fmaxf(v, 0.f);
                        if (F & FL_CVTO) v = tf32f(v);
                        C[idx] = v;
                    }
                }
            }
        }
    }
}

#define P_PROJ  (FL_BIAS | FL_CVTO | FL_DUAL)
#define P_APPLY (FL_RES | FL_CVTO | FL_DUAL)
#define P_GATE  (FL_BIAS | FL_GATE)
#define P_FUS   (FL_BIAS | FL_RELU | FL_CVTO)
#define P_HEAD  (FL_BIAS)

// ---------------- z pass: invZ + expS store; both attentions (grid.z) ----------------
__global__ void __launch_bounds__(256) attn_z_k(
    const float* __restrict__ Q0, const float* __restrict__ K0,
    const float* __restrict__ Q1, const float* __restrict__ K1,
    float* __restrict__ invZ, float* __restrict__ expS)
{
    __shared__ float dqT[64 * 36];
    __shared__ float dkS[2 * 32 * 136];
    __shared__ float zred[4][64];

    const int sel = blockIdx.z, b = blockIdx.y;
    const size_t sP = (size_t)MPROJ * HWP;
    const float* Q    = (sel ? Q1 : Q0) + (size_t)b * sP;
    const float* Kmat = (sel ? K1 : K0) + (size_t)b * sP;
    const int gi = sel * NB + b;
    invZ += (size_t)gi * HWP;
    expS += (size_t)gi * HWP * HWP;

    const int i0 = blockIdx.x * 64;
    const int tid = threadIdx.x;
    const int lane = tid & 31, warp = tid >> 5;
    const int g = lane >> 2, t4 = lane & 3;
    const uint32_t dkbase = (uint32_t)__cvta_generic_to_shared(dkS);

#pragma unroll
    for (int rep = 0; rep < 8; rep++) {
        int idx = tid + rep * 256;
        int r = idx >> 6, ii = idx & 63;
        dqT[ii * 36 + r] = Q[(size_t)r * HWP + i0 + ii];
    }
    auto loadK = [&](int buf, int j0) {
#pragma unroll
        for (int rep = 0; rep < 4; rep++) {
            int c = tid + rep * 256;
            int r = c >> 5, jg = c & 31;
            const float* src = Kmat + (size_t)r * HWP + j0 + jg * 4;
            uint32_t dst = dkbase + (uint32_t)((buf * 32 * 136 + r * 136 + jg * 4) * 4);
            cp16(dst, src, true);
        }
    };
    loadK(0, 0);
    asm volatile("cp.async.commit_group;\n");

    float zacc[2][2] = {{0.f, 0.f}, {0.f, 0.f}};
    const int wm = (warp >> 2) * 32, wn = (warp & 3) * 32;

    for (int jc = 0; jc < 32; jc++) {
        int cur = jc & 1;
        asm volatile("cp.async.wait_group 0;\n");
        __syncthreads();
        if (jc + 1 < 32) {
            loadK(cur ^ 1, (jc + 1) * 128);
            asm volatile("cp.async.commit_group;\n");
        }
        const float* dk = dkS + cur * 32 * 136;
        float sacc[2][4][4];
#pragma unroll
        for (int mt = 0; mt < 2; mt++)
#pragma unroll
            for (int nt = 0; nt < 4; nt++)
#pragma unroll
                for (int e = 0; e < 4; e++) sacc[mt][nt][e] = 0.f;
#pragma unroll
        for (int ks = 0; ks < 4; ks++) {
            int kk = ks * 8;
            uint32_t a[2][4];
#pragma unroll
            for (int mt = 0; mt < 2; mt++) {
                int r0 = wm + mt * 16 + g;
                a[mt][0] = __float_as_uint(dqT[r0 * 36 + kk + t4]);
                a[mt][1] = __float_as_uint(dqT[(r0 + 8) * 36 + kk + t4]);
                a[mt][2] = __float_as_uint(dqT[r0 * 36 + kk + t4 + 4]);
                a[mt][3] = __float_as_uint(dqT[(r0 + 8) * 36 + kk + t4 + 4]);
            }
#pragma unroll
            for (int nt = 0; nt < 4; nt++) {
                int cb = wn + nt * 8 + g;
                uint32_t b0 = __float_as_uint(dk[(kk + t4) * 136 + cb]);
                uint32_t b1 = __float_as_uint(dk[(kk + t4 + 4) * 136 + cb]);
#pragma unroll
                for (int mt = 0; mt < 2; mt++) mma8(sacc[mt][nt], a[mt], b0, b1);
            }
        }
        // exp, accumulate Z, store expS (tf32-rounded)
#pragma unroll
        for (int mt = 0; mt < 2; mt++) {
            int ra = i0 + wm + mt * 16 + g;
#pragma unroll
            for (int nt = 0; nt < 4; nt++) {
                int j = jc * 128 + wn + nt * 8 + 2 * t4;
                float e0 = __expf(sacc[mt][nt][0]);
                float e1 = __expf(sacc[mt][nt][1]);
                float e2 = __expf(sacc[mt][nt][2]);
                float e3 = __expf(sacc[mt][nt][3]);
                zacc[mt][0] += e0 + e1;
                zacc[mt][1] += e2 + e3;
                *reinterpret_cast<float2*>(expS + (size_t)ra * HWP + j) =
                    make_float2(tf32f(e0), tf32f(e1));
                *reinterpret_cast<float2*>(expS + (size_t)(ra + 8) * HWP + j) =
                    make_float2(tf32f(e2), tf32f(e3));
            }
        }
    }
#pragma unroll
    for (int mt = 0; mt < 2; mt++)
#pragma unroll
        for (int h = 0; h < 2; h++) {
            float v = zacc[mt][h];
            v += __shfl_xor_sync(0xffffffffu, v, 1);
            v += __shfl_xor_sync(0xffffffffu, v, 2);
            if (t4 == 0) zred[warp & 3][wm + mt * 16 + h * 8 + g] = v;
        }
    __syncthreads();
    if (tid < 64) {
        float s = zred[0][tid] + zred[1][tid] + zred[2][tid] + zred[3][tid];
        invZ[i0 + tid] = 1.f / s;
    }
}

// ---------------- vz = V * invZ (packed [attn*2+batch][256][4096], tf32) ----------------
__global__ void __launch_bounds__(256) scalev_k(
    const float* __restrict__ projR, const float* __restrict__ projD,
    const float* __restrict__ invZ, float* __restrict__ vz)
{
    size_t idx = (size_t)blockIdx.x * 256 + threadIdx.x;   // 4*CC*HWP
    int gi = (int)(idx / ((size_t)CC * HWP));
    int sel = gi >> 1, b = gi & 1;
    int c = (int)((idx / HWP) % CC);
    int i = (int)(idx % HWP);
    const float* src = (sel ? projD : projR)
        + (size_t)b * MPROJ * HWP + (size_t)(2 * RCQ + c) * HWP + i;
    vz[idx] = tf32f(*src * invZ[(size_t)gi * HWP + i]);
}

// ---------------- im2col ----------------
__global__ void __launch_bounds__(256) im2col_k(
    const float* __restrict__ in, float* __restrict__ col)
{
    size_t idx = (size_t)blockIdx.x * 256 + threadIdx.x;
    int p = (int)(idx % HWP);
    size_t t = idx / HWP;
    int row = (int)(t % KCOL);
    int n = (int)(t / KCOL);
    int tap = row % 9, ci = row / 9;
    int ky = tap / 3, kx = tap % 3;
    int y = p >> 6, x = p & 63;
    int yy = y + ky - 1, xx = x + kx - 1;
    float v = 0.f;
    if (yy >= 0 && yy < HH && xx >= 0 && xx < WW)
        v = in[(((size_t)n * C2 + ci) * HH + yy) * WW + xx];
    col[idx] = v;
}

// ---------------- host launcher ----------------
extern "C" void kernel_launch(void* const* d_in, const int* in_sizes, int n_in,
                              void* d_out, int out_size)
{
    const float* rgb  = (const float*)d_in[0];
    const float* chm  = (const float*)d_in[1];
    float* out = (float*)d_out;

    float *proj, *invZ, *expS, *vz, *cat, *fy, *y1, *col;
    float *wR, *wD, *bR, *bD, *wGate, *wF1, *wF2, *wHead, *bHead;
    cudaGetSymbolAddress((void**)&proj, g_proj);
    cudaGetSymbolAddress((void**)&invZ, g_invZ);
    cudaGetSymbolAddress((void**)&expS, g_expS);
    cudaGetSymbolAddress((void**)&vz, g_vz);
    cudaGetSymbolAddress((void**)&cat, g_cat);
    cudaGetSymbolAddress((void**)&fy, g_fy);
    cudaGetSymbolAddress((void**)&y1, g_y1);
    cudaGetSymbolAddress((void**)&col, g_col);
    cudaGetSymbolAddress((void**)&wR, g_wR);
    cudaGetSymbolAddress((void**)&wD, g_wD);
    cudaGetSymbolAddress((void**)&bR, g_bR);
    cudaGetSymbolAddress((void**)&bD, g_bD);
    cudaGetSymbolAddress((void**)&wGate, g_wGate);
    cudaGetSymbolAddress((void**)&wF1, g_wF1);
    cudaGetSymbolAddress((void**)&wF2, g_wF2);
    cudaGetSymbolAddress((void**)&wHead, g_wHead);
    cudaGetSymbolAddress((void**)&bHead, g_bHead);

    cudaFuncSetAttribute(tgemm_k<P_PROJ>,  cudaFuncAttributeMaxDynamicSharedMemorySize, SMEM_BYTES);
    cudaFuncSetAttribute(tgemm_k<P_APPLY>, cudaFuncAttributeMaxDynamicSharedMemorySize, SMEM_BYTES);
    cudaFuncSetAttribute(tgemm_k<P_GATE>,  cudaFuncAttributeMaxDynamicSharedMemorySize, SMEM_BYTES);
    cudaFuncSetAttribute(tgemm_k<P_FUS>,   cudaFuncAttributeMaxDynamicSharedMemorySize, SMEM_BYTES);
    cudaFuncSetAttribute(tgemm_k<P_HEAD>,  cudaFuncAttributeMaxDynamicSharedMemorySize, SMEM_BYTES);

    dim3 blk(256);
    const size_t sX = (size_t)CC * HWP;
    const size_t sF = (size_t)C2 * HWP;
    const size_t sP = (size_t)MPROJ * HWP;
    const size_t sS = (size_t)HWP * HWP;
    const size_t s1024 = (size_t)1024 * HWP;
    const size_t sCol = (size_t)KCOL * HWP;

    // --- prep (single kernel) ---
    PrepPtrs pp;
    pp.rq_w = (const float*)d_in[2];  pp.rq_b = (const float*)d_in[3];
    pp.rk_w = (const float*)d_in[4];  pp.rk_b = (const float*)d_in[5];
    pp.rv_w = (const float*)d_in[6];  pp.rv_b = (const float*)d_in[7];
    pp.dq_w = (const float*)d_in[8];  pp.dq_b = (const float*)d_in[9];
    pp.dk_w = (const float*)d_in[10]; pp.dk_b = (const float*)d_in[11];
    pp.gate_w = (const float*)d_in[14];
    pp.fus1_w = (const float*)d_in[16];
    pp.fus2_w = (const float*)d_in[18];
    pp.fus3_w = (const float*)d_in[20]; pp.fus3_b = (const float*)d_in[21];
    pp.skip_w = (const float*)d_in[22]; pp.skip_b = (const float*)d_in[23];
    pp.dv_w = (const float*)d_in[12]; pp.dv_b = (const float*)d_in[13];
    pp.wR = wR; pp.wD = wD; pp.wGate = wGate; pp.wF1 = wF1; pp.wF2 = wF2;
    pp.wHead = wHead; pp.bR = bR; pp.bD = bD; pp.bHead = bHead;
    prep_k<<<(PREP_TOT + 255) / 256, blk>>>(pp);

    const float* gate_b = (const float*)d_in[15];
    const float* fus1_b = (const float*)d_in[17];
    const float* fus2_b = (const float*)d_in[19];

    // --- projections, both modalities in one launch ---
    // sel0: wR @ rgb -> proj[0]; sel1: wD @ chm -> proj[1]
    tgemm_k<P_PROJ><<<dim3(32, 3, 4), blk, SMEM_BYTES>>>(
        wR, wD, CC, 0, rgb, chm, HWP, sX,
        proj, sP, (size_t)NB * sP, bR, bD, nullptr, nullptr, 0, MPROJ, HWP, CC);

    const float* projR = proj;
    const float* projD = proj + NB * sP;
    const float* rq = projR;
    const float* rk = projR + RCQ * HWP;
    const float* dq = projD;
    const float* dk = projD + RCQ * HWP;

    // --- z pass (both attentions): invZ + expS ---
    // sel0: attn for rgb branch uses (dq, dk); sel1: (rq, rk)
    attn_z_k<<<dim3(64, NB, 2), blk>>>(dq, dk, rq, rk, invZ, expS);

    // --- scale V by invZ into packed vz ---
    scalev_k<<<(unsigned)(((size_t)4 * CC * HWP) / 256), blk>>>(projR, projD, invZ, vz);

    // --- apply (both attentions x batch, one batched GEMM): cat = vz @ expS + res ---
    tgemm_k<P_APPLY><<<dim3(32, 2, 4), blk, SMEM_BYTES>>>(
        vz, vz + 2 * sX, HWP, sX, expS, expS + 2 * sS, HWP, sS,
        cat, sF, sX, nullptr, nullptr, rgb, chm, sX, CC, HWP, HWP);

    // --- gate GEMM + fused sigmoid-gated combine -> fy rows 0..511 (f) ---
    tgemm_k<P_GATE><<<dim3(32, 2, NB), blk, SMEM_BYTES>>>(
        wGate, nullptr, C2, 0, cat, nullptr, HWP, sF,
        fy, s1024, 0, gate_b, nullptr, cat, nullptr, sF, CC, HWP, C2);

    // --- fus1: y1 = relu(W1 @ f + b1) ---
    tgemm_k<P_FUS><<<dim3(32, 4, NB), blk, SMEM_BYTES>>>(
        wF1, nullptr, C2, 0, fy, nullptr, HWP, s1024,
        y1, sF, 0, fus1_b, nullptr, nullptr, nullptr, 0, C2, HWP, C2);

    // --- fus2: im2col + GEMM -> fy rows 512..1023 (y2) ---
    im2col_k<<<(unsigned)(((size_t)NB * KCOL * HWP) / 256), blk>>>(y1, col);
    tgemm_k<P_FUS><<<dim3(32, 4, NB), blk, SMEM_BYTES>>>(
        wF2, nullptr, KCOL, 0, col, nullptr, HWP, sCol,
        fy + 512 * HWP, s1024, 0, fus2_b, nullptr, nullptr, nullptr, 0, C2, HWP, KCOL);

    // --- head: out = [skip | fus3] @ [f ; y2] + (b3 + bskip), single K=1024 GEMM ---
    tgemm_k<P_HEAD><<<dim3(32, 2, NB), blk, SMEM_BYTES>>>(
        wHead, nullptr, 1024, 0, fy, nullptr, HWP, s1024,
        out, sX, 0, bHead, nullptr, nullptr, nullptr, 0, CC, HWP, 1024);

    (void)in_sizes; (void)n_in; (void)out_size;
}

// round 7
// speedup vs baseline: 1.4384x; 1.4384x over previous
#include <cuda_runtime.h>
#include <cstdint>
#include <math.h>

#define NB 2
#define CC 256
#define RCQ 32
#define HH 64
#define WW 64
#define HWP 4096
#define C2 512
#define KCOL 4608
#define MPROJ 320

// ---------------- scratch ----------------
__device__ float g_proj[(size_t)2 * NB * MPROJ * HWP];     // [mod][batch][320][4096]
__device__ float g_invZ[4 * HWP];                          // [attn*2+batch][4096]
__device__ float g_cat[(size_t)NB * C2 * HWP];
__device__ float g_fy[(size_t)NB * 1024 * HWP];            // rows 0-511 f, 512-1023 y2
__device__ float g_y1[(size_t)NB * C2 * HWP];
__device__ float g_col[(size_t)NB * KCOL * HWP];
// tf32 weights
__device__ float g_wR[MPROJ * CC];
__device__ float g_wD[MPROJ * CC];
__device__ float g_bR[MPROJ];
__device__ float g_bD[MPROJ];
__device__ float g_wGate[CC * C2];
__device__ float g_wF1[C2 * C2];
__device__ float g_wF2[C2 * KCOL];
__device__ float g_wHead[CC * 1024];
__device__ float g_bHead[CC];

// ---------------- helpers ----------------
__device__ __forceinline__ void cp16(uint32_t dst, const void* src, bool v) {
    int sz = v ? 16 : 0;
    asm volatile("cp.async.cg.shared.global [%0], [%1], 16, %2;\n"
                 :: "r"(dst), "l"(src), "r"(sz));
}
__device__ __forceinline__ uint32_t cvt_tf32(float x) {
    uint32_t r;
    asm("cvt.rna.tf32.f32 %0, %1;" : "=r"(r) : "f"(x));
    return r;
}
__device__ __forceinline__ float tf32f(float x) { return __uint_as_float(cvt_tf32(x)); }
__device__ __forceinline__ void mma8(float* c, const uint32_t* a, uint32_t b0, uint32_t b1) {
    asm volatile(
        "mma.sync.aligned.m16n8k8.row.col.f32.tf32.tf32.f32 "
        "{%0,%1,%2,%3}, {%4,%5,%6,%7}, {%8,%9}, {%0,%1,%2,%3};"
        : "+f"(c[0]), "+f"(c[1]), "+f"(c[2]), "+f"(c[3])
        : "r"(a[0]), "r"(a[1]), "r"(a[2]), "r"(a[3]), "r"(b0), "r"(b1));
}

// ---------------- single prep kernel: weight cvt + concat + biases ----------------
struct PrepPtrs {
    const float *rq_w, *rk_w, *rv_w, *dq_w, *dk_w, *dv_w;
    const float *gate_w, *fus1_w, *fus2_w, *fus3_w, *skip_w;
    const float *rq_b, *rk_b, *rv_b, *dq_b, *dk_b, *dv_b, *fus3_b, *skip_b;
    float *wR, *wD, *wGate, *wF1, *wF2, *wHead, *bR, *bD, *bHead;
};
#define PREP_TOT 3179392
__global__ void __launch_bounds__(256) prep_k(PrepPtrs p) {
    int i = blockIdx.x * 256 + threadIdx.x;
    if (i >= PREP_TOT) return;
    if (i < 8192)            p.wR[i] = tf32f(p.rq_w[i]);
    else if (i < 16384)      p.wR[i] = tf32f(p.rk_w[i - 8192]);
    else if (i < 81920)      p.wR[i] = tf32f(p.rv_w[i - 16384]);
    else if (i < 90112)      p.wD[i - 81920] = tf32f(p.dq_w[i - 81920]);
    else if (i < 98304)      p.wD[i - 81920] = tf32f(p.dk_w[i - 90112]);
    else if (i < 163840)     p.wD[i - 81920] = tf32f(p.dv_w[i - 98304]);
    else if (i < 294912)     p.wGate[i - 163840] = tf32f(p.gate_w[i - 163840]);
    else if (i < 557056)     p.wF1[i - 294912] = tf32f(p.fus1_w[i - 294912]);
    else if (i < 2916352)    p.wF2[i - 557056] = tf32f(p.fus2_w[i - 557056]);
    else if (i < 3178496) {
        int j = i - 2916352;
        int m = j >> 10, k = j & 1023;
        float v = (k < 512) ? p.skip_w[m * 512 + k] : p.fus3_w[m * 512 + k - 512];
        p.wHead[j] = tf32f(v);
    } else if (i < 3178816) {
        int j = i - 3178496;
        p.bR[j] = (j < 32) ? p.rq_b[j] : (j < 64) ? p.rk_b[j - 32] : p.rv_b[j - 64];
    } else if (i < 3179136) {
        int j = i - 3178816;
        p.bD[j] = (j < 32) ? p.dq_b[j] : (j < 64) ? p.dk_b[j - 32] : p.dv_b[j - 64];
    } else {
        int j = i - 3179136;
        p.bHead[j] = p.fus3_b[j] + p.skip_b[j];
    }
}

// ---------------- TF32 GEMM ----------------
#define FL_RELU 2
#define FL_BIAS 8
#define FL_GATE 16
#define FL_CVTO 32
#define FL_DUAL 64

#define ASTR 36
#define BSTR 136
#define ABUF (128 * ASTR)
#define BBUF (32 * BSTR)
#define SMEM_BYTES ((2 * ABUF + 2 * BBUF) * 4)   // 71680

template <int F>
__global__ void __launch_bounds__(256, 2) tgemm_k(
    const float* __restrict__ A, const float* __restrict__ A2, int lda, size_t sA,
    const float* __restrict__ B, const float* __restrict__ B2, int ldb, size_t sB,
    float* __restrict__ C, size_t sC, size_t cSelOff,
    const float* __restrict__ bias, const float* __restrict__ bias2,
    const float* __restrict__ res, size_t sRes,
    int M, int N, int K)
{
    extern __shared__ float sm[];
    const int bz = blockIdx.z;
    const int sel   = (F & FL_DUAL) ? (bz >> 1) : 0;
    const int batch = (F & FL_DUAL) ? (bz & 1) : bz;
    const float* Ap = (((F & FL_DUAL) && sel) ? A2 : A) + (size_t)batch * sA;
    const float* Bp = (((F & FL_DUAL) && sel) ? B2 : B) + (size_t)batch * sB;
    C += (size_t)batch * sC + (sel ? cSelOff : 0);
    const float* biasp = (((F & FL_DUAL) && sel) ? bias2 : bias);
    const float* resp = res ? res + (size_t)batch * sRes : nullptr;

    const int m0 = blockIdx.y * 128, n0 = blockIdx.x * 128;
    const int tid = threadIdx.x;
    const int lane = tid & 31, warp = tid >> 5;
    const int g = lane >> 2, t4 = lane & 3;
    const int wm = (warp >> 2) * 64;
    const int wn = (warp & 3) * 32;

    const uint32_t sbase = (uint32_t)__cvta_generic_to_shared(sm);

    float acc[4][4][4];
#pragma unroll
    for (int mt = 0; mt < 4; mt++)
#pragma unroll
        for (int nt = 0; nt < 4; nt++)
#pragma unroll
            for (int i = 0; i < 4; i++) acc[mt][nt][i] = 0.f;

    auto loadA = [&](int buf, int k0) {
#pragma unroll
        for (int i = 0; i < 4; i++) {
            int c = tid + i * 256;
            int m = c >> 3, kg = c & 7;
            bool v = (m0 + m) < M;
            int mm = v ? (m0 + m) : 0;
            const float* src = Ap + (size_t)mm * lda + k0 + kg * 4;
            uint32_t dst = sbase + (uint32_t)((buf * ABUF + m * ASTR + kg * 4) * 4);
            cp16(dst, src, v);
        }
    };
    auto loadB = [&](int buf, int k0) {
#pragma unroll
        for (int i = 0; i < 4; i++) {
            int c = tid + i * 256;
            int k = c >> 5, ng = c & 31;
            const float* src = Bp + (size_t)(k0 + k) * ldb + n0 + ng * 4;
            uint32_t dst = sbase + (uint32_t)((2 * ABUF + buf * BBUF + k * BSTR + ng * 4) * 4);
            cp16(dst, src, true);
        }
    };

    const int KT = K / 32;
    loadA(0, 0);
    loadB(0, 0);
    asm volatile("cp.async.commit_group;\n");

    int cur = 0;
    for (int kt = 0; kt < KT; kt++) {
        if (kt + 1 < KT) {
            loadA(cur ^ 1, (kt + 1) * 32);
            loadB(cur ^ 1, (kt + 1) * 32);
            asm volatile("cp.async.commit_group;\n");
            asm volatile("cp.async.wait_group 1;\n");
        } else {
            asm volatile("cp.async.wait_group 0;\n");
        }
        __syncthreads();

        const float* Ab = sm + cur * ABUF;
        const float* Bb = sm + 2 * ABUF + cur * BBUF;
#pragma unroll
        for (int ks = 0; ks < 4; ks++) {
            const int kk = ks * 8;
            uint32_t af[4][4];
#pragma unroll
            for (int mt = 0; mt < 4; mt++) {
                int r0 = wm + mt * 16 + g;
                af[mt][0] = __float_as_uint(Ab[r0 * ASTR + kk + t4]);
                af[mt][1] = __float_as_uint(Ab[(r0 + 8) * ASTR + kk + t4]);
                af[mt][2] = __float_as_uint(Ab[r0 * ASTR + kk + t4 + 4]);
                af[mt][3] = __float_as_uint(Ab[(r0 + 8) * ASTR + kk + t4 + 4]);
            }
#pragma unroll
            for (int nt = 0; nt < 4; nt++) {
                int cb = wn + nt * 8 + g;
                uint32_t b0 = __float_as_uint(Bb[(kk + t4) * BSTR + cb]);
                uint32_t b1 = __float_as_uint(Bb[(kk + t4 + 4) * BSTR + cb]);
#pragma unroll
                for (int mt = 0; mt < 4; mt++) mma8(acc[mt][nt], af[mt], b0, b1);
            }
        }
        __syncthreads();
        cur ^= 1;
    }

#pragma unroll
    for (int mt = 0; mt < 4; mt++) {
        int r0 = m0 + wm + mt * 16 + g;
#pragma unroll
        for (int nt = 0; nt < 4; nt++) {
            int cb = n0 + wn + nt * 8 + 2 * t4;
            const float* a4 = acc[mt][nt];
#pragma unroll
            for (int half = 0; half < 2; half++) {
                int r = r0 + half * 8;
                if (r >= M) continue;
                float bv = (F & FL_BIAS) ? biasp[r] : 0.f;
#pragma unroll
                for (int j = 0; j < 2; j++) {
                    size_t idx = (size_t)r * N + cb + j;
                    float v = a4[half * 2 + j] + bv;
                    if (F & FL_GATE) {
                        float a = resp[idx];
                        float b2 = resp[idx + (size_t)CC * N];
                        float gg = 1.f / (1.f + __expf(-v));
                        C[idx] = tf32f(a * gg + b2 * (1.f - gg));
                        C[idx + (size_t)CC * N] = tf32f(a * b2);
                    } else {
                        if (F & FL_RELU) v = fmaxf(v, 0.f);
                        if (F & FL_CVTO) v = tf32f(v);
                        C[idx] = v;
                    }
                }
            }
        }
    }
}

#define P_PROJ  (FL_BIAS | FL_CVTO | FL_DUAL)
#define P_GATE  (FL_BIAS | FL_GATE)
#define P_FUS   (FL_BIAS | FL_RELU | FL_CVTO)
#define P_HEAD  (FL_BIAS)

// ---------------- z pass: invZ[i] = 1/sum_j exp(S[i,j]); both attentions via grid.z ----
__global__ void __launch_bounds__(256) attn_z_k(
    const float* __restrict__ Q0, const float* __restrict__ K0,
    const float* __restrict__ Q1, const float* __restrict__ K1,
    float* __restrict__ invZ)
{
    __shared__ float dqT[64 * 36];
    __shared__ float dkS[2 * 32 * 136];
    __shared__ float zred[4][64];

    const int sel = blockIdx.z, b = blockIdx.y;
    const size_t sP = (size_t)MPROJ * HWP;
    const float* Q    = (sel ? Q1 : Q0) + (size_t)b * sP;
    const float* Kmat = (sel ? K1 : K0) + (size_t)b * sP;
    invZ += (size_t)(sel * NB + b) * HWP;

    const int i0 = blockIdx.x * 64;
    const int tid = threadIdx.x;
    const int lane = tid & 31, warp = tid >> 5;
    const int g = lane >> 2, t4 = lane & 3;
    const uint32_t dkbase = (uint32_t)__cvta_generic_to_shared(dkS);

#pragma unroll
    for (int rep = 0; rep < 8; rep++) {
        int idx = tid + rep * 256;
        int r = idx >> 6, ii = idx & 63;
        dqT[ii * 36 + r] = Q[(size_t)r * HWP + i0 + ii];
    }
    auto loadK = [&](int buf, int j0) {
#pragma unroll
        for (int rep = 0; rep < 4; rep++) {
            int c = tid + rep * 256;
            int r = c >> 5, jg = c & 31;
            const float* src = Kmat + (size_t)r * HWP + j0 + jg * 4;
            uint32_t dst = dkbase + (uint32_t)((buf * 32 * 136 + r * 136 + jg * 4) * 4);
            cp16(dst, src, true);
        }
    };
    loadK(0, 0);
    asm volatile("cp.async.commit_group;\n");

    float zacc[2][2] = {{0.f, 0.f}, {0.f, 0.f}};
    const int wm = (warp >> 2) * 32, wn = (warp & 3) * 32;

    for (int jc = 0; jc < 32; jc++) {
        int cur = jc & 1;
        asm volatile("cp.async.wait_group 0;\n");
        __syncthreads();
        if (jc + 1 < 32) {
            loadK(cur ^ 1, (jc + 1) * 128);
            asm volatile("cp.async.commit_group;\n");
        }
        const float* dk = dkS + cur * 32 * 136;
        float sacc[2][4][4];
#pragma unroll
        for (int mt = 0; mt < 2; mt++)
#pragma unroll
            for (int nt = 0; nt < 4; nt++)
#pragma unroll
                for (int e = 0; e < 4; e++) sacc[mt][nt][e] = 0.f;
#pragma unroll
        for (int ks = 0; ks < 4; ks++) {
            int kk = ks * 8;
            uint32_t a[2][4];
#pragma unroll
            for (int mt = 0; mt < 2; mt++) {
                int r0 = wm + mt * 16 + g;
                a[mt][0] = __float_as_uint(dqT[r0 * 36 + kk + t4]);
                a[mt][1] = __float_as_uint(dqT[(r0 + 8) * 36 + kk + t4]);
                a[mt][2] = __float_as_uint(dqT[r0 * 36 + kk + t4 + 4]);
                a[mt][3] = __float_as_uint(dqT[(r0 + 8) * 36 + kk + t4 + 4]);
            }
#pragma unroll
            for (int nt = 0; nt < 4; nt++) {
                int cb = wn + nt * 8 + g;
                uint32_t b0 = __float_as_uint(dk[(kk + t4) * 136 + cb]);
                uint32_t b1 = __float_as_uint(dk[(kk + t4 + 4) * 136 + cb]);
#pragma unroll
                for (int mt = 0; mt < 2; mt++) mma8(sacc[mt][nt], a[mt], b0, b1);
            }
        }
#pragma unroll
        for (int mt = 0; mt < 2; mt++)
#pragma unroll
            for (int nt = 0; nt < 4; nt++) {
                zacc[mt][0] += __expf(sacc[mt][nt][0]) + __expf(sacc[mt][nt][1]);
                zacc[mt][1] += __expf(sacc[mt][nt][2]) + __expf(sacc[mt][nt][3]);
            }
    }
#pragma unroll
    for (int mt = 0; mt < 2; mt++)
#pragma unroll
        for (int h = 0; h < 2; h++) {
            float v = zacc[mt][h];
            v += __shfl_xor_sync(0xffffffffu, v, 1);
            v += __shfl_xor_sync(0xffffffffu, v, 2);
            if (t4 == 0) zred[warp & 3][wm + mt * 16 + h * 8 + g] = v;
        }
    __syncthreads();
    if (tid < 64) {
        float s = zred[0][tid] + zred[1][tid] + zred[2][tid] + zred[3][tid];
        invZ[i0 + tid] = 1.f / s;
    }
}

// ---------------- fused attention apply (recompute S in smem, both attns via grid.z) ---
#define AP_DKT 0
#define AP_DQ  (128 * 36)
#define AP_RV  (AP_DQ + 2 * 32 * 40)
#define AP_ES  (AP_RV + 2 * 128 * 36)
#define AP_SMEM_BYTES ((AP_ES + 32 * 136) * 4)   // 82944

__global__ void __launch_bounds__(256) attn_apply_k(
    const float* __restrict__ Q0, const float* __restrict__ K0, const float* __restrict__ V0,
    const float* __restrict__ Q1, const float* __restrict__ K1, const float* __restrict__ V1,
    const float* __restrict__ invZg,
    const float* __restrict__ res0, const float* __restrict__ res1,
    float* __restrict__ out)
{
    extern __shared__ float sm[];
    float* dkT = sm + AP_DKT;   // [128 j][36]
    float* eS  = sm + AP_ES;    // [32 i][136]

    const int bz = blockIdx.z;
    const int sel = bz >> 1, b = bz & 1;
    const int j0 = blockIdx.x * 128;
    const int c0 = blockIdx.y * 128;
    const size_t sP = (size_t)MPROJ * HWP;
    const size_t sX = (size_t)CC * HWP;
    const size_t sF = (size_t)C2 * HWP;

    const float* Q    = (sel ? Q1 : Q0) + (size_t)b * sP;
    const float* Km   = (sel ? K1 : K0) + (size_t)b * sP;
    const float* V    = (sel ? V1 : V0) + (size_t)b * sP + (size_t)c0 * HWP;
    const float* invZ = invZg + (size_t)(sel * NB + b) * HWP;
    const float* res  = (sel ? res1 : res0) + (size_t)b * sX + (size_t)c0 * HWP;
    out += (size_t)b * sF + (size_t)sel * sX + (size_t)c0 * HWP;

    const int tid = threadIdx.x;
    const int lane = tid & 31, warp = tid >> 5;
    const int g = lane >> 2, t4 = lane & 3;
    const uint32_t sbase = (uint32_t)__cvta_generic_to_shared(sm);

    // transpose-load K tile once: [128 j][32 r]
#pragma unroll
    for (int rep = 0; rep < 16; rep++) {
        int idx = tid + rep * 256;
        int r = idx >> 7, jj = idx & 127;
        dkT[jj * 36 + r] = Km[(size_t)r * HWP + j0 + jj];
    }

    auto loadQ = [&](int buf, int i0) {
        int r = tid >> 3, ig = tid & 7;
        const float* src = Q + (size_t)r * HWP + i0 + ig * 4;
        uint32_t dst = sbase + (uint32_t)((AP_DQ + buf * 32 * 40 + r * 40 + ig * 4) * 4);
        cp16(dst, src, true);
    };
    auto loadV = [&](int buf, int i0) {
#pragma unroll
        for (int rep = 0; rep < 4; rep++) {
            int c = tid + rep * 256;
            int row = c >> 3, ig = c & 7;
            const float* src = V + (size_t)row * HWP + i0 + ig * 4;
            uint32_t dst = sbase + (uint32_t)((AP_RV + buf * 128 * 36 + row * 36 + ig * 4) * 4);
            cp16(dst, src, true);
        }
    };
    loadQ(0, 0);
    loadV(0, 0);
    asm volatile("cp.async.commit_group;\n");

    float acc[4][4][4];
#pragma unroll
    for (int mt = 0; mt < 4; mt++)
#pragma unroll
        for (int nt = 0; nt < 4; nt++)
#pragma unroll
            for (int e = 0; e < 4; e++) acc[mt][nt][e] = 0.f;

    const int wj = warp * 16;
    const int wm = (warp >> 2) * 64, wn = (warp & 3) * 32;

    for (int ic = 0; ic < 128; ic++) {
        const int i0 = ic * 32;
        const int cur = ic & 1;
        asm volatile("cp.async.wait_group 0;\n");
        __syncthreads();
        if (ic + 1 < 128) {
            loadQ(cur ^ 1, i0 + 32);
            loadV(cur ^ 1, i0 + 32);
            asm volatile("cp.async.commit_group;\n");
        }
        // ---- phase A: S'[j (m=128), i (n=32)] ----
        const float* dq = sm + AP_DQ + cur * 32 * 40;   // [32 r][40]
        float sacc[4][4];
#pragma unroll
        for (int nt = 0; nt < 4; nt++)
#pragma unroll
            for (int e = 0; e < 4; e++) sacc[nt][e] = 0.f;
#pragma unroll
        for (int ks = 0; ks < 4; ks++) {
            int kk = ks * 8;
            uint32_t a[4];
            a[0] = __float_as_uint(dkT[(wj + g) * 36 + kk + t4]);
            a[1] = __float_as_uint(dkT[(wj + g + 8) * 36 + kk + t4]);
            a[2] = __float_as_uint(dkT[(wj + g) * 36 + kk + t4 + 4]);
            a[3] = __float_as_uint(dkT[(wj + g + 8) * 36 + kk + t4 + 4]);
#pragma unroll
            for (int nt = 0; nt < 4; nt++) {
                int ci = nt * 8 + g;
                uint32_t b0 = __float_as_uint(dq[(kk + t4) * 40 + ci]);
                uint32_t b1 = __float_as_uint(dq[(kk + t4 + 4) * 40 + ci]);
                mma8(sacc[nt], a, b0, b1);
            }
        }
        // exp * invZ -> eS[i][j] (transposed store), tf32-rounded
#pragma unroll
        for (int nt = 0; nt < 4; nt++) {
            int il = nt * 8 + 2 * t4;
            float iz0 = invZ[i0 + il];
            float iz1 = invZ[i0 + il + 1];
            eS[il * 136 + wj + g]           = tf32f(__expf(sacc[nt][0]) * iz0);
            eS[(il + 1) * 136 + wj + g]     = tf32f(__expf(sacc[nt][1]) * iz1);
            eS[il * 136 + wj + g + 8]       = tf32f(__expf(sacc[nt][2]) * iz0);
            eS[(il + 1) * 136 + wj + g + 8] = tf32f(__expf(sacc[nt][3]) * iz1);
        }
        __syncthreads();
        // ---- phase B: acc[c (m=128), j (n=128)] += V_tile @ eS ----
        const float* rv = sm + AP_RV + cur * 128 * 36;  // [128 c][36]
#pragma unroll
        for (int ks = 0; ks < 4; ks++) {
            int kk = ks * 8;
            uint32_t af[4][4];
#pragma unroll
            for (int mt = 0; mt < 4; mt++) {
                int r0 = wm + mt * 16 + g;
                af[mt][0] = __float_as_uint(rv[r0 * 36 + kk + t4]);
                af[mt][1] = __float_as_uint(rv[(r0 + 8) * 36 + kk + t4]);
                af[mt][2] = __float_as_uint(rv[r0 * 36 + kk + t4 + 4]);
                af[mt][3] = __float_as_uint(rv[(r0 + 8) * 36 + kk + t4 + 4]);
            }
#pragma unroll
            for (int nt = 0; nt < 4; nt++) {
                int cb = wn + nt * 8 + g;
                uint32_t b0 = __float_as_uint(eS[(kk + t4) * 136 + cb]);
                uint32_t b1 = __float_as_uint(eS[(kk + t4 + 4) * 136 + cb]);
#pragma unroll
                for (int mt = 0; mt < 4; mt++) mma8(acc[mt][nt], af[mt], b0, b1);
            }
        }
    }
    // epilogue: + residual, tf32-rounded
#pragma unroll
    for (int mt = 0; mt < 4; mt++)
#pragma unroll
        for (int nt = 0; nt < 4; nt++)
#pragma unroll
            for (int e = 0; e < 4; e++) {
                int row = wm + mt * 16 + g + (e >> 1) * 8;
                int col = j0 + wn + nt * 8 + 2 * t4 + (e & 1);
                size_t o = (size_t)row * HWP + col;
                out[o] = tf32f(acc[mt][nt][e] + res[o]);
            }
}

// ---------------- im2col ----------------
__global__ void __launch_bounds__(256) im2col_k(
    const float* __restrict__ in, float* __restrict__ col)
{
    size_t idx = (size_t)blockIdx.x * 256 + threadIdx.x;
    int p = (int)(idx % HWP);
    size_t t = idx / HWP;
    int row = (int)(t % KCOL);
    int n = (int)(t / KCOL);
    int tap = row % 9, ci = row / 9;
    int ky = tap / 3, kx = tap % 3;
    int y = p >> 6, x = p & 63;
    int yy = y + ky - 1, xx = x + kx - 1;
    float v = 0.f;
    if (yy >= 0 && yy < HH && xx >= 0 && xx < WW)
        v = in[(((size_t)n * C2 + ci) * HH + yy) * WW + xx];
    col[idx] = v;
}

// ---------------- host launcher ----------------
extern "C" void kernel_launch(void* const* d_in, const int* in_sizes, int n_in,
                              void* d_out, int out_size)
{
    const float* rgb  = (const float*)d_in[0];
    const float* chm  = (const float*)d_in[1];
    float* out = (float*)d_out;

    float *proj, *invZ, *cat, *fy, *y1, *col;
    float *wR, *wD, *bR, *bD, *wGate, *wF1, *wF2, *wHead, *bHead;
    cudaGetSymbolAddress((void**)&proj, g_proj);
    cudaGetSymbolAddress((void**)&invZ, g_invZ);
    cudaGetSymbolAddress((void**)&cat, g_cat);
    cudaGetSymbolAddress((void**)&fy, g_fy);
    cudaGetSymbolAddress((void**)&y1, g_y1);
    cudaGetSymbolAddress((void**)&col, g_col);
    cudaGetSymbolAddress((void**)&wR, g_wR);
    cudaGetSymbolAddress((void**)&wD, g_wD);
    cudaGetSymbolAddress((void**)&bR, g_bR);
    cudaGetSymbolAddress((void**)&bD, g_bD);
    cudaGetSymbolAddress((void**)&wGate, g_wGate);
    cudaGetSymbolAddress((void**)&wF1, g_wF1);
    cudaGetSymbolAddress((void**)&wF2, g_wF2);
    cudaGetSymbolAddress((void**)&wHead, g_wHead);
    cudaGetSymbolAddress((void**)&bHead, g_bHead);

    cudaFuncSetAttribute(tgemm_k<P_PROJ>, cudaFuncAttributeMaxDynamicSharedMemorySize, SMEM_BYTES);
    cudaFuncSetAttribute(tgemm_k<P_GATE>, cudaFuncAttributeMaxDynamicSharedMemorySize, SMEM_BYTES);
    cudaFuncSetAttribute(tgemm_k<P_FUS>,  cudaFuncAttributeMaxDynamicSharedMemorySize, SMEM_BYTES);
    cudaFuncSetAttribute(tgemm_k<P_HEAD>, cudaFuncAttributeMaxDynamicSharedMemorySize, SMEM_BYTES);
    cudaFuncSetAttribute(attn_apply_k, cudaFuncAttributeMaxDynamicSharedMemorySize, AP_SMEM_BYTES);

    dim3 blk(256);
    const size_t sX = (size_t)CC * HWP;
    const size_t sF = (size_t)C2 * HWP;
    const size_t sP = (size_t)MPROJ * HWP;
    const size_t s1024 = (size_t)1024 * HWP;
    const size_t sCol = (size_t)KCOL * HWP;

    // --- prep ---
    PrepPtrs pp;
    pp.rq_w = (const float*)d_in[2];  pp.rq_b = (const float*)d_in[3];
    pp.rk_w = (const float*)d_in[4];  pp.rk_b = (const float*)d_in[5];
    pp.rv_w = (const float*)d_in[6];  pp.rv_b = (const float*)d_in[7];
    pp.dq_w = (const float*)d_in[8];  pp.dq_b = (const float*)d_in[9];
    pp.dk_w = (const float*)d_in[10]; pp.dk_b = (const float*)d_in[11];
    pp.dv_w = (const float*)d_in[12]; pp.dv_b = (const float*)d_in[13];
    pp.gate_w = (const float*)d_in[14];
    pp.fus1_w = (const float*)d_in[16];
    pp.fus2_w = (const float*)d_in[18];
    pp.fus3_w = (const float*)d_in[20]; pp.fus3_b = (const float*)d_in[21];
    pp.skip_w = (const float*)d_in[22]; pp.skip_b = (const float*)d_in[23];
    pp.wR = wR; pp.wD = wD; pp.wGate = wGate; pp.wF1 = wF1; pp.wF2 = wF2;
    pp.wHead = wHead; pp.bR = bR; pp.bD = bD; pp.bHead = bHead;
    prep_k<<<(PREP_TOT + 255) / 256, blk>>>(pp);

    const float* gate_b = (const float*)d_in[15];
    const float* fus1_b = (const float*)d_in[17];
    const float* fus2_b = (const float*)d_in[19];

    // --- projections (both modalities, one launch) ---
    tgemm_k<P_PROJ><<<dim3(32, 3, 4), blk, SMEM_BYTES>>>(
        wR, wD, CC, 0, rgb, chm, HWP, sX,
        proj, sP, (size_t)NB * sP, bR, bD, nullptr, 0, MPROJ, HWP, CC);

    const float* projR = proj;
    const float* projD = proj + NB * sP;
    const float* rq = projR;
    const float* rk = projR + RCQ * HWP;
    const float* rv = projR + 2 * RCQ * HWP;
    const float* dq = projD;
    const float* dk = projD + RCQ * HWP;
    const float* dv = projD + 2 * RCQ * HWP;

    // --- z pass: sel0 uses (dq,dk) [rgb branch attn], sel1 uses (rq,rk) ---
    attn_z_k<<<dim3(64, NB, 2), blk>>>(dq, dk, rq, rk, invZ);

    // --- fused apply (both attns x batch x 2 c-tiles = 256 CTAs, one launch) ---
    // sel0: cat[:,0:C]   = rv @ softmax(dq.dk) + rgb
    // sel1: cat[:,C:2C]  = dv @ softmax(rq.rk) + chm
    attn_apply_k<<<dim3(32, 2, 4), blk, AP_SMEM_BYTES>>>(
        dq, dk, rv, rq, rk, dv, invZ, rgb, chm, cat);

    // --- gate GEMM + fused sigmoid-gated combine -> fy rows 0..511 (f) ---
    tgemm_k<P_GATE><<<dim3(32, 2, NB), blk, SMEM_BYTES>>>(
        wGate, nullptr, C2, 0, cat, nullptr, HWP, sF,
        fy, s1024, 0, gate_b, nullptr, cat, sF, CC, HWP, C2);

    // --- fus1: y1 = relu(W1 @ f + b1) ---
    tgemm_k<P_FUS><<<dim3(32, 4, NB), blk, SMEM_BYTES>>>(
        wF1, nullptr, C2, 0, fy, nullptr, HWP, s1024,
        y1, sF, 0, fus1_b, nullptr, nullptr, 0, C2, HWP, C2);

    // --- fus2: im2col + GEMM -> fy rows 512..1023 (y2) ---
    im2col_k<<<(unsigned)(((size_t)NB * KCOL * HWP) / 256), blk>>>(y1, col);
    tgemm_k<P_FUS><<<dim3(32, 4, NB), blk, SMEM_BYTES>>>(
        wF2, nullptr, KCOL, 0, col, nullptr, HWP, sCol,
        fy + 512 * HWP, s1024, 0, fus2_b, nullptr, nullptr, 0, C2, HWP, KCOL);

    // --- head: out = [skip | fus3] @ [f ; y2] + (bskip + b3) ---
    tgemm_k<P_HEAD><<<dim3(32, 2, NB), blk, SMEM_BYTES>>>(
        wHead, nullptr, 1024, 0, fy, nullptr, HWP, s1024,
        out, sX, 0, bHead, nullptr, nullptr, 0, CC, HWP, 1024);

    (void)in_sizes; (void)n_in; (void)out_size;
}

// round 10
// speedup vs baseline: 1.7438x; 1.2123x over previous
#include <cuda_runtime.h>
#include <cuda_fp16.h>
#include <cstdint>
#include <math.h>

#define NB 2
#define CC 256
#define RCQ 32
#define HH 64
#define WW 64
#define HWP 4096
#define C2 512
#define KCOL 4608
#define MPROJ 320

// ---------------- scratch ----------------
__device__ __half g_projH[(size_t)2 * NB * MPROJ * HWP];   // [mod][batch][320][4096] fp16
__device__ __half g_qkT[(size_t)2 * NB * HWP * 64];        // [mod][batch][i][q0-31|k32-63]
__device__ float g_invZ[4 * HWP];                          // [attn*2+batch][4096]
__device__ float g_cat[(size_t)NB * C2 * HWP];
__device__ float g_fy[(size_t)NB * 1024 * HWP];            // rows 0-511 f, 512-1023 y2
__device__ float g_y1[(size_t)NB * C2 * HWP];
__device__ float g_col[(size_t)NB * KCOL * HWP];
// tf32 weights
__device__ float g_wR[MPROJ * CC];
__device__ float g_wD[MPROJ * CC];
__device__ float g_bR[MPROJ];
__device__ float g_bD[MPROJ];
__device__ float g_wGate[CC * C2];
__device__ float g_wF1[C2 * C2];
__device__ float g_wF2[C2 * KCOL];
__device__ float g_wHead[CC * 1024];
__device__ float g_bHead[CC];

// ---------------- helpers ----------------
__device__ __forceinline__ void cp16(uint32_t dst, const void* src, bool v) {
    int sz = v ? 16 : 0;
    asm volatile("cp.async.cg.shared.global [%0], [%1], 16, %2;\n"
                 :: "r"(dst), "l"(src), "r"(sz));
}
__device__ __forceinline__ uint32_t cvt_tf32(float x) {
    uint32_t r;
    asm("cvt.rna.tf32.f32 %0, %1;" : "=r"(r) : "f"(x));
    return r;
}
__device__ __forceinline__ float tf32f(float x) { return __uint_as_float(cvt_tf32(x)); }
__device__ __forceinline__ void mma8(float* c, const uint32_t* a, uint32_t b0, uint32_t b1) {
    asm volatile(
        "mma.sync.aligned.m16n8k8.row.col.f32.tf32.tf32.f32 "
        "{%0,%1,%2,%3}, {%4,%5,%6,%7}, {%8,%9}, {%0,%1,%2,%3};"
        : "+f"(c[0]), "+f"(c[1]), "+f"(c[2]), "+f"(c[3])
        : "r"(a[0]), "r"(a[1]), "r"(a[2]), "r"(a[3]), "r"(b0), "r"(b1));
}
__device__ __forceinline__ void mma16h(float* c, const uint32_t* a, uint32_t b0, uint32_t b1) {
    asm volatile(
        "mma.sync.aligned.m16n8k16.row.col.f32.f16.f16.f32 "
        "{%0,%1,%2,%3}, {%4,%5,%6,%7}, {%8,%9}, {%0,%1,%2,%3};"
        : "+f"(c[0]), "+f"(c[1]), "+f"(c[2]), "+f"(c[3])
        : "r"(a[0]), "r"(a[1]), "r"(a[2]), "r"(a[3]), "r"(b0), "r"(b1));
}
__device__ __forceinline__ uint32_t lds32h(const __half* p) {
    return *(const uint32_t*)p;
}

// ---------------- single prep kernel: weight cvt + concat + biases ----------------
struct PrepPtrs {
    const float *rq_w, *rk_w, *rv_w, *dq_w, *dk_w, *dv_w;
    const float *gate_w, *fus1_w, *fus2_w, *fus3_w, *skip_w;
    const float *rq_b, *rk_b, *rv_b, *dq_b, *dk_b, *dv_b, *fus3_b, *skip_b;
    float *wR, *wD, *wGate, *wF1, *wF2, *wHead, *bR, *bD, *bHead;
};
#define PREP_TOT 3179392
__global__ void __launch_bounds__(256) prep_k(PrepPtrs p) {
    int i = blockIdx.x * 256 + threadIdx.x;
    if (i >= PREP_TOT) return;
    if (i < 8192)            p.wR[i] = tf32f(p.rq_w[i]);
    else if (i < 16384)      p.wR[i] = tf32f(p.rk_w[i - 8192]);
    else if (i < 81920)      p.wR[i] = tf32f(p.rv_w[i - 16384]);
    else if (i < 90112)      p.wD[i - 81920] = tf32f(p.dq_w[i - 81920]);
    else if (i < 98304)      p.wD[i - 81920] = tf32f(p.dk_w[i - 90112]);
    else if (i < 163840)     p.wD[i - 81920] = tf32f(p.dv_w[i - 98304]);
    else if (i < 294912)     p.wGate[i - 163840] = tf32f(p.gate_w[i - 163840]);
    else if (i < 557056)     p.wF1[i - 294912] = tf32f(p.fus1_w[i - 294912]);
    else if (i < 2916352)    p.wF2[i - 557056] = tf32f(p.fus2_w[i - 557056]);
    else if (i < 3178496) {
        int j = i - 2916352;
        int m = j >> 10, k = j & 1023;
        float v = (k < 512) ? p.skip_w[m * 512 + k] : p.fus3_w[m * 512 + k - 512];
        p.wHead[j] = tf32f(v);
    } else if (i < 3178816) {
        int j = i - 3178496;
        p.bR[j] = (j < 32) ? p.rq_b[j] : (j < 64) ? p.rk_b[j - 32] : p.rv_b[j - 64];
    } else if (i < 3179136) {
        int j = i - 3178816;
        p.bD[j] = (j < 32) ? p.dq_b[j] : (j < 64) ? p.dk_b[j - 32] : p.dv_b[j - 64];
    } else {
        int j = i - 3179136;
        p.bHead[j] = p.fus3_b[j] + p.skip_b[j];
    }
}

// ---------------- TF32 GEMM (f32 in, f32 or f16 out) ----------------
#define FL_RELU 2
#define FL_BIAS 8
#define FL_GATE 16
#define FL_CVTO 32
#define FL_DUAL 64
#define FL_HALF 256

#define ASTR 36
#define BSTR 136
#define ABUF (128 * ASTR)
#define BBUF (32 * BSTR)
#define SMEM_BYTES ((2 * ABUF + 2 * BBUF) * 4)   // 71680

template <int F>
__global__ void __launch_bounds__(256, 2) tgemm_k(
    const float* __restrict__ A, const float* __restrict__ A2, int lda, size_t sA,
    const float* __restrict__ B, const float* __restrict__ B2, int ldb, size_t sB,
    float* __restrict__ Cf, size_t sC, size_t cSelOff,
    const float* __restrict__ bias, const float* __restrict__ bias2,
    const float* __restrict__ res, size_t sRes,
    int M, int N, int K)
{
    extern __shared__ float sm[];
    const int bz = blockIdx.z;
    const int sel   = (F & FL_DUAL) ? (bz >> 1) : 0;
    const int batch = (F & FL_DUAL) ? (bz & 1) : bz;
    const float* Ap = (((F & FL_DUAL) && sel) ? A2 : A) + (size_t)batch * sA;
    const float* Bp = (((F & FL_DUAL) && sel) ? B2 : B) + (size_t)batch * sB;
    float* C = Cf;
    __half* Ch = nullptr;
    if (F & FL_HALF) Ch = (__half*)Cf + (size_t)batch * sC + (sel ? cSelOff : 0);
    else C = Cf + (size_t)batch * sC + (sel ? cSelOff : 0);
    const float* biasp = (((F & FL_DUAL) && sel) ? bias2 : bias);
    const float* resp = res ? res + (size_t)batch * sRes : nullptr;

    const int m0 = blockIdx.y * 128, n0 = blockIdx.x * 128;
    const int tid = threadIdx.x;
    const int lane = tid & 31, warp = tid >> 5;
    const int g = lane >> 2, t4 = lane & 3;
    const int wm = (warp >> 2) * 64;
    const int wn = (warp & 3) * 32;

    const uint32_t sbase = (uint32_t)__cvta_generic_to_shared(sm);

    float acc[4][4][4];
#pragma unroll
    for (int mt = 0; mt < 4; mt++)
#pragma unroll
        for (int nt = 0; nt < 4; nt++)
#pragma unroll
            for (int i = 0; i < 4; i++) acc[mt][nt][i] = 0.f;

    auto loadA = [&](int buf, int k0) {
#pragma unroll
        for (int i = 0; i < 4; i++) {
            int c = tid + i * 256;
            int m = c >> 3, kg = c & 7;
            bool v = (m0 + m) < M;
            int mm = v ? (m0 + m) : 0;
            const float* src = Ap + (size_t)mm * lda + k0 + kg * 4;
            uint32_t dst = sbase + (uint32_t)((buf * ABUF + m * ASTR + kg * 4) * 4);
            cp16(dst, src, v);
        }
    };
    auto loadB = [&](int buf, int k0) {
#pragma unroll
        for (int i = 0; i < 4; i++) {
            int c = tid + i * 256;
            int k = c >> 5, ng = c & 31;
            const float* src = Bp + (size_t)(k0 + k) * ldb + n0 + ng * 4;
            uint32_t dst = sbase + (uint32_t)((2 * ABUF + buf * BBUF + k * BSTR + ng * 4) * 4);
            cp16(dst, src, true);
        }
    };

    const int KT = K / 32;
    loadA(0, 0);
    loadB(0, 0);
    asm volatile("cp.async.commit_group;\n");

    int cur = 0;
    for (int kt = 0; kt < KT; kt++) {
        if (kt + 1 < KT) {
            loadA(cur ^ 1, (kt + 1) * 32);
            loadB(cur ^ 1, (kt + 1) * 32);
            asm volatile("cp.async.commit_group;\n");
            asm volatile("cp.async.wait_group 1;\n");
        } else {
            asm volatile("cp.async.wait_group 0;\n");
        }
        __syncthreads();

        const float* Ab = sm + cur * ABUF;
        const float* Bb = sm + 2 * ABUF + cur * BBUF;
#pragma unroll
        for (int ks = 0; ks < 4; ks++) {
            const int kk = ks * 8;
            uint32_t af[4][4];
#pragma unroll
            for (int mt = 0; mt < 4; mt++) {
                int r0 = wm + mt * 16 + g;
                af[mt][0] = __float_as_uint(Ab[r0 * ASTR + kk + t4]);
                af[mt][1] = __float_as_uint(Ab[(r0 + 8) * ASTR + kk + t4]);
                af[mt][2] = __float_as_uint(Ab[r0 * ASTR + kk + t4 + 4]);
                af[mt][3] = __float_as_uint(Ab[(r0 + 8) * ASTR + kk + t4 + 4]);
            }
#pragma unroll
            for (int nt = 0; nt < 4; nt++) {
                int cb = wn + nt * 8 + g;
                uint32_t b0 = __float_as_uint(Bb[(kk + t4) * BSTR + cb]);
                uint32_t b1 = __float_as_uint(Bb[(kk + t4 + 4) * BSTR + cb]);
#pragma unroll
                for (int mt = 0; mt < 4; mt++) mma8(acc[mt][nt], af[mt], b0, b1);
            }
        }
        __syncthreads();
        cur ^= 1;
    }

#pragma unroll
    for (int mt = 0; mt < 4; mt++) {
        int r0 = m0 + wm + mt * 16 + g;
#pragma unroll
        for (int nt = 0; nt < 4; nt++) {
            int cb = n0 + wn + nt * 8 + 2 * t4;
            const float* a4 = acc[mt][nt];
#pragma unroll
            for (int half = 0; half < 2; half++) {
                int r = r0 + half * 8;
                if (r >= M) continue;
                float bv = (F & FL_BIAS) ? biasp[r] : 0.f;
                float v0 = a4[half * 2 + 0] + bv;
                float v1 = a4[half * 2 + 1] + bv;
                size_t idx = (size_t)r * N + cb;
                if (F & FL_HALF) {
                    *(__half2*)(Ch + idx) = __floats2half2_rn(v0, v1);
                } else if (F & FL_GATE) {
#pragma unroll
                    for (int j = 0; j < 2; j++) {
                        float v = j ? v1 : v0;
                        float a = resp[idx + j];
                        float b2 = resp[idx + j + (size_t)CC * N];
                        float gg = 1.f / (1.f + __expf(-v));
                        C[idx + j] = tf32f(a * gg + b2 * (1.f - gg));
                        C[idx + j + (size_t)CC * N] = tf32f(a * b2);
                    }
                } else {
#pragma unroll
                    for (int j = 0; j < 2; j++) {
                        float v = j ? v1 : v0;
                        if (F & FL_RELU) v = fmaxf(v, 0.f);
                        if (F & FL_CVTO) v = tf32f(v);
                        C[idx + j] = v;
                    }
                }
            }
        }
    }
}

#define P_PROJ  (FL_BIAS | FL_DUAL | FL_HALF)
#define P_GATE  (FL_BIAS | FL_GATE)
#define P_FUS   (FL_BIAS | FL_RELU | FL_CVTO)
#define P_HEAD  (FL_BIAS)

// ---------------- q/k transpose: projH rows 0-63 -> qkT[i][64] ----------------
__global__ void __launch_bounds__(256) qkT_k(
    const __half* __restrict__ projH, __half* __restrict__ qkT)
{
    __shared__ __half smt[64][72];
    int mod = blockIdx.z, b = blockIdx.y, i0 = blockIdx.x * 64;
    const __half* src = projH + (size_t)(mod * NB + b) * MPROJ * HWP;
    __half* dst = qkT + (size_t)(mod * NB + b) * HWP * 64;
    int tid = threadIdx.x;
#pragma unroll
    for (int t = 0; t < 16; t++) {
        int e = tid + t * 256;
        int r = e >> 6, ii = e & 63;
        smt[ii][r] = src[(size_t)r * HWP + i0 + ii];
    }
    __syncthreads();
#pragma unroll
    for (int t = 0; t < 16; t++) {
        int e = tid + t * 256;
        int ii = e >> 6, r = e & 63;
        dst[(size_t)(i0 + ii) * 64 + r] = smt[ii][r];
    }
}

// ---------------- z pass (fp16 mma): invZ[i] = 1/sum_j exp(S[i,j]) ----------------
#define ZSH 40
__global__ void __launch_bounds__(256) attn_z_k(
    const __half* __restrict__ qkT, float* __restrict__ invZ)
{
    __shared__ __half qT[64 * ZSH];
    __shared__ __half kT[2][128 * ZSH];
    __shared__ float zred[4][64];

    const int sel = blockIdx.z, b = blockIdx.y;
    const __half* QK = qkT + (size_t)((1 - sel) * NB + b) * HWP * 64;
    invZ += (size_t)(sel * NB + b) * HWP;

    const int i0 = blockIdx.x * 64;
    const int tid = threadIdx.x;
    const int lane = tid & 31, warp = tid >> 5;
    const int g = lane >> 2, t4 = lane & 3;
    const uint32_t qbase = (uint32_t)__cvta_generic_to_shared(qT);
    const uint32_t kbase = (uint32_t)__cvta_generic_to_shared(kT);

    // qT: 64 rows x 4 chunks (q cols 0-31)
    {
        int r = tid >> 2, ig = tid & 3;
        cp16(qbase + (uint32_t)((r * ZSH + ig * 8) * 2), QK + (size_t)(i0 + r) * 64 + ig * 8, true);
    }
    auto loadK = [&](int buf, int j0) {
#pragma unroll
        for (int rep = 0; rep < 2; rep++) {
            int c = tid + rep * 256;
            int r = c >> 2, ig = c & 3;
            cp16(kbase + (uint32_t)((buf * 128 * ZSH + r * ZSH + ig * 8) * 2),
                 QK + (size_t)(j0 + r) * 64 + 32 + ig * 8, true);
        }
    };
    loadK(0, 0);
    asm volatile("cp.async.commit_group;\n");

    float zacc[2][2] = {{0.f, 0.f}, {0.f, 0.f}};
    const int wm = (warp >> 2) * 32, wn = (warp & 3) * 32;

    for (int jc = 0; jc < 32; jc++) {
        int cur = jc & 1;
        asm volatile("cp.async.wait_group 0;\n");
        __syncthreads();
        if (jc + 1 < 32) {
            loadK(cur ^ 1, (jc + 1) * 128);
            asm volatile("cp.async.commit_group;\n");
        }
        const __half* kk_ = kT[cur];
        float sacc[2][4][4];
#pragma unroll
        for (int mt = 0; mt < 2; mt++)
#pragma unroll
            for (int nt = 0; nt < 4; nt++)
#pragma unroll
                for (int e = 0; e < 4; e++) sacc[mt][nt][e] = 0.f;
#pragma unroll
        for (int ks = 0; ks < 2; ks++) {
            int k0 = ks * 16;
            uint32_t a[2][4];
#pragma unroll
            for (int mt = 0; mt < 2; mt++) {
                int r0 = wm + mt * 16 + g;
                a[mt][0] = lds32h(qT + r0 * ZSH + k0 + 2 * t4);
                a[mt][1] = lds32h(qT + (r0 + 8) * ZSH + k0 + 2 * t4);
                a[mt][2] = lds32h(qT + r0 * ZSH + k0 + 2 * t4 + 8);
                a[mt][3] = lds32h(qT + (r0 + 8) * ZSH + k0 + 2 * t4 + 8);
            }
#pragma unroll
            for (int nt = 0; nt < 4; nt++) {
                int cb = wn + nt * 8 + g;
                uint32_t b0 = lds32h(kk_ + cb * ZSH + k0 + 2 * t4);
                uint32_t b1 = lds32h(kk_ + cb * ZSH + k0 + 2 * t4 + 8);
#pragma unroll
                for (int mt = 0; mt < 2; mt++) mma16h(sacc[mt][nt], a[mt], b0, b1);
            }
        }
#pragma unroll
        for (int mt = 0; mt < 2; mt++)
#pragma unroll
            for (int nt = 0; nt < 4; nt++) {
                zacc[mt][0] += __expf(sacc[mt][nt][0]) + __expf(sacc[mt][nt][1]);
                zacc[mt][1] += __expf(sacc[mt][nt][2]) + __expf(sacc[mt][nt][3]);
            }
    }
#pragma unroll
    for (int mt = 0; mt < 2; mt++)
#pragma unroll
        for (int h = 0; h < 2; h++) {
            float v = zacc[mt][h];
            v += __shfl_xor_sync(0xffffffffu, v, 1);
            v += __shfl_xor_sync(0xffffffffu, v, 2);
            if (t4 == 0) zred[warp & 3][wm + mt * 16 + h * 8 + g] = v;
        }
    __syncthreads();
    if (tid < 64) {
        float s = zred[0][tid] + zred[1][tid] + zred[2][tid] + zred[3][tid];
        invZ[i0 + tid] = 1.f / s;
    }
}

// ---------------- fused attention apply (fp16 mma, recompute S in smem) ----------------
#define ASH 40
#define AP_DKT 0
#define AP_DQ  (128 * ASH)                 // 5120
#define AP_RV  (AP_DQ + 2 * 32 * ASH)      // 7680
#define AP_ES  (AP_RV + 2 * 128 * ASH)     // 17920
#define AP_TOT (AP_ES + 128 * ASH)         // 23040 halfs = 46080 B

__global__ void __launch_bounds__(256, 2) attn_apply_k(
    const __half* __restrict__ qkT, const __half* __restrict__ projH,
    const float* __restrict__ invZg,
    const float* __restrict__ res0, const float* __restrict__ res1,
    float* __restrict__ out)
{
    __shared__ __half sm[AP_TOT];

    const int bz = blockIdx.z;
    const int sel = bz >> 1, b = bz & 1;
    const int j0 = blockIdx.x * 128;
    const int c0 = blockIdx.y * 128;
    const size_t sX = (size_t)CC * HWP;
    const size_t sF = (size_t)C2 * HWP;

    const __half* QK = qkT + (size_t)((1 - sel) * NB + b) * HWP * 64;
    const __half* V  = projH + (size_t)(sel * NB + b) * MPROJ * HWP
                     + (size_t)(64 + c0) * HWP;
    const float* invZ = invZg + (size_t)(sel * NB + b) * HWP;
    const float* res  = (sel ? res1 : res0) + (size_t)b * sX + (size_t)c0 * HWP;
    out += (size_t)b * sF + (size_t)sel * sX + (size_t)c0 * HWP;

    const int tid = threadIdx.x;
    const int lane = tid & 31, warp = tid >> 5;
    const int g = lane >> 2, t4 = lane & 3;
    const uint32_t sbase = (uint32_t)__cvta_generic_to_shared(sm);

    // dkT: 128 j-rows x 4 chunks (k cols 32-63)
#pragma unroll
    for (int rep = 0; rep < 2; rep++) {
        int c = tid + rep * 256;
        int r = c >> 2, ig = c & 3;
        cp16(sbase + (uint32_t)((AP_DKT + r * ASH + ig * 8) * 2),
             QK + (size_t)(j0 + r) * 64 + 32 + ig * 8, true);
    }
    auto loadQ = [&](int buf, int i0c) {
        if (tid < 128) {
            int r = tid >> 2, ig = tid & 3;
            cp16(sbase + (uint32_t)((AP_DQ + buf * 32 * ASH + r * ASH + ig * 8) * 2),
                 QK + (size_t)(i0c + r) * 64 + ig * 8, true);
        }
    };
    auto loadV = [&](int buf, int i0c) {
#pragma unroll
        for (int rep = 0; rep < 2; rep++) {
            int c = tid + rep * 256;
            int row = c >> 2, ig = c & 3;
            cp16(sbase + (uint32_t)((AP_RV + buf * 128 * ASH + row * ASH + ig * 8) * 2),
                 V + (size_t)row * HWP + i0c + ig * 8, true);
        }
    };
    loadQ(0, 0);
    loadV(0, 0);
    asm volatile("cp.async.commit_group;\n");

    float acc[4][4][4];
#pragma unroll
    for (int mt = 0; mt < 4; mt++)
#pragma unroll
        for (int nt = 0; nt < 4; nt++)
#pragma unroll
            for (int e = 0; e < 4; e++) acc[mt][nt][e] = 0.f;

    const int wj = warp * 16;
    const int wm = (warp >> 2) * 64, wn = (warp & 3) * 32;

    for (int ic = 0; ic < 128; ic++) {
        const int i0c = ic * 32;
        const int cur = ic & 1;
        asm volatile("cp.async.wait_group 0;\n");
        __syncthreads();          // buffers ready + prev phase-B done (eS reusable)
        if (ic + 1 < 128) {
            loadQ(cur ^ 1, i0c + 32);
            loadV(cur ^ 1, i0c + 32);
            asm volatile("cp.async.commit_group;\n");
        }
        // ---- phase A: S'[j (m=128), i (n=32)], k=r=32 (2 ksteps) ----
        const __half* dq = sm + AP_DQ + cur * 32 * ASH;
        float sacc[4][4];
#pragma unroll
        for (int nt = 0; nt < 4; nt++)
#pragma unroll
            for (int e = 0; e < 4; e++) sacc[nt][e] = 0.f;
#pragma unroll
        for (int ks = 0; ks < 2; ks++) {
            int k0 = ks * 16;
            uint32_t a[4];
            a[0] = lds32h(sm + AP_DKT + (wj + g) * ASH + k0 + 2 * t4);
            a[1] = lds32h(sm + AP_DKT + (wj + g + 8) * ASH + k0 + 2 * t4);
            a[2] = lds32h(sm + AP_DKT + (wj + g) * ASH + k0 + 2 * t4 + 8);
            a[3] = lds32h(sm + AP_DKT + (wj + g + 8) * ASH + k0 + 2 * t4 + 8);
#pragma unroll
            for (int nt = 0; nt < 4; nt++) {
                int ci = nt * 8 + g;
                uint32_t b0 = lds32h(dq + ci * ASH + k0 + 2 * t4);
                uint32_t b1 = lds32h(dq + ci * ASH + k0 + 2 * t4 + 8);
                mma16h(sacc[nt], a, b0, b1);
            }
        }
        // exp * invZ -> eS_T[j][i] as half2
#pragma unroll
        for (int nt = 0; nt < 4; nt++) {
            int il = nt * 8 + 2 * t4;
            float iz0 = invZ[i0c + il];
            float iz1 = invZ[i0c + il + 1];
            __half2 h0 = __floats2half2_rn(__expf(sacc[nt][0]) * iz0,
                                           __expf(sacc[nt][1]) * iz1);
            __half2 h1 = __floats2half2_rn(__expf(sacc[nt][2]) * iz0,
                                           __expf(sacc[nt][3]) * iz1);
            *(__half2*)(sm + AP_ES + (wj + g) * ASH + il) = h0;
            *(__half2*)(sm + AP_ES + (wj + g + 8) * ASH + il) = h1;
        }
        __syncthreads();
        // ---- phase B: acc[c (m=128), j (n=128)] += V_tile @ eS, k=i=32 (2 ksteps) ----
        const __half* rv = sm + AP_RV + cur * 128 * ASH;
#pragma unroll
        for (int ks = 0; ks < 2; ks++) {
            int k0 = ks * 16;
            uint32_t af[4][4];
#pragma unroll
            for (int mt = 0; mt < 4; mt++) {
                int r0 = wm + mt * 16 + g;
                af[mt][0] = lds32h(rv + r0 * ASH + k0 + 2 * t4);
                af[mt][1] = lds32h(rv + (r0 + 8) * ASH + k0 + 2 * t4);
                af[mt][2] = lds32h(rv + r0 * ASH + k0 + 2 * t4 + 8);
                af[mt][3] = lds32h(rv + (r0 + 8) * ASH + k0 + 2 * t4 + 8);
            }
#pragma unroll
            for (int nt = 0; nt < 4; nt++) {
                int cb = wn + nt * 8 + g;
                uint32_t b0 = lds32h(sm + AP_ES + cb * ASH + k0 + 2 * t4);
                uint32_t b1 = lds32h(sm + AP_ES + cb * ASH + k0 + 2 * t4 + 8);
#pragma unroll
                for (int mt = 0; mt < 4; mt++) mma16h(acc[mt][nt], af[mt], b0, b1);
            }
        }
    }
    // epilogue: + residual, tf32-rounded (cat feeds tf32 GEMM operands)
#pragma unroll
    for (int mt = 0; mt < 4; mt++)
#pragma unroll
        for (int nt = 0; nt < 4; nt++)
#pragma unroll
            for (int e = 0; e < 4; e++) {
                int row = wm + mt * 16 + g + (e >> 1) * 8;
                int col = j0 + wn + nt * 8 + 2 * t4 + (e & 1);
                size_t o = (size_t)row * HWP + col;
                out[o] = tf32f(acc[mt][nt][e] + res[o]);
            }
}

// ---------------- im2col ----------------
__global__ void __launch_bounds__(256) im2col_k(
    const float* __restrict__ in, float* __restrict__ col)
{
    size_t idx = (size_t)blockIdx.x * 256 + threadIdx.x;
    int p = (int)(idx % HWP);
    size_t t = idx / HWP;
    int row = (int)(t % KCOL);
    int n = (int)(t / KCOL);
    int tap = row % 9, ci = row / 9;
    int ky = tap / 3, kx = tap % 3;
    int y = p >> 6, x = p & 63;
    int yy = y + ky - 1, xx = x + kx - 1;
    float v = 0.f;
    if (yy >= 0 && yy < HH && xx >= 0 && xx < WW)
        v = in[(((size_t)n * C2 + ci) * HH + yy) * WW + xx];
    col[idx] = v;
}

// ---------------- host launcher ----------------
extern "C" void kernel_launch(void* const* d_in, const int* in_sizes, int n_in,
                              void* d_out, int out_size)
{
    const float* rgb  = (const float*)d_in[0];
    const float* chm  = (const float*)d_in[1];
    float* out = (float*)d_out;

    float *invZ, *cat, *fy, *y1, *col;
    float *wR, *wD, *bR, *bD, *wGate, *wF1, *wF2, *wHead, *bHead;
    __half *projH, *qkT;
    cudaGetSymbolAddress((void**)&projH, g_projH);
    cudaGetSymbolAddress((void**)&qkT, g_qkT);
    cudaGetSymbolAddress((void**)&invZ, g_invZ);
    cudaGetSymbolAddress((void**)&cat, g_cat);
    cudaGetSymbolAddress((void**)&fy, g_fy);
    cudaGetSymbolAddress((void**)&y1, g_y1);
    cudaGetSymbolAddress((void**)&col, g_col);
    cudaGetSymbolAddress((void**)&wR, g_wR);
    cudaGetSymbolAddress((void**)&wD, g_wD);
    cudaGetSymbolAddress((void**)&bR, g_bR);
    cudaGetSymbolAddress((void**)&bD, g_bD);
    cudaGetSymbolAddress((void**)&wGate, g_wGate);
    cudaGetSymbolAddress((void**)&wF1, g_wF1);
    cudaGetSymbolAddress((void**)&wF2, g_wF2);
    cudaGetSymbolAddress((void**)&wHead, g_wHead);
    cudaGetSymbolAddress((void**)&bHead, g_bHead);

    cudaFuncSetAttribute(tgemm_k<P_PROJ>, cudaFuncAttributeMaxDynamicSharedMemorySize, SMEM_BYTES);
    cudaFuncSetAttribute(tgemm_k<P_GATE>, cudaFuncAttributeMaxDynamicSharedMemorySize, SMEM_BYTES);
    cudaFuncSetAttribute(tgemm_k<P_FUS>,  cudaFuncAttributeMaxDynamicSharedMemorySize, SMEM_BYTES);
    cudaFuncSetAttribute(tgemm_k<P_HEAD>, cudaFuncAttributeMaxDynamicSharedMemorySize, SMEM_BYTES);

    dim3 blk(256);
    const size_t sX = (size_t)CC * HWP;
    const size_t sF = (size_t)C2 * HWP;
    const size_t sPH = (size_t)MPROJ * HWP;          // half units
    const size_t s1024 = (size_t)1024 * HWP;
    const size_t sCol = (size_t)KCOL * HWP;

    // --- prep ---
    PrepPtrs pp;
    pp.rq_w = (const float*)d_in[2];  pp.rq_b = (const float*)d_in[3];
    pp.rk_w = (const float*)d_in[4];  pp.rk_b = (const float*)d_in[5];
    pp.rv_w = (const float*)d_in[6];  pp.rv_b = (const float*)d_in[7];
    pp.dq_w = (const float*)d_in[8];  pp.dq_b = (const float*)d_in[9];
    pp.dk_w = (const float*)d_in[10]; pp.dk_b = (const float*)d_in[11];
    pp.dv_w = (const float*)d_in[12]; pp.dv_b = (const float*)d_in[13];
    pp.gate_w = (const float*)d_in[14];
    pp.fus1_w = (const float*)d_in[16];
    pp.fus2_w = (const float*)d_in[18];
    pp.fus3_w = (const float*)d_in[20]; pp.fus3_b = (const float*)d_in[21];
    pp.skip_w = (const float*)d_in[22]; pp.skip_b = (const float*)d_in[23];
    pp.wR = wR; pp.wD = wD; pp.wGate = wGate; pp.wF1 = wF1; pp.wF2 = wF2;
    pp.wHead = wHead; pp.bR = bR; pp.bD = bD; pp.bHead = bHead;
    prep_k<<<(PREP_TOT + 255) / 256, blk>>>(pp);

    const float* gate_b = (const float*)d_in[15];
    const float* fus1_b = (const float*)d_in[17];
    const float* fus2_b = (const float*)d_in[19];

    // --- projections (both modalities, fp16 output) ---
    tgemm_k<P_PROJ><<<dim3(32, 3, 4), blk, SMEM_BYTES>>>(
        wR, wD, CC, 0, rgb, chm, HWP, sX,
        (float*)projH, sPH, (size_t)NB * sPH, bR, bD, nullptr, 0, MPROJ, HWP, CC);

    // --- q/k transpose into [i][64] layout ---
    qkT_k<<<dim3(64, NB, 2), blk>>>(projH, qkT);

    // --- z pass (both attentions) ---
    attn_z_k<<<dim3(64, NB, 2), blk>>>(qkT, invZ);

    // --- fused apply: sel0 -> cat[:,0:C] (rv @ softmax(dq.dk) + rgb); sel1 -> cat[:,C:2C] ---
    attn_apply_k<<<dim3(32, 2, 4), blk>>>(qkT, projH, invZ, rgb, chm, cat);

    // --- gate GEMM + fused sigmoid-gated combine -> fy rows 0..511 (f) ---
    tgemm_k<P_GATE><<<dim3(32, 2, NB), blk, SMEM_BYTES>>>(
        wGate, nullptr, C2, 0, cat, nullptr, HWP, sF,
        fy, s1024, 0, gate_b, nullptr, cat, sF, CC, HWP, C2);

    // --- fus1: y1 = relu(W1 @ f + b1) ---
    tgemm_k<P_FUS><<<dim3(32, 4, NB), blk, SMEM_BYTES>>>(
        wF1, nullptr, C2, 0, fy, nullptr, HWP, s1024,
        y1, sF, 0, fus1_b, nullptr, nullptr, 0, C2, HWP, C2);

    // --- fus2: im2col + GEMM -> fy rows 512..1023 (y2) ---
    im2col_k<<<(unsigned)(((size_t)NB * KCOL * HWP) / 256), blk>>>(y1, col);
    tgemm_k<P_FUS><<<dim3(32, 4, NB), blk, SMEM_BYTES>>>(
        wF2, nullptr, KCOL, 0, col, nullptr, HWP, sCol,
        fy + 512 * HWP, s1024, 0, fus2_b, nullptr, nullptr, 0, C2, HWP, KCOL);

    // --- head: out = [skip | fus3] @ [f ; y2] + (bskip + b3) ---
    tgemm_k<P_HEAD><<<dim3(32, 2, NB), blk, SMEM_BYTES>>>(
        wHead, nullptr, 1024, 0, fy, nullptr, HWP, s1024,
        out, sX, 0, bHead, nullptr, nullptr, 0, CC, HWP, 1024);

    (void)in_sizes; (void)n_in; (void)out_size;
}

// round 12
// speedup vs baseline: 2.0239x; 1.1607x over previous
#include <cuda_runtime.h>
#include <cuda_fp16.h>
#include <cstdint>
#include <math.h>

#define NB 2
#define CC 256
#define RCQ 32
#define HH 64
#define WW 64
#define HWP 4096
#define C2 512
#define KCOL 4608
#define MPROJ 320

// ---------------- scratch ----------------
__device__ __half g_projH[(size_t)2 * NB * MPROJ * HWP];   // [mod][batch][320][4096] fp16
__device__ __half g_qkT[(size_t)2 * NB * HWP * 64];        // [mod][batch][i][q0-31|k32-63]
__device__ float g_invZ[4 * HWP];                          // [attn*2+batch][4096]
__device__ float g_cat[(size_t)NB * C2 * HWP];
__device__ float g_fy[(size_t)NB * 1024 * HWP];            // rows 0-511 f, 512-1023 y2
__device__ __half g_y1h[(size_t)NB * C2 * HWP];            // fus1 output, fp16
__device__ __half g_colh[(size_t)NB * HWP * KCOL];         // im2col, PIXEL-major [p][k], fp16
// weights
__device__ float g_wR[MPROJ * CC];
__device__ float g_wD[MPROJ * CC];
__device__ float g_bR[MPROJ];
__device__ float g_bD[MPROJ];
__device__ float g_wGate[CC * C2];
__device__ float g_wF1[C2 * C2];
__device__ __half g_wF2h[C2 * KCOL];
__device__ float g_wHead[CC * 1024];
__device__ float g_bHead[CC];

// ---------------- helpers ----------------
__device__ __forceinline__ void cp16(uint32_t dst, const void* src, bool v) {
    int sz = v ? 16 : 0;
    asm volatile("cp.async.cg.shared.global [%0], [%1], 16, %2;\n"
                 :: "r"(dst), "l"(src), "r"(sz));
}
__device__ __forceinline__ uint32_t cvt_tf32(float x) {
    uint32_t r;
    asm("cvt.rna.tf32.f32 %0, %1;" : "=r"(r) : "f"(x));
    return r;
}
__device__ __forceinline__ float tf32f(float x) { return __uint_as_float(cvt_tf32(x)); }
__device__ __forceinline__ void mma8(float* c, const uint32_t* a, uint32_t b0, uint32_t b1) {
    asm volatile(
        "mma.sync.aligned.m16n8k8.row.col.f32.tf32.tf32.f32 "
        "{%0,%1,%2,%3}, {%4,%5,%6,%7}, {%8,%9}, {%0,%1,%2,%3};"
        : "+f"(c[0]), "+f"(c[1]), "+f"(c[2]), "+f"(c[3])
        : "r"(a[0]), "r"(a[1]), "r"(a[2]), "r"(a[3]), "r"(b0), "r"(b1));
}
__device__ __forceinline__ void mma16h(float* c, const uint32_t* a, uint32_t b0, uint32_t b1) {
    asm volatile(
        "mma.sync.aligned.m16n8k16.row.col.f32.f16.f16.f32 "
        "{%0,%1,%2,%3}, {%4,%5,%6,%7}, {%8,%9}, {%0,%1,%2,%3};"
        : "+f"(c[0]), "+f"(c[1]), "+f"(c[2]), "+f"(c[3])
        : "r"(a[0]), "r"(a[1]), "r"(a[2]), "r"(a[3]), "r"(b0), "r"(b1));
}
__device__ __forceinline__ uint32_t lds32h(const __half* p) {
    return *(const uint32_t*)p;
}

// ---------------- single prep kernel: weight cvt + concat + biases ----------------
struct PrepPtrs {
    const float *rq_w, *rk_w, *rv_w, *dq_w, *dk_w, *dv_w;
    const float *gate_w, *fus1_w, *fus2_w, *fus3_w, *skip_w;
    const float *rq_b, *rk_b, *rv_b, *dq_b, *dk_b, *dv_b, *fus3_b, *skip_b;
    float *wR, *wD, *wGate, *wF1, *wHead, *bR, *bD, *bHead;
    __half *wF2h;
};
#define PREP_TOT 3179392
__global__ void __launch_bounds__(256) prep_k(PrepPtrs p) {
    int i = blockIdx.x * 256 + threadIdx.x;
    if (i >= PREP_TOT) return;
    if (i < 8192)            p.wR[i] = tf32f(p.rq_w[i]);
    else if (i < 16384)      p.wR[i] = tf32f(p.rk_w[i - 8192]);
    else if (i < 81920)      p.wR[i] = tf32f(p.rv_w[i - 16384]);
    else if (i < 90112)      p.wD[i - 81920] = tf32f(p.dq_w[i - 81920]);
    else if (i < 98304)      p.wD[i - 81920] = tf32f(p.dk_w[i - 90112]);
    else if (i < 163840)     p.wD[i - 81920] = tf32f(p.dv_w[i - 98304]);
    else if (i < 294912)     p.wGate[i - 163840] = tf32f(p.gate_w[i - 163840]);
    else if (i < 557056)     p.wF1[i - 294912] = tf32f(p.fus1_w[i - 294912]);
    else if (i < 2916352)    p.wF2h[i - 557056] = __float2half(p.fus2_w[i - 557056]);
    else if (i < 3178496) {
        int j = i - 2916352;
        int m = j >> 10, k = j & 1023;
        float v = (k < 512) ? p.skip_w[m * 512 + k] : p.fus3_w[m * 512 + k - 512];
        p.wHead[j] = tf32f(v);
    } else if (i < 3178816) {
        int j = i - 3178496;
        p.bR[j] = (j < 32) ? p.rq_b[j] : (j < 64) ? p.rk_b[j - 32] : p.rv_b[j - 64];
    } else if (i < 3179136) {
        int j = i - 3178816;
        p.bD[j] = (j < 32) ? p.dq_b[j] : (j < 64) ? p.dk_b[j - 32] : p.dv_b[j - 64];
    } else {
        int j = i - 3179136;
        p.bHead[j] = p.fus3_b[j] + p.skip_b[j];
    }
}

// ---------------- TF32 GEMM (f32 in, f32 or f16 out) ----------------
#define FL_RELU 2
#define FL_BIAS 8
#define FL_GATE 16
#define FL_CVTO 32
#define FL_DUAL 64
#define FL_HALF 256

#define ASTR 36
#define BSTR 136
#define ABUF (128 * ASTR)
#define BBUF (32 * BSTR)
#define SMEM_BYTES ((2 * ABUF + 2 * BBUF) * 4)   // 71680

template <int F>
__global__ void __launch_bounds__(256, 2) tgemm_k(
    const float* __restrict__ A, const float* __restrict__ A2, int lda, size_t sA,
    const float* __restrict__ B, const float* __restrict__ B2, int ldb, size_t sB,
    float* __restrict__ Cf, size_t sC, size_t cSelOff,
    const float* __restrict__ bias, const float* __restrict__ bias2,
    const float* __restrict__ res, size_t sRes,
    int M, int N, int K)
{
    extern __shared__ float sm[];
    const int bz = blockIdx.z;
    const int sel   = (F & FL_DUAL) ? (bz >> 1) : 0;
    const int batch = (F & FL_DUAL) ? (bz & 1) : bz;
    const float* Ap = (((F & FL_DUAL) && sel) ? A2 : A) + (size_t)batch * sA;
    const float* Bp = (((F & FL_DUAL) && sel) ? B2 : B) + (size_t)batch * sB;
    float* C = Cf;
    __half* Ch = nullptr;
    if (F & FL_HALF) Ch = (__half*)Cf + (size_t)batch * sC + (sel ? cSelOff : 0);
    else C = Cf + (size_t)batch * sC + (sel ? cSelOff : 0);
    const float* biasp = (((F & FL_DUAL) && sel) ? bias2 : bias);
    const float* resp = res ? res + (size_t)batch * sRes : nullptr;

    const int m0 = blockIdx.y * 128, n0 = blockIdx.x * 128;
    const int tid = threadIdx.x;
    const int lane = tid & 31, warp = tid >> 5;
    const int g = lane >> 2, t4 = lane & 3;
    const int wm = (warp >> 2) * 64;
    const int wn = (warp & 3) * 32;

    const uint32_t sbase = (uint32_t)__cvta_generic_to_shared(sm);

    float acc[4][4][4];
#pragma unroll
    for (int mt = 0; mt < 4; mt++)
#pragma unroll
        for (int nt = 0; nt < 4; nt++)
#pragma unroll
            for (int i = 0; i < 4; i++) acc[mt][nt][i] = 0.f;

    auto loadA = [&](int buf, int k0) {
#pragma unroll
        for (int i = 0; i < 4; i++) {
            int c = tid + i * 256;
            int m = c >> 3, kg = c & 7;
            bool v = (m0 + m) < M;
            int mm = v ? (m0 + m) : 0;
            const float* src = Ap + (size_t)mm * lda + k0 + kg * 4;
            uint32_t dst = sbase + (uint32_t)((buf * ABUF + m * ASTR + kg * 4) * 4);
            cp16(dst, src, v);
        }
    };
    auto loadB = [&](int buf, int k0) {
#pragma unroll
        for (int i = 0; i < 4; i++) {
            int c = tid + i * 256;
            int k = c >> 5, ng = c & 31;
            const float* src = Bp + (size_t)(k0 + k) * ldb + n0 + ng * 4;
            uint32_t dst = sbase + (uint32_t)((2 * ABUF + buf * BBUF + k * BSTR + ng * 4) * 4);
            cp16(dst, src, true);
        }
    };

    const int KT = K / 32;
    loadA(0, 0);
    loadB(0, 0);
    asm volatile("cp.async.commit_group;\n");

    int cur = 0;
    for (int kt = 0; kt < KT; kt++) {
        if (kt + 1 < KT) {
            loadA(cur ^ 1, (kt + 1) * 32);
            loadB(cur ^ 1, (kt + 1) * 32);
            asm volatile("cp.async.commit_group;\n");
            asm volatile("cp.async.wait_group 1;\n");
        } else {
            asm volatile("cp.async.wait_group 0;\n");
        }
        __syncthreads();

        const float* Ab = sm + cur * ABUF;
        const float* Bb = sm + 2 * ABUF + cur * BBUF;
#pragma unroll
        for (int ks = 0; ks < 4; ks++) {
            const int kk = ks * 8;
            uint32_t af[4][4];
#pragma unroll
            for (int mt = 0; mt < 4; mt++) {
                int r0 = wm + mt * 16 + g;
                af[mt][0] = __float_as_uint(Ab[r0 * ASTR + kk + t4]);
                af[mt][1] = __float_as_uint(Ab[(r0 + 8) * ASTR + kk + t4]);
                af[mt][2] = __float_as_uint(Ab[r0 * ASTR + kk + t4 + 4]);
                af[mt][3] = __float_as_uint(Ab[(r0 + 8) * ASTR + kk + t4 + 4]);
            }
#pragma unroll
            for (int nt = 0; nt < 4; nt++) {
                int cb = wn + nt * 8 + g;
                uint32_t b0 = __float_as_uint(Bb[(kk + t4) * BSTR + cb]);
                uint32_t b1 = __float_as_uint(Bb[(kk + t4 + 4) * BSTR + cb]);
#pragma unroll
                for (int mt = 0; mt < 4; mt++) mma8(acc[mt][nt], af[mt], b0, b1);
            }
        }
        __syncthreads();
        cur ^= 1;
    }

#pragma unroll
    for (int mt = 0; mt < 4; mt++) {
        int r0 = m0 + wm + mt * 16 + g;
#pragma unroll
        for (int nt = 0; nt < 4; nt++) {
            int cb = n0 + wn + nt * 8 + 2 * t4;
            const float* a4 = acc[mt][nt];
#pragma unroll
            for (int half = 0; half < 2; half++) {
                int r = r0 + half * 8;
                if (r >= M) continue;
                float bv = (F & FL_BIAS) ? biasp[r] : 0.f;
                float v0 = a4[half * 2 + 0] + bv;
                float v1 = a4[half * 2 + 1] + bv;
                if (F & FL_RELU) { v0 = fmaxf(v0, 0.f); v1 = fmaxf(v1, 0.f); }
                size_t idx = (size_t)r * N + cb;
                if (F & FL_HALF) {
                    *(__half2*)(Ch + idx) = __floats2half2_rn(v0, v1);
                } else if (F & FL_GATE) {
#pragma unroll
                    for (int j = 0; j < 2; j++) {
                        float v = j ? v1 : v0;
                        float a = resp[idx + j];
                        float b2 = resp[idx + j + (size_t)CC * N];
                        float gg = 1.f / (1.f + __expf(-v));
                        C[idx + j] = tf32f(a * gg + b2 * (1.f - gg));
                        C[idx + j + (size_t)CC * N] = tf32f(a * b2);
                    }
                } else {
#pragma unroll
                    for (int j = 0; j < 2; j++) {
                        float v = j ? v1 : v0;
                        if (F & FL_CVTO) v = tf32f(v);
                        C[idx + j] = v;
                    }
                }
            }
        }
    }
}

#define P_PROJ  (FL_BIAS | FL_DUAL | FL_HALF)
#define P_GATE  (FL_BIAS | FL_GATE)
#define P_FUS1  (FL_BIAS | FL_RELU | FL_HALF)
#define P_HEAD  (FL_BIAS)

// ---------------- FP16 GEMM for conv: C[m][n] = sum_k A[m][k]*B[n][k], relu+bias ------
#define HSTR 40
#define HG_ABUF (128 * HSTR)
__global__ void __launch_bounds__(256, 2) hgemm_k(
    const __half* __restrict__ A,                 // [M][K] half
    const __half* __restrict__ B, size_t sB,      // [N][K] half, per-batch stride
    float* __restrict__ C, size_t sC,             // [M][N] f32
    const float* __restrict__ bias,
    int N, int K)
{
    __shared__ __half hsm[4 * HG_ABUF];           // A double buf + B double buf = 40960 B

    const int batch = blockIdx.z;
    const int m0 = blockIdx.y * 128, n0 = blockIdx.x * 128;
    B += (size_t)batch * sB;
    C += (size_t)batch * sC;

    const int tid = threadIdx.x;
    const int lane = tid & 31, warp = tid >> 5;
    const int g = lane >> 2, t4 = lane & 3;
    const int wm = (warp >> 2) * 64, wn = (warp & 3) * 32;
    const uint32_t sbase = (uint32_t)__cvta_generic_to_shared(hsm);

    float acc[4][4][4];
#pragma unroll
    for (int mt = 0; mt < 4; mt++)
#pragma unroll
        for (int nt = 0; nt < 4; nt++)
#pragma unroll
            for (int e = 0; e < 4; e++) acc[mt][nt][e] = 0.f;

    auto loadA = [&](int buf, int k0) {
#pragma unroll
        for (int rep = 0; rep < 2; rep++) {
            int c = tid + rep * 256;
            int r = c >> 2, ig = c & 3;
            cp16(sbase + (uint32_t)((buf * HG_ABUF + r * HSTR + ig * 8) * 2),
                 A + (size_t)(m0 + r) * K + k0 + ig * 8, true);
        }
    };
    auto loadB = [&](int buf, int k0) {
#pragma unroll
        for (int rep = 0; rep < 2; rep++) {
            int c = tid + rep * 256;
            int r = c >> 2, ig = c & 3;
            cp16(sbase + (uint32_t)((2 * HG_ABUF + buf * HG_ABUF + r * HSTR + ig * 8) * 2),
                 B + (size_t)(n0 + r) * K + k0 + ig * 8, true);
        }
    };

    const int KT = K / 32;
    loadA(0, 0);
    loadB(0, 0);
    asm volatile("cp.async.commit_group;\n");

    int cur = 0;
    for (int kt = 0; kt < KT; kt++) {
        if (kt + 1 < KT) {
            loadA(cur ^ 1, (kt + 1) * 32);
            loadB(cur ^ 1, (kt + 1) * 32);
            asm volatile("cp.async.commit_group;\n");
            asm volatile("cp.async.wait_group 1;\n");
        } else {
            asm volatile("cp.async.wait_group 0;\n");
        }
        __syncthreads();

        const __half* Ab = hsm + cur * HG_ABUF;
        const __half* Bb = hsm + 2 * HG_ABUF + cur * HG_ABUF;
#pragma unroll
        for (int ks = 0; ks < 2; ks++) {
            int k0 = ks * 16;
            uint32_t af[4][4];
#pragma unroll
            for (int mt = 0; mt < 4; mt++) {
                int r0 = wm + mt * 16 + g;
                af[mt][0] = lds32h(Ab + r0 * HSTR + k0 + 2 * t4);
                af[mt][1] = lds32h(Ab + (r0 + 8) * HSTR + k0 + 2 * t4);
                af[mt][2] = lds32h(Ab + r0 * HSTR + k0 + 2 * t4 + 8);
                af[mt][3] = lds32h(Ab + (r0 + 8) * HSTR + k0 + 2 * t4 + 8);
            }
#pragma unroll
            for (int nt = 0; nt < 4; nt++) {
                int cb = wn + nt * 8 + g;
                uint32_t b0 = lds32h(Bb + cb * HSTR + k0 + 2 * t4);
                uint32_t b1 = lds32h(Bb + cb * HSTR + k0 + 2 * t4 + 8);
#pragma unroll
                for (int mt = 0; mt < 4; mt++) mma16h(acc[mt][nt], af[mt], b0, b1);
            }
        }
        __syncthreads();
        cur ^= 1;
    }

    // epilogue: bias + relu, f32 out
#pragma unroll
    for (int mt = 0; mt < 4; mt++) {
        int r0 = m0 + wm + mt * 16 + g;
#pragma unroll
        for (int nt = 0; nt < 4; nt++) {
            int cb = n0 + wn + nt * 8 + 2 * t4;
#pragma unroll
            for (int half = 0; half < 2; half++) {
                int r = r0 + half * 8;
                float bv = bias[r];
#pragma unroll
                for (int j = 0; j < 2; j++) {
                    float v = fmaxf(acc[mt][nt][half * 2 + j] + bv, 0.f);
                    C[(size_t)r * N + cb + j] = v;
                }
            }
        }
    }
}

// ---------------- q/k transpose: projH rows 0-63 -> qkT[i][64] ----------------
__global__ void __launch_bounds__(256) qkT_k(
    const __half* __restrict__ projH, __half* __restrict__ qkT)
{
    __shared__ __half smt[64][72];
    int mod = blockIdx.z, b = blockIdx.y, i0 = blockIdx.x * 64;
    const __half* src = projH + (size_t)(mod * NB + b) * MPROJ * HWP;
    __half* dst = qkT + (size_t)(mod * NB + b) * HWP * 64;
    int tid = threadIdx.x;
#pragma unroll
    for (int t = 0; t < 16; t++) {
        int e = tid + t * 256;
        int r = e >> 6, ii = e & 63;
        smt[ii][r] = src[(size_t)r * HWP + i0 + ii];
    }
    __syncthreads();
#pragma unroll
    for (int t = 0; t < 16; t++) {
        int e = tid + t * 256;
        int ii = e >> 6, r = e & 63;
        dst[(size_t)(i0 + ii) * 64 + r] = smt[ii][r];
    }
}

// ---------------- z pass (fp16 mma): invZ[i] = 1/sum_j exp(S[i,j]) ----------------
#define ZSH 40
__global__ void __launch_bounds__(256) attn_z_k(
    const __half* __restrict__ qkT, float* __restrict__ invZ)
{
    __shared__ __half qT[64 * ZSH];
    __shared__ __half kT[2][128 * ZSH];
    __shared__ float zred[4][64];

    const int sel = blockIdx.z, b = blockIdx.y;
    const __half* QK = qkT + (size_t)((1 - sel) * NB + b) * HWP * 64;
    invZ += (size_t)(sel * NB + b) * HWP;

    const int i0 = blockIdx.x * 64;
    const int tid = threadIdx.x;
    const int lane = tid & 31, warp = tid >> 5;
    const int g = lane >> 2, t4 = lane & 3;
    const uint32_t qbase = (uint32_t)__cvta_generic_to_shared(qT);
    const uint32_t kbase = (uint32_t)__cvta_generic_to_shared(kT);

    {
        int r = tid >> 2, ig = tid & 3;
        cp16(qbase + (uint32_t)((r * ZSH + ig * 8) * 2), QK + (size_t)(i0 + r) * 64 + ig * 8, true);
    }
    auto loadK = [&](int buf, int j0) {
#pragma unroll
        for (int rep = 0; rep < 2; rep++) {
            int c = tid + rep * 256;
            int r = c >> 2, ig = c & 3;
            cp16(kbase + (uint32_t)((buf * 128 * ZSH + r * ZSH + ig * 8) * 2),
                 QK + (size_t)(j0 + r) * 64 + 32 + ig * 8, true);
        }
    };
    loadK(0, 0);
    asm volatile("cp.async.commit_group;\n");

    float zacc[2][2] = {{0.f, 0.f}, {0.f, 0.f}};
    const int wm = (warp >> 2) * 32, wn = (warp & 3) * 32;

    for (int jc = 0; jc < 32; jc++) {
        int cur = jc & 1;
        asm volatile("cp.async.wait_group 0;\n");
        __syncthreads();
        if (jc + 1 < 32) {
            loadK(cur ^ 1, (jc + 1) * 128);
            asm volatile("cp.async.commit_group;\n");
        }
        const __half* kk_ = kT[cur];
        float sacc[2][4][4];
#pragma unroll
        for (int mt = 0; mt < 2; mt++)
#pragma unroll
            for (int nt = 0; nt < 4; nt++)
#pragma unroll
                for (int e = 0; e < 4; e++) sacc[mt][nt][e] = 0.f;
#pragma unroll
        for (int ks = 0; ks < 2; ks++) {
            int k0 = ks * 16;
            uint32_t a[2][4];
#pragma unroll
            for (int mt = 0; mt < 2; mt++) {
                int r0 = wm + mt * 16 + g;
                a[mt][0] = lds32h(qT + r0 * ZSH + k0 + 2 * t4);
                a[mt][1] = lds32h(qT + (r0 + 8) * ZSH + k0 + 2 * t4);
                a[mt][2] = lds32h(qT + r0 * ZSH + k0 + 2 * t4 + 8);
                a[mt][3] = lds32h(qT + (r0 + 8) * ZSH + k0 + 2 * t4 + 8);
            }
#pragma unroll
            for (int nt = 0; nt < 4; nt++) {
                int cb = wn + nt * 8 + g;
                uint32_t b0 = lds32h(kk_ + cb * ZSH + k0 + 2 * t4);
                uint32_t b1 = lds32h(kk_ + cb * ZSH + k0 + 2 * t4 + 8);
#pragma unroll
                for (int mt = 0; mt < 2; mt++) mma16h(sacc[mt][nt], a[mt], b0, b1);
            }
        }
#pragma unroll
        for (int mt = 0; mt < 2; mt++)
#pragma unroll
            for (int nt = 0; nt < 4; nt++) {
                zacc[mt][0] += __expf(sacc[mt][nt][0]) + __expf(sacc[mt][nt][1]);
                zacc[mt][1] += __expf(sacc[mt][nt][2]) + __expf(sacc[mt][nt][3]);
            }
    }
#pragma unroll
    for (int mt = 0; mt < 2; mt++)
#pragma unroll
        for (int h = 0; h < 2; h++) {
            float v = zacc[mt][h];
            v += __shfl_xor_sync(0xffffffffu, v, 1);
            v += __shfl_xor_sync(0xffffffffu, v, 2);
            if (t4 == 0) zred[warp & 3][wm + mt * 16 + h * 8 + g] = v;
        }
    __syncthreads();
    if (tid < 64) {
        float s = zred[0][tid] + zred[1][tid] + zred[2][tid] + zred[3][tid];
        invZ[i0 + tid] = 1.f / s;
    }
}

// ---------------- fused attention apply (fp16 mma, recompute S in smem) ----------------
#define ASH 40
#define AP_DKT 0
#define AP_DQ  (128 * ASH)
#define AP_RV  (AP_DQ + 2 * 32 * ASH)
#define AP_ES  (AP_RV + 2 * 128 * ASH)
#define AP_TOT (AP_ES + 128 * ASH)         // 23040 halfs = 46080 B

__global__ void __launch_bounds__(256, 2) attn_apply_k(
    const __half* __restrict__ qkT, const __half* __restrict__ projH,
    const float* __restrict__ invZg,
    const float* __restrict__ res0, const float* __restrict__ res1,
    float* __restrict__ out)
{
    __shared__ __half sm[AP_TOT];

    const int bz = blockIdx.z;
    const int sel = bz >> 1, b = bz & 1;
    const int j0 = blockIdx.x * 128;
    const int c0 = blockIdx.y * 128;
    const size_t sX = (size_t)CC * HWP;
    const size_t sF = (size_t)C2 * HWP;

    const __half* QK = qkT + (size_t)((1 - sel) * NB + b) * HWP * 64;
    const __half* V  = projH + (size_t)(sel * NB + b) * MPROJ * HWP
                     + (size_t)(64 + c0) * HWP;
    const float* invZ = invZg + (size_t)(sel * NB + b) * HWP;
    const float* res  = (sel ? res1 : res0) + (size_t)b * sX + (size_t)c0 * HWP;
    out += (size_t)b * sF + (size_t)sel * sX + (size_t)c0 * HWP;

    const int tid = threadIdx.x;
    const int lane = tid & 31, warp = tid >> 5;
    const int g = lane >> 2, t4 = lane & 3;
    const uint32_t sbase = (uint32_t)__cvta_generic_to_shared(sm);

#pragma unroll
    for (int rep = 0; rep < 2; rep++) {
        int c = tid + rep * 256;
        int r = c >> 2, ig = c & 3;
        cp16(sbase + (uint32_t)((AP_DKT + r * ASH + ig * 8) * 2),
             QK + (size_t)(j0 + r) * 64 + 32 + ig * 8, true);
    }
    auto loadQ = [&](int buf, int i0c) {
        if (tid < 128) {
            int r = tid >> 2, ig = tid & 3;
            cp16(sbase + (uint32_t)((AP_DQ + buf * 32 * ASH + r * ASH + ig * 8) * 2),
                 QK + (size_t)(i0c + r) * 64 + ig * 8, true);
        }
    };
    auto loadV = [&](int buf, int i0c) {
#pragma unroll
        for (int rep = 0; rep < 2; rep++) {
            int c = tid + rep * 256;
            int row = c >> 2, ig = c & 3;
            cp16(sbase + (uint32_t)((AP_RV + buf * 128 * ASH + row * ASH + ig * 8) * 2),
                 V + (size_t)row * HWP + i0c + ig * 8, true);
        }
    };
    loadQ(0, 0);
    loadV(0, 0);
    asm volatile("cp.async.commit_group;\n");

    float acc[4][4][4];
#pragma unroll
    for (int mt = 0; mt < 4; mt++)
#pragma unroll
        for (int nt = 0; nt < 4; nt++)
#pragma unroll
            for (int e = 0; e < 4; e++) acc[mt][nt][e] = 0.f;

    const int wj = warp * 16;
    const int wm = (warp >> 2) * 64, wn = (warp & 3) * 32;

    for (int ic = 0; ic < 128; ic++) {
        const int i0c = ic * 32;
        const int cur = ic & 1;
        asm volatile("cp.async.wait_group 0;\n");
        __syncthreads();
        if (ic + 1 < 128) {
            loadQ(cur ^ 1, i0c + 32);
            loadV(cur ^ 1, i0c + 32);
            asm volatile("cp.async.commit_group;\n");
        }
        const __half* dq = sm + AP_DQ + cur * 32 * ASH;
        float sacc[4][4];
#pragma unroll
        for (int nt = 0; nt < 4; nt++)
#pragma unroll
            for (int e = 0; e < 4; e++) sacc[nt][e] = 0.f;
#pragma unroll
        for (int ks = 0; ks < 2; ks++) {
            int k0 = ks * 16;
            uint32_t a[4];
            a[0] = lds32h(sm + AP_DKT + (wj + g) * ASH + k0 + 2 * t4);
            a[1] = lds32h(sm + AP_DKT + (wj + g + 8) * ASH + k0 + 2 * t4);
            a[2] = lds32h(sm + AP_DKT + (wj + g) * ASH + k0 + 2 * t4 + 8);
            a[3] = lds32h(sm + AP_DKT + (wj + g + 8) * ASH + k0 + 2 * t4 + 8);
#pragma unroll
            for (int nt = 0; nt < 4; nt++) {
                int ci = nt * 8 + g;
                uint32_t b0 = lds32h(dq + ci * ASH + k0 + 2 * t4);
                uint32_t b1 = lds32h(dq + ci * ASH + k0 + 2 * t4 + 8);
                mma16h(sacc[nt], a, b0, b1);
            }
        }
#pragma unroll
        for (int nt = 0; nt < 4; nt++) {
            int il = nt * 8 + 2 * t4;
            float iz0 = invZ[i0c + il];
            float iz1 = invZ[i0c + il + 1];
            __half2 h0 = __floats2half2_rn(__expf(sacc[nt][0]) * iz0,
                                           __expf(sacc[nt][1]) * iz1);
            __half2 h1 = __floats2half2_rn(__expf(sacc[nt][2]) * iz0,
                                           __expf(sacc[nt][3]) * iz1);
            *(__half2*)(sm + AP_ES + (wj + g) * ASH + il) = h0;
            *(__half2*)(sm + AP_ES + (wj + g + 8) * ASH + il) = h1;
        }
        __syncthreads();
        const __half* rv = sm + AP_RV + cur * 128 * ASH;
#pragma unroll
        for (int ks = 0; ks < 2; ks++) {
            int k0 = ks * 16;
            uint32_t af[4][4];
#pragma unroll
            for (int mt = 0; mt < 4; mt++) {
                int r0 = wm + mt * 16 + g;
                af[mt][0] = lds32h(rv + r0 * ASH + k0 + 2 * t4);
                af[mt][1] = lds32h(rv + (r0 + 8) * ASH + k0 + 2 * t4);
                af[mt][2] = lds32h(rv + r0 * ASH + k0 + 2 * t4 + 8);
                af[mt][3] = lds32h(rv + (r0 + 8) * ASH + k0 + 2 * t4 + 8);
            }
#pragma unroll
            for (int nt = 0; nt < 4; nt++) {
                int cb = wn + nt * 8 + g;
                uint32_t b0 = lds32h(sm + AP_ES + cb * ASH + k0 + 2 * t4);
                uint32_t b1 = lds32h(sm + AP_ES + cb * ASH + k0 + 2 * t4 + 8);
#pragma unroll
                for (int mt = 0; mt < 4; mt++) mma16h(acc[mt][nt], af[mt], b0, b1);
            }
        }
    }
#pragma unroll
    for (int mt = 0; mt < 4; mt++)
#pragma unroll
        for (int nt = 0; nt < 4; nt++)
#pragma unroll
            for (int e = 0; e < 4; e++) {
                int row = wm + mt * 16 + g + (e >> 1) * 8;
                int col = j0 + wn + nt * 8 + 2 * t4 + (e & 1);
                size_t o = (size_t)row * HWP + col;
                out[o] = tf32f(acc[mt][nt][e] + res[o]);
            }
}

// ---------------- im2col (half in, half out, PIXEL-major [p][k]) ----------------
__global__ void __launch_bounds__(256) im2col_k(
    const __half* __restrict__ in, __half* __restrict__ col)
{
    size_t idx = (size_t)blockIdx.x * 256 + threadIdx.x;   // NB*HWP*KCOL
    int k = (int)(idx % KCOL);
    size_t rest = idx / KCOL;
    int p = (int)(rest % HWP);
    int n = (int)(rest / HWP);
    int ci = k / 9, tap = k % 9;
    int ky = tap / 3, kx = tap % 3;
    int y = p >> 6, x = p & 63;
    int yy = y + ky - 1, xx = x + kx - 1;
    __half v = __float2half(0.f);
    if (yy >= 0 && yy < HH && xx >= 0 && xx < WW)
        v = in[(((size_t)n * C2 + ci) << 12) + yy * WW + xx];
    col[idx] = v;
}

// ---------------- host launcher ----------------
extern "C" void kernel_launch(void* const* d_in, const int* in_sizes, int n_in,
                              void* d_out, int out_size)
{
    const float* rgb  = (const float*)d_in[0];
    const float* chm  = (const float*)d_in[1];
    float* out = (float*)d_out;

    float *invZ, *cat, *fy;
    float *wR, *wD, *bR, *bD, *wGate, *wF1, *wHead, *bHead;
    __half *projH, *qkT, *y1h, *colh, *wF2h;
    cudaGetSymbolAddress((void**)&projH, g_projH);
    cudaGetSymbolAddress((void**)&qkT, g_qkT);
    cudaGetSymbolAddress((void**)&invZ, g_invZ);
    cudaGetSymbolAddress((void**)&cat, g_cat);
    cudaGetSymbolAddress((void**)&fy, g_fy);
    cudaGetSymbolAddress((void**)&y1h, g_y1h);
    cudaGetSymbolAddress((void**)&colh, g_colh);
    cudaGetSymbolAddress((void**)&wR, g_wR);
    cudaGetSymbolAddress((void**)&wD, g_wD);
    cudaGetSymbolAddress((void**)&bR, g_bR);
    cudaGetSymbolAddress((void**)&bD, g_bD);
    cudaGetSymbolAddress((void**)&wGate, g_wGate);
    cudaGetSymbolAddress((void**)&wF1, g_wF1);
    cudaGetSymbolAddress((void**)&wF2h, g_wF2h);
    cudaGetSymbolAddress((void**)&wHead, g_wHead);
    cudaGetSymbolAddress((void**)&bHead, g_bHead);

    cudaFuncSetAttribute(tgemm_k<P_PROJ>, cudaFuncAttributeMaxDynamicSharedMemorySize, SMEM_BYTES);
    cudaFuncSetAttribute(tgemm_k<P_GATE>, cudaFuncAttributeMaxDynamicSharedMemorySize, SMEM_BYTES);
    cudaFuncSetAttribute(tgemm_k<P_FUS1>, cudaFuncAttributeMaxDynamicSharedMemorySize, SMEM_BYTES);
    cudaFuncSetAttribute(tgemm_k<P_HEAD>, cudaFuncAttributeMaxDynamicSharedMemorySize, SMEM_BYTES);

    dim3 blk(256);
    const size_t sX = (size_t)CC * HWP;
    const size_t sF = (size_t)C2 * HWP;
    const size_t sPH = (size_t)MPROJ * HWP;          // half units
    const size_t s1024 = (size_t)1024 * HWP;
    const size_t sColH = (size_t)HWP * KCOL;         // half units

    // --- prep ---
    PrepPtrs pp;
    pp.rq_w = (const float*)d_in[2];  pp.rq_b = (const float*)d_in[3];
    pp.rk_w = (const float*)d_in[4];  pp.rk_b = (const float*)d_in[5];
    pp.rv_w = (const float*)d_in[6];  pp.rv_b = (const float*)d_in[7];
    pp.dq_w = (const float*)d_in[8];  pp.dq_b = (const float*)d_in[9];
    pp.dk_w = (const float*)d_in[10]; pp.dk_b = (const float*)d_in[11];
    pp.dv_w = (const float*)d_in[12]; pp.dv_b = (const float*)d_in[13];
    pp.gate_w = (const float*)d_in[14];
    pp.fus1_w = (const float*)d_in[16];
    pp.fus2_w = (const float*)d_in[18];
    pp.fus3_w = (const float*)d_in[20]; pp.fus3_b = (const float*)d_in[21];
    pp.skip_w = (const float*)d_in[22]; pp.skip_b = (const float*)d_in[23];
    pp.wR = wR; pp.wD = wD; pp.wGate = wGate; pp.wF1 = wF1; pp.wF2h = wF2h;
    pp.wHead = wHead; pp.bR = bR; pp.bD = bD; pp.bHead = bHead;
    prep_k<<<(PREP_TOT + 255) / 256, blk>>>(pp);

    const float* gate_b = (const float*)d_in[15];
    const float* fus1_b = (const float*)d_in[17];
    const float* fus2_b = (const float*)d_in[19];

    // --- projections (both modalities, fp16 output) ---
    tgemm_k<P_PROJ><<<dim3(32, 3, 4), blk, SMEM_BYTES>>>(
        wR, wD, CC, 0, rgb, chm, HWP, sX,
        (float*)projH, sPH, (size_t)NB * sPH, bR, bD, nullptr, 0, MPROJ, HWP, CC);

    // --- q/k transpose into [i][64] layout ---
    qkT_k<<<dim3(64, NB, 2), blk>>>(projH, qkT);

    // --- z pass (both attentions) ---
    attn_z_k<<<dim3(64, NB, 2), blk>>>(qkT, invZ);

    // --- fused apply: sel0 -> cat[:,0:C]; sel1 -> cat[:,C:2C] ---
    attn_apply_k<<<dim3(32, 2, 4), blk>>>(qkT, projH, invZ, rgb, chm, cat);

    // --- gate GEMM + fused sigmoid-gated combine -> fy rows 0..511 (f) ---
    tgemm_k<P_GATE><<<dim3(32, 2, NB), blk, SMEM_BYTES>>>(
        wGate, nullptr, C2, 0, cat, nullptr, HWP, sF,
        fy, s1024, 0, gate_b, nullptr, cat, sF, CC, HWP, C2);

    // --- fus1: y1h = relu(W1 @ f + b1), fp16 out ---
    tgemm_k<P_FUS1><<<dim3(32, 4, NB), blk, SMEM_BYTES>>>(
        wF1, nullptr, C2, 0, fy, nullptr, HWP, s1024,
        (float*)y1h, sF, 0, fus1_b, nullptr, nullptr, 0, C2, HWP, C2);

    // --- fus2: half im2col (pixel-major) + fp16 GEMM -> fy rows 512..1023 (y2, f32) ---
    im2col_k<<<(unsigned)(((size_t)NB * HWP * KCOL) / 256), blk>>>(y1h, colh);
    hgemm_k<<<dim3(32, 4, NB), blk>>>(
        wF2h, colh, sColH, fy + 512 * HWP, s1024, fus2_b, HWP, KCOL);

    // --- head: out = [skip | fus3] @ [f ; y2] + (bskip + b3) ---
    tgemm_k<P_HEAD><<<dim3(32, 2, NB), blk, SMEM_BYTES>>>(
        wHead, nullptr, 1024, 0, fy, nullptr, HWP, s1024,
        out, sX, 0, bHead, nullptr, nullptr, 0, CC, HWP, 1024);

    (void)in_sizes; (void)n_in; (void)out_size;
}

// round 14
// speedup vs baseline: 2.1076x; 1.0413x over previous
#include <cuda_runtime.h>
#include <cuda_fp16.h>
#include <cstdint>
#include <math.h>

#define NB 2
#define CC 256
#define RCQ 32
#define HH 64
#define WW 64
#define HWP 4096
#define C2 512
#define KCOL 4608
#define MPROJ 320

// ---------------- scratch ----------------
__device__ __half g_projH[(size_t)2 * NB * MPROJ * HWP];   // [mod][batch][320][4096] fp16
__device__ __half g_qkT[(size_t)2 * NB * HWP * 64];        // [mod][batch][i][q0-31|k32-63]
__device__ float g_invZ[4 * HWP];
__device__ float g_cat[(size_t)NB * C2 * HWP];             // channel-major f32 (tf32-rounded)
__device__ __half g_fyP[(size_t)NB * HWP * 1024];          // PIXEL-major [p][f 0:512 | y2 512:1024]
__device__ __half g_y1h[(size_t)NB * C2 * HWP];            // fus1 output, channel-major fp16
__device__ __half g_colh[(size_t)NB * HWP * KCOL];         // im2col, pixel-major [p][k], fp16
// weights
__device__ float g_wR[MPROJ * CC];
__device__ float g_wD[MPROJ * CC];
__device__ float g_bR[MPROJ];
__device__ float g_bD[MPROJ];
__device__ float g_wGate[CC * C2];
__device__ __half g_wF1h[C2 * C2];
__device__ __half g_wF2h[C2 * KCOL];
__device__ __half g_wHeadH[CC * 1024];
__device__ float g_bHead[CC];

// ---------------- helpers ----------------
__device__ __forceinline__ void cp16(uint32_t dst, const void* src, bool v) {
    int sz = v ? 16 : 0;
    asm volatile("cp.async.cg.shared.global [%0], [%1], 16, %2;\n"
                 :: "r"(dst), "l"(src), "r"(sz));
}
__device__ __forceinline__ uint32_t cvt_tf32(float x) {
    uint32_t r;
    asm("cvt.rna.tf32.f32 %0, %1;" : "=r"(r) : "f"(x));
    return r;
}
__device__ __forceinline__ float tf32f(float x) { return __uint_as_float(cvt_tf32(x)); }
__device__ __forceinline__ void mma8(float* c, const uint32_t* a, uint32_t b0, uint32_t b1) {
    asm volatile(
        "mma.sync.aligned.m16n8k8.row.col.f32.tf32.tf32.f32 "
        "{%0,%1,%2,%3}, {%4,%5,%6,%7}, {%8,%9}, {%0,%1,%2,%3};"
        : "+f"(c[0]), "+f"(c[1]), "+f"(c[2]), "+f"(c[3])
        : "r"(a[0]), "r"(a[1]), "r"(a[2]), "r"(a[3]), "r"(b0), "r"(b1));
}
__device__ __forceinline__ void mma16h(float* c, const uint32_t* a, uint32_t b0, uint32_t b1) {
    asm volatile(
        "mma.sync.aligned.m16n8k16.row.col.f32.f16.f16.f32 "
        "{%0,%1,%2,%3}, {%4,%5,%6,%7}, {%8,%9}, {%0,%1,%2,%3};"
        : "+f"(c[0]), "+f"(c[1]), "+f"(c[2]), "+f"(c[3])
        : "r"(a[0]), "r"(a[1]), "r"(a[2]), "r"(a[3]), "r"(b0), "r"(b1));
}
__device__ __forceinline__ uint32_t lds32h(const __half* p) {
    return *(const uint32_t*)p;
}

// ---------------- single prep kernel ----------------
struct PrepPtrs {
    const float *rq_w, *rk_w, *rv_w, *dq_w, *dk_w, *dv_w;
    const float *gate_w, *fus1_w, *fus2_w, *fus3_w, *skip_w;
    const float *rq_b, *rk_b, *rv_b, *dq_b, *dk_b, *dv_b, *fus3_b, *skip_b;
    float *wR, *wD, *wGate, *bR, *bD, *bHead;
    __half *wF1h, *wF2h, *wHeadH;
};
#define PREP_TOT 3179392
__global__ void __launch_bounds__(256) prep_k(PrepPtrs p) {
    int i = blockIdx.x * 256 + threadIdx.x;
    if (i >= PREP_TOT) return;
    if (i < 8192)            p.wR[i] = tf32f(p.rq_w[i]);
    else if (i < 16384)      p.wR[i] = tf32f(p.rk_w[i - 8192]);
    else if (i < 81920)      p.wR[i] = tf32f(p.rv_w[i - 16384]);
    else if (i < 90112)      p.wD[i - 81920] = tf32f(p.dq_w[i - 81920]);
    else if (i < 98304)      p.wD[i - 81920] = tf32f(p.dk_w[i - 90112]);
    else if (i < 163840)     p.wD[i - 81920] = tf32f(p.dv_w[i - 98304]);
    else if (i < 294912)     p.wGate[i - 163840] = tf32f(p.gate_w[i - 163840]);
    else if (i < 557056)     p.wF1h[i - 294912] = __float2half(p.fus1_w[i - 294912]);
    else if (i < 2916352)    p.wF2h[i - 557056] = __float2half(p.fus2_w[i - 557056]);
    else if (i < 3178496) {
        int j = i - 2916352;
        int m = j >> 10, k = j & 1023;
        float v = (k < 512) ? p.skip_w[m * 512 + k] : p.fus3_w[m * 512 + k - 512];
        p.wHeadH[j] = __float2half(v);
    } else if (i < 3178816) {
        int j = i - 3178496;
        p.bR[j] = (j < 32) ? p.rq_b[j] : (j < 64) ? p.rk_b[j - 32] : p.rv_b[j - 64];
    } else if (i < 3179136) {
        int j = i - 3178816;
        p.bD[j] = (j < 32) ? p.dq_b[j] : (j < 64) ? p.dk_b[j - 32] : p.dv_b[j - 64];
    } else {
        int j = i - 3179136;
        p.bHead[j] = p.fus3_b[j] + p.skip_b[j];
    }
}

// ---------------- TF32 GEMM (proj + gate) ----------------
#define FL_BIAS  8
#define FL_DUAL  64
#define FL_HALF  256
#define FL_GATET 512

#define ASTR 36
#define BSTR 136
#define ABUF (128 * ASTR)
#define BBUF (32 * BSTR)
#define SMEM_BYTES ((2 * ABUF + 2 * BBUF) * 4)   // 71680
#define TSTRIDE 136
#define TTILE (128 * TSTRIDE)                    // 17408 halfs per transpose tile

template <int F>
__global__ void __launch_bounds__(256, 2) tgemm_k(
    const float* __restrict__ A, const float* __restrict__ A2, int lda, size_t sA,
    const float* __restrict__ B, const float* __restrict__ B2, int ldb, size_t sB,
    float* __restrict__ Cf, size_t sC, size_t cSelOff,
    const float* __restrict__ bias, const float* __restrict__ bias2,
    const float* __restrict__ res, size_t sRes,
    int M, int N, int K)
{
    extern __shared__ float sm[];
    const int bz = blockIdx.z;
    const int sel   = (F & FL_DUAL) ? (bz >> 1) : 0;
    const int batch = (F & FL_DUAL) ? (bz & 1) : bz;
    const float* Ap = (((F & FL_DUAL) && sel) ? A2 : A) + (size_t)batch * sA;
    const float* Bp = (((F & FL_DUAL) && sel) ? B2 : B) + (size_t)batch * sB;
    __half* Ch = nullptr;
    if (F & (FL_HALF | FL_GATET))
        Ch = (__half*)Cf + (size_t)batch * sC + (sel ? cSelOff : 0);
    const float* biasp = (((F & FL_DUAL) && sel) ? bias2 : bias);
    const float* resp = res ? res + (size_t)batch * sRes : nullptr;

    const int m0 = blockIdx.y * 128, n0 = blockIdx.x * 128;
    const int tid = threadIdx.x;
    const int lane = tid & 31, warp = tid >> 5;
    const int g = lane >> 2, t4 = lane & 3;
    const int wm = (warp >> 2) * 64;
    const int wn = (warp & 3) * 32;

    const uint32_t sbase = (uint32_t)__cvta_generic_to_shared(sm);

    float acc[4][4][4];
#pragma unroll
    for (int mt = 0; mt < 4; mt++)
#pragma unroll
        for (int nt = 0; nt < 4; nt++)
#pragma unroll
            for (int i = 0; i < 4; i++) acc[mt][nt][i] = 0.f;

    auto loadA = [&](int buf, int k0) {
#pragma unroll
        for (int i = 0; i < 4; i++) {
            int c = tid + i * 256;
            int m = c >> 3, kg = c & 7;
            bool v = (m0 + m) < M;
            int mm = v ? (m0 + m) : 0;
            const float* src = Ap + (size_t)mm * lda + k0 + kg * 4;
            uint32_t dst = sbase + (uint32_t)((buf * ABUF + m * ASTR + kg * 4) * 4);
            cp16(dst, src, v);
        }
    };
    auto loadB = [&](int buf, int k0) {
#pragma unroll
        for (int i = 0; i < 4; i++) {
            int c = tid + i * 256;
            int k = c >> 5, ng = c & 31;
            const float* src = Bp + (size_t)(k0 + k) * ldb + n0 + ng * 4;
            uint32_t dst = sbase + (uint32_t)((2 * ABUF + buf * BBUF + k * BSTR + ng * 4) * 4);
            cp16(dst, src, true);
        }
    };

    const int KT = K / 32;
    loadA(0, 0);
    loadB(0, 0);
    asm volatile("cp.async.commit_group;\n");

    int cur = 0;
    for (int kt = 0; kt < KT; kt++) {
        if (kt + 1 < KT) {
            loadA(cur ^ 1, (kt + 1) * 32);
            loadB(cur ^ 1, (kt + 1) * 32);
            asm volatile("cp.async.commit_group;\n");
            asm volatile("cp.async.wait_group 1;\n");
        } else {
            asm volatile("cp.async.wait_group 0;\n");
        }
        __syncthreads();

        const float* Ab = sm + cur * ABUF;
        const float* Bb = sm + 2 * ABUF + cur * BBUF;
#pragma unroll
        for (int ks = 0; ks < 4; ks++) {
            const int kk = ks * 8;
            uint32_t af[4][4];
#pragma unroll
            for (int mt = 0; mt < 4; mt++) {
                int r0 = wm + mt * 16 + g;
                af[mt][0] = __float_as_uint(Ab[r0 * ASTR + kk + t4]);
                af[mt][1] = __float_as_uint(Ab[(r0 + 8) * ASTR + kk + t4]);
                af[mt][2] = __float_as_uint(Ab[r0 * ASTR + kk + t4 + 4]);
                af[mt][3] = __float_as_uint(Ab[(r0 + 8) * ASTR + kk + t4 + 4]);
            }
#pragma unroll
            for (int nt = 0; nt < 4; nt++) {
                int cb = wn + nt * 8 + g;
                uint32_t b0 = __float_as_uint(Bb[(kk + t4) * BSTR + cb]);
                uint32_t b1 = __float_as_uint(Bb[(kk + t4 + 4) * BSTR + cb]);
#pragma unroll
                for (int mt = 0; mt < 4; mt++) mma8(acc[mt][nt], af[mt], b0, b1);
            }
        }
        __syncthreads();
        cur ^= 1;
    }

    if (F & FL_GATET) {
        // gated combine + smem transpose -> pixel-major fyP (c_fused at m0, d_fused at 256+m0)
        __half* tsm = (__half*)sm;
#pragma unroll
        for (int mt = 0; mt < 4; mt++) {
            int cl0 = wm + mt * 16 + g;
#pragma unroll
            for (int nt = 0; nt < 4; nt++) {
                int pl0 = wn + nt * 8 + 2 * t4;
                const float* a4 = acc[mt][nt];
#pragma unroll
                for (int half = 0; half < 2; half++) {
                    int cl = cl0 + half * 8;
                    int rr = m0 + cl;
                    float bv = biasp[rr];
#pragma unroll
                    for (int j = 0; j < 2; j++) {
                        int pl = pl0 + j;
                        float v = a4[half * 2 + j] + bv;
                        size_t idx = (size_t)rr * N + n0 + pl;
                        float a = resp[idx];
                        float b2 = resp[idx + (size_t)CC * N];
                        float gg = 1.f / (1.f + __expf(-v));
                        tsm[pl * TSTRIDE + cl] = __float2half(a * gg + b2 * (1.f - gg));
                        tsm[TTILE + pl * TSTRIDE + cl] = __float2half(a * b2);
                    }
                }
            }
        }
        __syncthreads();
        int p = tid >> 1, cpart = (tid & 1) * 64;
        const uint4* s0 = (const uint4*)(tsm + p * TSTRIDE + cpart);
        uint4* d0 = (uint4*)(Ch + (size_t)(n0 + p) * 1024 + m0 + cpart);
#pragma unroll
        for (int t = 0; t < 8; t++) d0[t] = s0[t];
        const uint4* s1 = (const uint4*)(tsm + TTILE + p * TSTRIDE + cpart);
        uint4* d1 = (uint4*)(Ch + (size_t)(n0 + p) * 1024 + 256 + m0 + cpart);
#pragma unroll
        for (int t = 0; t < 8; t++) d1[t] = s1[t];
        return;
    }

    // FL_HALF epilogue (projections)
#pragma unroll
    for (int mt = 0; mt < 4; mt++) {
        int r0 = m0 + wm + mt * 16 + g;
#pragma unroll
        for (int nt = 0; nt < 4; nt++) {
            int cb = n0 + wn + nt * 8 + 2 * t4;
            const float* a4 = acc[mt][nt];
#pragma unroll
            for (int half = 0; half < 2; half++) {
                int r = r0 + half * 8;
                if (r >= M) continue;
                float bv = (F & FL_BIAS) ? biasp[r] : 0.f;
                float v0 = a4[half * 2 + 0] + bv;
                float v1 = a4[half * 2 + 1] + bv;
                size_t idx = (size_t)r * N + cb;
                *(__half2*)(Ch + idx) = __floats2half2_rn(v0, v1);
            }
        }
    }
}

#define P_PROJ  (FL_BIAS | FL_DUAL | FL_HALF)
#define P_GATET (FL_BIAS | FL_GATET)

// ---------------- FP16 GEMM: C[m][n] = sum_k A[m][k]*B[n][k] ----------------
// E=0: half out channel-major + relu (fus1 -> y1h)
// E=1: half out TRANSPOSED into pixel-major fyP at colOff, + relu (conv -> fyP[p][512+c])
// E=2: f32 out channel-major, no relu (head -> out)
#define HSTR 40
#define HG_ABUF (128 * HSTR)
template <int E>
__global__ void __launch_bounds__(256, 2) hgemm_k(
    const __half* __restrict__ A,
    const __half* __restrict__ B, int ldb, size_t sB,
    void* __restrict__ Cout, size_t sC, int colOff,
    const float* __restrict__ bias,
    int N, int K)
{
    __shared__ __half hsm[4 * HG_ABUF];           // 40960 B

    const int batch = blockIdx.z;
    const int m0 = blockIdx.y * 128, n0 = blockIdx.x * 128;
    B += (size_t)batch * sB;

    const int tid = threadIdx.x;
    const int lane = tid & 31, warp = tid >> 5;
    const int g = lane >> 2, t4 = lane & 3;
    const int wm = (warp >> 2) * 64, wn = (warp & 3) * 32;
    const uint32_t sbase = (uint32_t)__cvta_generic_to_shared(hsm);

    float acc[4][4][4];
#pragma unroll
    for (int mt = 0; mt < 4; mt++)
#pragma unroll
        for (int nt = 0; nt < 4; nt++)
#pragma unroll
            for (int e = 0; e < 4; e++) acc[mt][nt][e] = 0.f;

    auto loadA = [&](int buf, int k0) {
#pragma unroll
        for (int rep = 0; rep < 2; rep++) {
            int c = tid + rep * 256;
            int r = c >> 2, ig = c & 3;
            cp16(sbase + (uint32_t)((buf * HG_ABUF + r * HSTR + ig * 8) * 2),
                 A + (size_t)(m0 + r) * K + k0 + ig * 8, true);
        }
    };
    auto loadB = [&](int buf, int k0) {
#pragma unroll
        for (int rep = 0; rep < 2; rep++) {
            int c = tid + rep * 256;
            int r = c >> 2, ig = c & 3;
            cp16(sbase + (uint32_t)((2 * HG_ABUF + buf * HG_ABUF + r * HSTR + ig * 8) * 2),
                 B + (size_t)(n0 + r) * ldb + k0 + ig * 8, true);
        }
    };

    const int KT = K / 32;
    loadA(0, 0);
    loadB(0, 0);
    asm volatile("cp.async.commit_group;\n");

    int cur = 0;
    for (int kt = 0; kt < KT; kt++) {
        if (kt + 1 < KT) {
            loadA(cur ^ 1, (kt + 1) * 32);
            loadB(cur ^ 1, (kt + 1) * 32);
            asm volatile("cp.async.commit_group;\n");
            asm volatile("cp.async.wait_group 1;\n");
        } else {
            asm volatile("cp.async.wait_group 0;\n");
        }
        __syncthreads();

        const __half* Ab = hsm + cur * HG_ABUF;
        const __half* Bb = hsm + 2 * HG_ABUF + cur * HG_ABUF;
#pragma unroll
        for (int ks = 0; ks < 2; ks++) {
            int k0 = ks * 16;
            uint32_t af[4][4];
#pragma unroll
            for (int mt = 0; mt < 4; mt++) {
                int r0 = wm + mt * 16 + g;
                af[mt][0] = lds32h(Ab + r0 * HSTR + k0 + 2 * t4);
                af[mt][1] = lds32h(Ab + (r0 + 8) * HSTR + k0 + 2 * t4);
                af[mt][2] = lds32h(Ab + r0 * HSTR + k0 + 2 * t4 + 8);
                af[mt][3] = lds32h(Ab + (r0 + 8) * HSTR + k0 + 2 * t4 + 8);
            }
#pragma unroll
            for (int nt = 0; nt < 4; nt++) {
                int cb = wn + nt * 8 + g;
                uint32_t b0 = lds32h(Bb + cb * HSTR + k0 + 2 * t4);
                uint32_t b1 = lds32h(Bb + cb * HSTR + k0 + 2 * t4 + 8);
#pragma unroll
                for (int mt = 0; mt < 4; mt++) mma16h(acc[mt][nt], af[mt], b0, b1);
            }
        }
        __syncthreads();
        cur ^= 1;
    }

    if (E == 1) {
        // transpose through smem -> pixel-major half at colOff
        __half* tsm = hsm;
#pragma unroll
        for (int mt = 0; mt < 4; mt++) {
            int cl0 = wm + mt * 16 + g;
#pragma unroll
            for (int nt = 0; nt < 4; nt++) {
                int pl0 = wn + nt * 8 + 2 * t4;
                const float* a4 = acc[mt][nt];
#pragma unroll
                for (int half = 0; half < 2; half++) {
                    int cl = cl0 + half * 8;
                    float bv = bias[m0 + cl];
#pragma unroll
                    for (int j = 0; j < 2; j++) {
                        float v = fmaxf(a4[half * 2 + j] + bv, 0.f);
                        tsm[(pl0 + j) * TSTRIDE + cl] = __float2half(v);
                    }
                }
            }
        }
        __syncthreads();
        __half* C = (__half*)Cout + (size_t)batch * sC;
        int p = tid >> 1, cpart = (tid & 1) * 64;
        const uint4* s0 = (const uint4*)(tsm + p * TSTRIDE + cpart);
        uint4* d0 = (uint4*)(C + (size_t)(n0 + p) * 1024 + colOff + m0 + cpart);
#pragma unroll
        for (int t = 0; t < 8; t++) d0[t] = s0[t];
    } else {
#pragma unroll
        for (int mt = 0; mt < 4; mt++) {
            int r0 = m0 + wm + mt * 16 + g;
#pragma unroll
            for (int nt = 0; nt < 4; nt++) {
                int cb = n0 + wn + nt * 8 + 2 * t4;
#pragma unroll
                for (int half = 0; half < 2; half++) {
                    int r = r0 + half * 8;
                    float bv = bias[r];
                    float v0 = acc[mt][nt][half * 2 + 0] + bv;
                    float v1 = acc[mt][nt][half * 2 + 1] + bv;
                    if (E == 0) {
                        v0 = fmaxf(v0, 0.f);
                        v1 = fmaxf(v1, 0.f);
                        __half* C = (__half*)Cout + (size_t)batch * sC;
                        *(__half2*)(C + (size_t)r * N + cb) = __floats2half2_rn(v0, v1);
                    } else {
                        float* C = (float*)Cout + (size_t)batch * sC;
                        C[(size_t)r * N + cb] = v0;
                        C[(size_t)r * N + cb + 1] = v1;
                    }
                }
            }
        }
    }
}

// ---------------- q/k transpose: projH rows 0-63 -> qkT[i][64] ----------------
__global__ void __launch_bounds__(256) qkT_k(
    const __half* __restrict__ projH, __half* __restrict__ qkT)
{
    __shared__ __half smt[64][72];
    int mod = blockIdx.z, b = blockIdx.y, i0 = blockIdx.x * 64;
    const __half* src = projH + (size_t)(mod * NB + b) * MPROJ * HWP;
    __half* dst = qkT + (size_t)(mod * NB + b) * HWP * 64;
    int tid = threadIdx.x;
#pragma unroll
    for (int t = 0; t < 16; t++) {
        int e = tid + t * 256;
        int r = e >> 6, ii = e & 63;
        smt[ii][r] = src[(size_t)r * HWP + i0 + ii];
    }
    __syncthreads();
#pragma unroll
    for (int t = 0; t < 16; t++) {
        int e = tid + t * 256;
        int ii = e >> 6, r = e & 63;
        dst[(size_t)(i0 + ii) * 64 + r] = smt[ii][r];
    }
}

// ---------------- z pass (fp16 mma): invZ[i] = 1/sum_j exp(S[i,j]) ----------------
#define ZSH 40
__global__ void __launch_bounds__(256) attn_z_k(
    const __half* __restrict__ qkT, float* __restrict__ invZ)
{
    __shared__ __half qT[64 * ZSH];
    __shared__ __half kT[2][128 * ZSH];
    __shared__ float zred[4][64];

    const int sel = blockIdx.z, b = blockIdx.y;
    const __half* QK = qkT + (size_t)((1 - sel) * NB + b) * HWP * 64;
    invZ += (size_t)(sel * NB + b) * HWP;

    const int i0 = blockIdx.x * 64;
    const int tid = threadIdx.x;
    const int lane = tid & 31, warp = tid >> 5;
    const int g = lane >> 2, t4 = lane & 3;
    const uint32_t qbase = (uint32_t)__cvta_generic_to_shared(qT);
    const uint32_t kbase = (uint32_t)__cvta_generic_to_shared(kT);

    {
        int r = tid >> 2, ig = tid & 3;
        cp16(qbase + (uint32_t)((r * ZSH + ig * 8) * 2), QK + (size_t)(i0 + r) * 64 + ig * 8, true);
    }
    auto loadK = [&](int buf, int j0) {
#pragma unroll
        for (int rep = 0; rep < 2; rep++) {
            int c = tid + rep * 256;
            int r = c >> 2, ig = c & 3;
            cp16(kbase + (uint32_t)((buf * 128 * ZSH + r * ZSH + ig * 8) * 2),
                 QK + (size_t)(j0 + r) * 64 + 32 + ig * 8, true);
        }
    };
    loadK(0, 0);
    asm volatile("cp.async.commit_group;\n");

    float zacc[2][2] = {{0.f, 0.f}, {0.f, 0.f}};
    const int wm = (warp >> 2) * 32, wn = (warp & 3) * 32;

    for (int jc = 0; jc < 32; jc++) {
        int cur = jc & 1;
        asm volatile("cp.async.wait_group 0;\n");
        __syncthreads();
        if (jc + 1 < 32) {
            loadK(cur ^ 1, (jc + 1) * 128);
            asm volatile("cp.async.commit_group;\n");
        }
        const __half* kk_ = kT[cur];
        float sacc[2][4][4];
#pragma unroll
        for (int mt = 0; mt < 2; mt++)
#pragma unroll
            for (int nt = 0; nt < 4; nt++)
#pragma unroll
                for (int e = 0; e < 4; e++) sacc[mt][nt][e] = 0.f;
#pragma unroll
        for (int ks = 0; ks < 2; ks++) {
            int k0 = ks * 16;
            uint32_t a[2][4];
#pragma unroll
            for (int mt = 0; mt < 2; mt++) {
                int r0 = wm + mt * 16 + g;
                a[mt][0] = lds32h(qT + r0 * ZSH + k0 + 2 * t4);
                a[mt][1] = lds32h(qT + (r0 + 8) * ZSH + k0 + 2 * t4);
                a[mt][2] = lds32h(qT + r0 * ZSH + k0 + 2 * t4 + 8);
                a[mt][3] = lds32h(qT + (r0 + 8) * ZSH + k0 + 2 * t4 + 8);
            }
#pragma unroll
            for (int nt = 0; nt < 4; nt++) {
                int cb = wn + nt * 8 + g;
                uint32_t b0 = lds32h(kk_ + cb * ZSH + k0 + 2 * t4);
                uint32_t b1 = lds32h(kk_ + cb * ZSH + k0 + 2 * t4 + 8);
#pragma unroll
                for (int mt = 0; mt < 2; mt++) mma16h(sacc[mt][nt], a[mt], b0, b1);
            }
        }
#pragma unroll
        for (int mt = 0; mt < 2; mt++)
#pragma unroll
            for (int nt = 0; nt < 4; nt++) {
                zacc[mt][0] += __expf(sacc[mt][nt][0]) + __expf(sacc[mt][nt][1]);
                zacc[mt][1] += __expf(sacc[mt][nt][2]) + __expf(sacc[mt][nt][3]);
            }
    }
#pragma unroll
    for (int mt = 0; mt < 2; mt++)
#pragma unroll
        for (int h = 0; h < 2; h++) {
            float v = zacc[mt][h];
            v += __shfl_xor_sync(0xffffffffu, v, 1);
            v += __shfl_xor_sync(0xffffffffu, v, 2);
            if (t4 == 0) zred[warp & 3][wm + mt * 16 + h * 8 + g] = v;
        }
    __syncthreads();
    if (tid < 64) {
        float s = zred[0][tid] + zred[1][tid] + zred[2][tid] + zred[3][tid];
        invZ[i0 + tid] = 1.f / s;
    }
}

// ---------------- fused attention apply (fp16 mma, recompute S in smem) ----------------
#define ASH 40
#define AP_DKT 0
#define AP_DQ  (128 * ASH)
#define AP_RV  (AP_DQ + 2 * 32 * ASH)
#define AP_ES  (AP_RV + 2 * 128 * ASH)
#define AP_TOT (AP_ES + 128 * ASH)         // 23040 halfs = 46080 B

__global__ void __launch_bounds__(256, 2) attn_apply_k(
    const __half* __restrict__ qkT, const __half* __restrict__ projH,
    const float* __restrict__ invZg,
    const float* __restrict__ res0, const float* __restrict__ res1,
    float* __restrict__ out)
{
    __shared__ __half sm[AP_TOT];

    const int bz = blockIdx.z;
    const int sel = bz >> 1, b = bz & 1;
    const int j0 = blockIdx.x * 128;
    const int c0 = blockIdx.y * 128;
    const size_t sX = (size_t)CC * HWP;
    const size_t sF = (size_t)C2 * HWP;

    const __half* QK = qkT + (size_t)((1 - sel) * NB + b) * HWP * 64;
    const __half* V  = projH + (size_t)(sel * NB + b) * MPROJ * HWP
                     + (size_t)(64 + c0) * HWP;
    const float* invZ = invZg + (size_t)(sel * NB + b) * HWP;
    const float* res  = (sel ? res1 : res0) + (size_t)b * sX + (size_t)c0 * HWP;
    out += (size_t)b * sF + (size_t)sel * sX + (size_t)c0 * HWP;

    const int tid = threadIdx.x;
    const int lane = tid & 31, warp = tid >> 5;
    const int g = lane >> 2, t4 = lane & 3;
    const uint32_t sbase = (uint32_t)__cvta_generic_to_shared(sm);

#pragma unroll
    for (int rep = 0; rep < 2; rep++) {
        int c = tid + rep * 256;
        int r = c >> 2, ig = c & 3;
        cp16(sbase + (uint32_t)((AP_DKT + r * ASH + ig * 8) * 2),
             QK + (size_t)(j0 + r) * 64 + 32 + ig * 8, true);
    }
    auto loadQ = [&](int buf, int i0c) {
        if (tid < 128) {
            int r = tid >> 2, ig = tid & 3;
            cp16(sbase + (uint32_t)((AP_DQ + buf * 32 * ASH + r * ASH + ig * 8) * 2),
                 QK + (size_t)(i0c + r) * 64 + ig * 8, true);
        }
    };
    auto loadV = [&](int buf, int i0c) {
#pragma unroll
        for (int rep = 0; rep < 2; rep++) {
            int c = tid + rep * 256;
            int row = c >> 2, ig = c & 3;
            cp16(sbase + (uint32_t)((AP_RV + buf * 128 * ASH + row * ASH + ig * 8) * 2),
                 V + (size_t)row * HWP + i0c + ig * 8, true);
        }
    };
    loadQ(0, 0);
    loadV(0, 0);
    asm volatile("cp.async.commit_group;\n");

    float acc[4][4][4];
#pragma unroll
    for (int mt = 0; mt < 4; mt++)
#pragma unroll
        for (int nt = 0; nt < 4; nt++)
#pragma unroll
            for (int e = 0; e < 4; e++) acc[mt][nt][e] = 0.f;

    const int wj = warp * 16;
    const int wm = (warp >> 2) * 64, wn = (warp & 3) * 32;

    for (int ic = 0; ic < 128; ic++) {
        const int i0c = ic * 32;
        const int cur = ic & 1;
        asm volatile("cp.async.wait_group 0;\n");
        __syncthreads();
        if (ic + 1 < 128) {
            loadQ(cur ^ 1, i0c + 32);
            loadV(cur ^ 1, i0c + 32);
            asm volatile("cp.async.commit_group;\n");
        }
        const __half* dq = sm + AP_DQ + cur * 32 * ASH;
        float sacc[4][4];
#pragma unroll
        for (int nt = 0; nt < 4; nt++)
#pragma unroll
            for (int e = 0; e < 4; e++) sacc[nt][e] = 0.f;
#pragma unroll
        for (int ks = 0; ks < 2; ks++) {
            int k0 = ks * 16;
            uint32_t a[4];
            a[0] = lds32h(sm + AP_DKT + (wj + g) * ASH + k0 + 2 * t4);
            a[1] = lds32h(sm + AP_DKT + (wj + g + 8) * ASH + k0 + 2 * t4);
            a[2] = lds32h(sm + AP_DKT + (wj + g) * ASH + k0 + 2 * t4 + 8);
            a[3] = lds32h(sm + AP_DKT + (wj + g + 8) * ASH + k0 + 2 * t4 + 8);
#pragma unroll
            for (int nt = 0; nt < 4; nt++) {
                int ci = nt * 8 + g;
                uint32_t b0 = lds32h(dq + ci * ASH + k0 + 2 * t4);
                uint32_t b1 = lds32h(dq + ci * ASH + k0 + 2 * t4 + 8);
                mma16h(sacc[nt], a, b0, b1);
            }
        }
#pragma unroll
        for (int nt = 0; nt < 4; nt++) {
            int il = nt * 8 + 2 * t4;
            float iz0 = invZ[i0c + il];
            float iz1 = invZ[i0c + il + 1];
            __half2 h0 = __floats2half2_rn(__expf(sacc[nt][0]) * iz0,
                                           __expf(sacc[nt][1]) * iz1);
            __half2 h1 = __floats2half2_rn(__expf(sacc[nt][2]) * iz0,
                                           __expf(sacc[nt][3]) * iz1);
            *(__half2*)(sm + AP_ES + (wj + g) * ASH + il) = h0;
            *(__half2*)(sm + AP_ES + (wj + g + 8) * ASH + il) = h1;
        }
        __syncthreads();
        const __half* rv = sm + AP_RV + cur * 128 * ASH;
#pragma unroll
        for (int ks = 0; ks < 2; ks++) {
            int k0 = ks * 16;
            uint32_t af[4][4];
#pragma unroll
            for (int mt = 0; mt < 4; mt++) {
                int r0 = wm + mt * 16 + g;
                af[mt][0] = lds32h(rv + r0 * ASH + k0 + 2 * t4);
                af[mt][1] = lds32h(rv + (r0 + 8) * ASH + k0 + 2 * t4);
                af[mt][2] = lds32h(rv + r0 * ASH + k0 + 2 * t4 + 8);
                af[mt][3] = lds32h(rv + (r0 + 8) * ASH + k0 + 2 * t4 + 8);
            }
#pragma unroll
            for (int nt = 0; nt < 4; nt++) {
                int cb = wn + nt * 8 + g;
                uint32_t b0 = lds32h(sm + AP_ES + cb * ASH + k0 + 2 * t4);
                uint32_t b1 = lds32h(sm + AP_ES + cb * ASH + k0 + 2 * t4 + 8);
#pragma unroll
                for (int mt = 0; mt < 4; mt++) mma16h(acc[mt][nt], af[mt], b0, b1);
            }
        }
    }
#pragma unroll
    for (int mt = 0; mt < 4; mt++)
#pragma unroll
        for (int nt = 0; nt < 4; nt++)
#pragma unroll
            for (int e = 0; e < 4; e++) {
                int row = wm + mt * 16 + g + (e >> 1) * 8;
                int col = j0 + wn + nt * 8 + 2 * t4 + (e & 1);
                size_t o = (size_t)row * HWP + col;
                out[o] = tf32f(acc[mt][nt][e] + res[o]);
            }
}

// ---------------- im2col (half in, half2 out, PIXEL-major [p][k]) ----------------
__global__ void __launch_bounds__(256) im2col_k(
    const __half* __restrict__ in, __half* __restrict__ col)
{
    size_t idx2 = (size_t)blockIdx.x * 256 + threadIdx.x;  // over NB*HWP*KCOL/2
    size_t idx = idx2 * 2;
    int k = (int)(idx % KCOL);
    size_t rest = idx / KCOL;
    int p = (int)(rest % HWP);
    int n = (int)(rest / HWP);
    int y = p >> 6, x = p & 63;
    __half v[2];
#pragma unroll
    for (int j = 0; j < 2; j++) {
        int kk = k + j;
        int ci = kk / 9, tap = kk % 9;
        int ky = tap / 3, kx = tap % 3;
        int yy = y + ky - 1, xx = x + kx - 1;
        v[j] = __float2half(0.f);
        if (yy >= 0 && yy < HH && xx >= 0 && xx < WW)
            v[j] = in[(((size_t)n * C2 + ci) << 12) + yy * WW + xx];
    }
    *(__half2*)(col + idx) = __halves2half2(v[0], v[1]);
}

// ---------------- host launcher ----------------
extern "C" void kernel_launch(void* const* d_in, const int* in_sizes, int n_in,
                              void* d_out, int out_size)
{
    const float* rgb  = (const float*)d_in[0];
    const float* chm  = (const float*)d_in[1];
    float* out = (float*)d_out;

    float *invZ, *cat;
    float *wR, *wD, *bR, *bD, *wGate, *bHead;
    __half *projH, *qkT, *y1h, *colh, *wF1h, *wF2h, *wHeadH, *fyP;
    cudaGetSymbolAddress((void**)&projH, g_projH);
    cudaGetSymbolAddress((void**)&qkT, g_qkT);
    cudaGetSymbolAddress((void**)&invZ, g_invZ);
    cudaGetSymbolAddress((void**)&cat, g_cat);
    cudaGetSymbolAddress((void**)&fyP, g_fyP);
    cudaGetSymbolAddress((void**)&y1h, g_y1h);
    cudaGetSymbolAddress((void**)&colh, g_colh);
    cudaGetSymbolAddress((void**)&wR, g_wR);
    cudaGetSymbolAddress((void**)&wD, g_wD);
    cudaGetSymbolAddress((void**)&bR, g_bR);
    cudaGetSymbolAddress((void**)&bD, g_bD);
    cudaGetSymbolAddress((void**)&wGate, g_wGate);
    cudaGetSymbolAddress((void**)&wF1h, g_wF1h);
    cudaGetSymbolAddress((void**)&wF2h, g_wF2h);
    cudaGetSymbolAddress((void**)&wHeadH, g_wHeadH);
    cudaGetSymbolAddress((void**)&bHead, g_bHead);

    cudaFuncSetAttribute(tgemm_k<P_PROJ>,  cudaFuncAttributeMaxDynamicSharedMemorySize, SMEM_BYTES);
    cudaFuncSetAttribute(tgemm_k<P_GATET>, cudaFuncAttributeMaxDynamicSharedMemorySize, SMEM_BYTES);

    dim3 blk(256);
    const size_t sX = (size_t)CC * HWP;
    const size_t sF = (size_t)C2 * HWP;
    const size_t sPH = (size_t)MPROJ * HWP;          // half units
    const size_t sFy = (size_t)HWP * 1024;           // half units
    const size_t sColH = (size_t)HWP * KCOL;         // half units

    // --- prep ---
    PrepPtrs pp;
    pp.rq_w = (const float*)d_in[2];  pp.rq_b = (const float*)d_in[3];
    pp.rk_w = (const float*)d_in[4];  pp.rk_b = (const float*)d_in[5];
    pp.rv_w = (const float*)d_in[6];  pp.rv_b = (const float*)d_in[7];
    pp.dq_w = (const float*)d_in[8];  pp.dq_b = (const float*)d_in[9];
    pp.dk_w = (const float*)d_in[10]; pp.dk_b = (const float*)d_in[11];
    pp.dv_w = (const float*)d_in[12]; pp.dv_b = (const float*)d_in[13];
    pp.gate_w = (const float*)d_in[14];
    pp.fus1_w = (const float*)d_in[16];
    pp.fus2_w = (const float*)d_in[18];
    pp.fus3_w = (const float*)d_in[20]; pp.fus3_b = (const float*)d_in[21];
    pp.skip_w = (const float*)d_in[22]; pp.skip_b = (const float*)d_in[23];
    pp.wR = wR; pp.wD = wD; pp.wGate = wGate;
    pp.wF1h = wF1h; pp.wF2h = wF2h; pp.wHeadH = wHeadH;
    pp.bR = bR; pp.bD = bD; pp.bHead = bHead;
    prep_k<<<(PREP_TOT + 255) / 256, blk>>>(pp);

    const float* gate_b = (const float*)d_in[15];
    const float* fus1_b = (const float*)d_in[17];
    const float* fus2_b = (const float*)d_in[19];

    // --- projections (both modalities, fp16 output) ---
    tgemm_k<P_PROJ><<<dim3(32, 3, 4), blk, SMEM_BYTES>>>(
        wR, wD, CC, 0, rgb, chm, HWP, sX,
        (float*)projH, sPH, (size_t)NB * sPH, bR, bD, nullptr, 0, MPROJ, HWP, CC);

    // --- q/k transpose into [i][64] layout ---
    qkT_k<<<dim3(64, NB, 2), blk>>>(projH, qkT);

    // --- z pass (both attentions) ---
    attn_z_k<<<dim3(64, NB, 2), blk>>>(qkT, invZ);

    // --- fused apply: sel0 -> cat[:,0:C]; sel1 -> cat[:,C:2C] ---
    attn_apply_k<<<dim3(32, 2, 4), blk>>>(qkT, projH, invZ, rgb, chm, cat);

    // --- gate GEMM + fused gated combine, transposed half out -> fyP[p][0:512] ---
    tgemm_k<P_GATET><<<dim3(32, 2, NB), blk, SMEM_BYTES>>>(
        wGate, nullptr, C2, 0, cat, nullptr, HWP, sF,
        (float*)fyP, sFy, 0, gate_b, nullptr, cat, sF, CC, HWP, C2);

    // --- fus1 (fp16): y1h = relu(W1 @ f + b1), channel-major ---
    hgemm_k<0><<<dim3(32, 4, NB), blk>>>(
        wF1h, fyP, 1024, sFy, y1h, sF, 0, fus1_b, HWP, C2);

    // --- fus2: half2 im2col + fp16 GEMM, transposed out -> fyP[p][512:1024] ---
    im2col_k<<<(unsigned)(((size_t)NB * HWP * KCOL) / 512), blk>>>(y1h, colh);
    hgemm_k<1><<<dim3(32, 4, NB), blk>>>(
        wF2h, colh, KCOL, sColH, fyP, sFy, 512, fus2_b, HWP, KCOL);

    // --- head (fp16, K=1024): out = [skip | fus3] @ [f ; y2] + (bskip + b3) ---
    hgemm_k<2><<<dim3(32, 2, NB), blk>>>(
        wHeadH, fyP, 1024, sFy, out, sX, 0, bHead, HWP, 1024);

    (void)in_sizes; (void)n_in; (void)out_size;
}

// round 15
// speedup vs baseline: 2.4705x; 1.1722x over previous
#include <cuda_runtime.h>
#include <cuda_fp16.h>
#include <cstdint>
#include <math.h>

#define NB 2
#define CC 256
#define RCQ 32
#define HH 64
#define WW 64
#define HWP 4096
#define C2 512
#define KCOL 4608
#define MPROJ 320
#define PADP 66
#define PADN (PADP * PADP)   // 4356 padded pixels

// ---------------- scratch ----------------
__device__ __half g_projH[(size_t)2 * NB * MPROJ * HWP];   // [mod][batch][320][4096] fp16
__device__ __half g_qkT[(size_t)2 * NB * HWP * 64];        // [mod][batch][i][q0-31|k32-63]
__device__ float g_invZ[4 * HWP];
__device__ float g_cat[(size_t)NB * C2 * HWP];             // channel-major f32 (tf32-rounded)
__device__ __half g_fyP[(size_t)NB * HWP * 1024];          // PIXEL-major [p][f 0:512 | y2 512:1024]
__device__ __half g_y1P[(size_t)NB * PADN * C2];           // padded pixel-major y1 (8.9 MB)
// weights
__device__ float g_wR[MPROJ * CC];
__device__ float g_wD[MPROJ * CC];
__device__ float g_bR[MPROJ];
__device__ float g_bD[MPROJ];
__device__ float g_wGate[CC * C2];
__device__ __half g_wF1h[C2 * C2];
__device__ __half g_wF2h[C2 * KCOL];                       // k reordered: tap*512 + ci
__device__ __half g_wHeadH[CC * 1024];
__device__ float g_bHead[CC];

// ---------------- helpers ----------------
__device__ __forceinline__ void cp16(uint32_t dst, const void* src, bool v) {
    int sz = v ? 16 : 0;
    asm volatile("cp.async.cg.shared.global [%0], [%1], 16, %2;\n"
                 :: "r"(dst), "l"(src), "r"(sz));
}
__device__ __forceinline__ uint32_t cvt_tf32(float x) {
    uint32_t r;
    asm("cvt.rna.tf32.f32 %0, %1;" : "=r"(r) : "f"(x));
    return r;
}
__device__ __forceinline__ float tf32f(float x) { return __uint_as_float(cvt_tf32(x)); }
__device__ __forceinline__ void mma8(float* c, const uint32_t* a, uint32_t b0, uint32_t b1) {
    asm volatile(
        "mma.sync.aligned.m16n8k8.row.col.f32.tf32.tf32.f32 "
        "{%0,%1,%2,%3}, {%4,%5,%6,%7}, {%8,%9}, {%0,%1,%2,%3};"
        : "+f"(c[0]), "+f"(c[1]), "+f"(c[2]), "+f"(c[3])
        : "r"(a[0]), "r"(a[1]), "r"(a[2]), "r"(a[3]), "r"(b0), "r"(b1));
}
__device__ __forceinline__ void mma16h(float* c, const uint32_t* a, uint32_t b0, uint32_t b1) {
    asm volatile(
        "mma.sync.aligned.m16n8k16.row.col.f32.f16.f16.f32 "
        "{%0,%1,%2,%3}, {%4,%5,%6,%7}, {%8,%9}, {%0,%1,%2,%3};"
        : "+f"(c[0]), "+f"(c[1]), "+f"(c[2]), "+f"(c[3])
        : "r"(a[0]), "r"(a[1]), "r"(a[2]), "r"(a[3]), "r"(b0), "r"(b1));
}
__device__ __forceinline__ uint32_t lds32h(const __half* p) {
    return *(const uint32_t*)p;
}

// ---------------- single prep kernel ----------------
struct PrepPtrs {
    const float *rq_w, *rk_w, *rv_w, *dq_w, *dk_w, *dv_w;
    const float *gate_w, *fus1_w, *fus2_w, *fus3_w, *skip_w;
    const float *rq_b, *rk_b, *rv_b, *dq_b, *dk_b, *dv_b, *fus3_b, *skip_b;
    float *wR, *wD, *wGate, *bR, *bD, *bHead;
    __half *wF1h, *wF2h, *wHeadH;
};
#define PREP_TOT 3179392
__global__ void __launch_bounds__(256) prep_k(PrepPtrs p) {
    int i = blockIdx.x * 256 + threadIdx.x;
    if (i >= PREP_TOT) return;
    if (i < 8192)            p.wR[i] = tf32f(p.rq_w[i]);
    else if (i < 16384)      p.wR[i] = tf32f(p.rk_w[i - 8192]);
    else if (i < 81920)      p.wR[i] = tf32f(p.rv_w[i - 16384]);
    else if (i < 90112)      p.wD[i - 81920] = tf32f(p.dq_w[i - 81920]);
    else if (i < 98304)      p.wD[i - 81920] = tf32f(p.dk_w[i - 90112]);
    else if (i < 163840)     p.wD[i - 81920] = tf32f(p.dv_w[i - 98304]);
    else if (i < 294912)     p.wGate[i - 163840] = tf32f(p.gate_w[i - 163840]);
    else if (i < 557056)     p.wF1h[i - 294912] = __float2half(p.fus1_w[i - 294912]);
    else if (i < 2916352) {
        // reorder conv weight k-index: src k = ci*9+tap  ->  dst k = tap*512+ci
        int j = i - 557056;
        int m = j / KCOL, rem = j % KCOL;
        int ci = rem / 9, tap = rem % 9;
        p.wF2h[(size_t)m * KCOL + tap * 512 + ci] = __float2half(p.fus2_w[j]);
    }
    else if (i < 3178496) {
        int j = i - 2916352;
        int m = j >> 10, k = j & 1023;
        float v = (k < 512) ? p.skip_w[m * 512 + k] : p.fus3_w[m * 512 + k - 512];
        p.wHeadH[j] = __float2half(v);
    } else if (i < 3178816) {
        int j = i - 3178496;
        p.bR[j] = (j < 32) ? p.rq_b[j] : (j < 64) ? p.rk_b[j - 32] : p.rv_b[j - 64];
    } else if (i < 3179136) {
        int j = i - 3178816;
        p.bD[j] = (j < 32) ? p.dq_b[j] : (j < 64) ? p.dk_b[j - 32] : p.dv_b[j - 64];
    } else {
        int j = i - 3179136;
        p.bHead[j] = p.fus3_b[j] + p.skip_b[j];
    }
}

// ---------------- zero y1P border (260 border pixels x 512 ch x NB) ----------------
#define ZB_TOT (NB * 260 * 64)   // uint4 count
__global__ void __launch_bounds__(256) zeroborder_k(__half* __restrict__ y1P) {
    int idx = blockIdx.x * 256 + threadIdx.x;
    if (idx >= ZB_TOT) return;
    int b = idx / (260 * 64);
    int rem = idx % (260 * 64);
    int pi = rem / 64, q = rem % 64;
    int y, x;
    if (pi < 66)       { y = 0;  x = pi; }
    else if (pi < 132) { y = 65; x = pi - 66; }
    else if (pi < 196) { y = pi - 132 + 1; x = 0; }
    else               { y = pi - 196 + 1; x = 65; }
    uint4 z = make_uint4(0, 0, 0, 0);
    ((uint4*)(y1P + ((size_t)b * PADN + y * PADP + x) * C2))[q] = z;
}

// ---------------- TF32 GEMM (proj + gate) ----------------
#define FL_BIAS  8
#define FL_DUAL  64
#define FL_HALF  256
#define FL_GATET 512

#define ASTR 36
#define BSTR 136
#define ABUF (128 * ASTR)
#define BBUF (32 * BSTR)
#define SMEM_BYTES ((2 * ABUF + 2 * BBUF) * 4)   // 71680
#define TSTRIDE 136
#define TTILE (128 * TSTRIDE)

template <int F>
__global__ void __launch_bounds__(256, 2) tgemm_k(
    const float* __restrict__ A, const float* __restrict__ A2, int lda, size_t sA,
    const float* __restrict__ B, const float* __restrict__ B2, int ldb, size_t sB,
    float* __restrict__ Cf, size_t sC, size_t cSelOff,
    const float* __restrict__ bias, const float* __restrict__ bias2,
    const float* __restrict__ res, size_t sRes,
    int M, int N, int K)
{
    extern __shared__ float sm[];
    const int bz = blockIdx.z;
    const int sel   = (F & FL_DUAL) ? (bz >> 1) : 0;
    const int batch = (F & FL_DUAL) ? (bz & 1) : bz;
    const float* Ap = (((F & FL_DUAL) && sel) ? A2 : A) + (size_t)batch * sA;
    const float* Bp = (((F & FL_DUAL) && sel) ? B2 : B) + (size_t)batch * sB;
    __half* Ch = nullptr;
    if (F & (FL_HALF | FL_GATET))
        Ch = (__half*)Cf + (size_t)batch * sC + (sel ? cSelOff : 0);
    const float* biasp = (((F & FL_DUAL) && sel) ? bias2 : bias);
    const float* resp = res ? res + (size_t)batch * sRes : nullptr;

    const int m0 = blockIdx.y * 128, n0 = blockIdx.x * 128;
    const int tid = threadIdx.x;
    const int lane = tid & 31, warp = tid >> 5;
    const int g = lane >> 2, t4 = lane & 3;
    const int wm = (warp >> 2) * 64;
    const int wn = (warp & 3) * 32;

    const uint32_t sbase = (uint32_t)__cvta_generic_to_shared(sm);

    float acc[4][4][4];
#pragma unroll
    for (int mt = 0; mt < 4; mt++)
#pragma unroll
        for (int nt = 0; nt < 4; nt++)
#pragma unroll
            for (int i = 0; i < 4; i++) acc[mt][nt][i] = 0.f;

    auto loadA = [&](int buf, int k0) {
#pragma unroll
        for (int i = 0; i < 4; i++) {
            int c = tid + i * 256;
            int m = c >> 3, kg = c & 7;
            bool v = (m0 + m) < M;
            int mm = v ? (m0 + m) : 0;
            const float* src = Ap + (size_t)mm * lda + k0 + kg * 4;
            uint32_t dst = sbase + (uint32_t)((buf * ABUF + m * ASTR + kg * 4) * 4);
            cp16(dst, src, v);
        }
    };
    auto loadB = [&](int buf, int k0) {
#pragma unroll
        for (int i = 0; i < 4; i++) {
            int c = tid + i * 256;
            int k = c >> 5, ng = c & 31;
            const float* src = Bp + (size_t)(k0 + k) * ldb + n0 + ng * 4;
            uint32_t dst = sbase + (uint32_t)((2 * ABUF + buf * BBUF + k * BSTR + ng * 4) * 4);
            cp16(dst, src, true);
        }
    };

    const int KT = K / 32;
    loadA(0, 0);
    loadB(0, 0);
    asm volatile("cp.async.commit_group;\n");

    int cur = 0;
    for (int kt = 0; kt < KT; kt++) {
        if (kt + 1 < KT) {
            loadA(cur ^ 1, (kt + 1) * 32);
            loadB(cur ^ 1, (kt + 1) * 32);
            asm volatile("cp.async.commit_group;\n");
            asm volatile("cp.async.wait_group 1;\n");
        } else {
            asm volatile("cp.async.wait_group 0;\n");
        }
        __syncthreads();

        const float* Ab = sm + cur * ABUF;
        const float* Bb = sm + 2 * ABUF + cur * BBUF;
#pragma unroll
        for (int ks = 0; ks < 4; ks++) {
            const int kk = ks * 8;
            uint32_t af[4][4];
#pragma unroll
            for (int mt = 0; mt < 4; mt++) {
                int r0 = wm + mt * 16 + g;
                af[mt][0] = __float_as_uint(Ab[r0 * ASTR + kk + t4]);
                af[mt][1] = __float_as_uint(Ab[(r0 + 8) * ASTR + kk + t4]);
                af[mt][2] = __float_as_uint(Ab[r0 * ASTR + kk + t4 + 4]);
                af[mt][3] = __float_as_uint(Ab[(r0 + 8) * ASTR + kk + t4 + 4]);
            }
#pragma unroll
            for (int nt = 0; nt < 4; nt++) {
                int cb = wn + nt * 8 + g;
                uint32_t b0 = __float_as_uint(Bb[(kk + t4) * BSTR + cb]);
                uint32_t b1 = __float_as_uint(Bb[(kk + t4 + 4) * BSTR + cb]);
#pragma unroll
                for (int mt = 0; mt < 4; mt++) mma8(acc[mt][nt], af[mt], b0, b1);
            }
        }
        __syncthreads();
        cur ^= 1;
    }

    if (F & FL_GATET) {
        __half* tsm = (__half*)sm;
#pragma unroll
        for (int mt = 0; mt < 4; mt++) {
            int cl0 = wm + mt * 16 + g;
#pragma unroll
            for (int nt = 0; nt < 4; nt++) {
                int pl0 = wn + nt * 8 + 2 * t4;
                const float* a4 = acc[mt][nt];
#pragma unroll
                for (int half = 0; half < 2; half++) {
                    int cl = cl0 + half * 8;
                    int rr = m0 + cl;
                    float bv = biasp[rr];
#pragma unroll
                    for (int j = 0; j < 2; j++) {
                        int pl = pl0 + j;
                        float v = a4[half * 2 + j] + bv;
                        size_t idx = (size_t)rr * N + n0 + pl;
                        float a = resp[idx];
                        float b2 = resp[idx + (size_t)CC * N];
                        float gg = 1.f / (1.f + __expf(-v));
                        tsm[pl * TSTRIDE + cl] = __float2half(a * gg + b2 * (1.f - gg));
                        tsm[TTILE + pl * TSTRIDE + cl] = __float2half(a * b2);
                    }
                }
            }
        }
        __syncthreads();
        int p = tid >> 1, cpart = (tid & 1) * 64;
        const uint4* s0 = (const uint4*)(tsm + p * TSTRIDE + cpart);
        uint4* d0 = (uint4*)(Ch + (size_t)(n0 + p) * 1024 + m0 + cpart);
#pragma unroll
        for (int t = 0; t < 8; t++) d0[t] = s0[t];
        const uint4* s1 = (const uint4*)(tsm + TTILE + p * TSTRIDE + cpart);
        uint4* d1 = (uint4*)(Ch + (size_t)(n0 + p) * 1024 + 256 + m0 + cpart);
#pragma unroll
        for (int t = 0; t < 8; t++) d1[t] = s1[t];
        return;
    }

    // FL_HALF epilogue (projections)
#pragma unroll
    for (int mt = 0; mt < 4; mt++) {
        int r0 = m0 + wm + mt * 16 + g;
#pragma unroll
        for (int nt = 0; nt < 4; nt++) {
            int cb = n0 + wn + nt * 8 + 2 * t4;
            const float* a4 = acc[mt][nt];
#pragma unroll
            for (int half = 0; half < 2; half++) {
                int r = r0 + half * 8;
                if (r >= M) continue;
                float bv = (F & FL_BIAS) ? biasp[r] : 0.f;
                float v0 = a4[half * 2 + 0] + bv;
                float v1 = a4[half * 2 + 1] + bv;
                size_t idx = (size_t)r * N + cb;
                *(__half2*)(Ch + idx) = __floats2half2_rn(v0, v1);
            }
        }
    }
}

#define P_PROJ  (FL_BIAS | FL_DUAL | FL_HALF)
#define P_GATET (FL_BIAS | FL_GATET)

// ---------------- FP16 GEMM: C[m][n] = sum_k A[m][k]*B[n][k] ----------------
// E=1: implicit-conv B (padded y1P, tap-shifted), relu, transposed out -> fyP[p][512+c]
// E=2: normal B, f32 out, no relu (head)
// E=3: normal B, relu, transposed out -> padded y1P (fus1)
#define HSTR 40
#define HG_ABUF (128 * HSTR)
template <int E>
__global__ void __launch_bounds__(256, 2) hgemm_k(
    const __half* __restrict__ A,
    const __half* __restrict__ B, int ldb, size_t sB,
    void* __restrict__ Cout, size_t sC, int colOff,
    const float* __restrict__ bias,
    int N, int K)
{
    __shared__ __half hsm[4 * HG_ABUF];           // 40960 B

    const int batch = blockIdx.z;
    const int m0 = blockIdx.y * 128, n0 = blockIdx.x * 128;
    B += (size_t)batch * sB;

    const int tid = threadIdx.x;
    const int lane = tid & 31, warp = tid >> 5;
    const int g = lane >> 2, t4 = lane & 3;
    const int wm = (warp >> 2) * 64, wn = (warp & 3) * 32;
    const uint32_t sbase = (uint32_t)__cvta_generic_to_shared(hsm);

    float acc[4][4][4];
#pragma unroll
    for (int mt = 0; mt < 4; mt++)
#pragma unroll
        for (int nt = 0; nt < 4; nt++)
#pragma unroll
            for (int e = 0; e < 4; e++) acc[mt][nt][e] = 0.f;

    auto loadA = [&](int buf, int k0) {
#pragma unroll
        for (int rep = 0; rep < 2; rep++) {
            int c = tid + rep * 256;
            int r = c >> 2, ig = c & 3;
            cp16(sbase + (uint32_t)((buf * HG_ABUF + r * HSTR + ig * 8) * 2),
                 A + (size_t)(m0 + r) * K + k0 + ig * 8, true);
        }
    };
    auto loadB = [&](int buf, int k0) {
        if (E == 1) {
            int tap = k0 >> 9, kc0 = k0 & 511;
            int ky = tap / 3, kx = tap % 3;
#pragma unroll
            for (int rep = 0; rep < 2; rep++) {
                int c = tid + rep * 256;
                int r = c >> 2, ig = c & 3;
                int p = n0 + r, y = p >> 6, x = p & 63;
                const __half* src = B + (size_t)((y + ky) * PADP + x + kx) * C2 + kc0 + ig * 8;
                cp16(sbase + (uint32_t)((2 * HG_ABUF + buf * HG_ABUF + r * HSTR + ig * 8) * 2),
                     src, true);
            }
        } else {
#pragma unroll
            for (int rep = 0; rep < 2; rep++) {
                int c = tid + rep * 256;
                int r = c >> 2, ig = c & 3;
                cp16(sbase + (uint32_t)((2 * HG_ABUF + buf * HG_ABUF + r * HSTR + ig * 8) * 2),
                     B + (size_t)(n0 + r) * ldb + k0 + ig * 8, true);
            }
        }
    };

    const int KT = K / 32;
    loadA(0, 0);
    loadB(0, 0);
    asm volatile("cp.async.commit_group;\n");

    int cur = 0;
    for (int kt = 0; kt < KT; kt++) {
        if (kt + 1 < KT) {
            loadA(cur ^ 1, (kt + 1) * 32);
            loadB(cur ^ 1, (kt + 1) * 32);
            asm volatile("cp.async.commit_group;\n");
            asm volatile("cp.async.wait_group 1;\n");
        } else {
            asm volatile("cp.async.wait_group 0;\n");
        }
        __syncthreads();

        const __half* Ab = hsm + cur * HG_ABUF;
        const __half* Bb = hsm + 2 * HG_ABUF + cur * HG_ABUF;
#pragma unroll
        for (int ks = 0; ks < 2; ks++) {
            int k0 = ks * 16;
            uint32_t af[4][4];
#pragma unroll
            for (int mt = 0; mt < 4; mt++) {
                int r0 = wm + mt * 16 + g;
                af[mt][0] = lds32h(Ab + r0 * HSTR + k0 + 2 * t4);
                af[mt][1] = lds32h(Ab + (r0 + 8) * HSTR + k0 + 2 * t4);
                af[mt][2] = lds32h(Ab + r0 * HSTR + k0 + 2 * t4 + 8);
                af[mt][3] = lds32h(Ab + (r0 + 8) * HSTR + k0 + 2 * t4 + 8);
            }
#pragma unroll
            for (int nt = 0; nt < 4; nt++) {
                int cb = wn + nt * 8 + g;
                uint32_t b0 = lds32h(Bb + cb * HSTR + k0 + 2 * t4);
                uint32_t b1 = lds32h(Bb + cb * HSTR + k0 + 2 * t4 + 8);
#pragma unroll
                for (int mt = 0; mt < 4; mt++) mma16h(acc[mt][nt], af[mt], b0, b1);
            }
        }
        __syncthreads();
        cur ^= 1;
    }

    if (E == 1 || E == 3) {
        // relu + transpose through smem -> pixel-major half destination
        __half* tsm = hsm;
#pragma unroll
        for (int mt = 0; mt < 4; mt++) {
            int cl0 = wm + mt * 16 + g;
#pragma unroll
            for (int nt = 0; nt < 4; nt++) {
                int pl0 = wn + nt * 8 + 2 * t4;
                const float* a4 = acc[mt][nt];
#pragma unroll
                for (int half = 0; half < 2; half++) {
                    int cl = cl0 + half * 8;
                    float bv = bias[m0 + cl];
#pragma unroll
                    for (int j = 0; j < 2; j++) {
                        float v = fmaxf(a4[half * 2 + j] + bv, 0.f);
                        tsm[(pl0 + j) * TSTRIDE + cl] = __float2half(v);
                    }
                }
            }
        }
        __syncthreads();
        __half* C = (__half*)Cout + (size_t)batch * sC;
        int p = tid >> 1, cpart = (tid & 1) * 64;
        int pixel = n0 + p;
        uint4* d0;
        if (E == 1) {
            d0 = (uint4*)(C + (size_t)pixel * 1024 + colOff + m0 + cpart);
        } else {
            int y = pixel >> 6, x = pixel & 63;
            d0 = (uint4*)(C + (size_t)((y + 1) * PADP + x + 1) * C2 + m0 + cpart);
        }
        const uint4* s0 = (const uint4*)(tsm + p * TSTRIDE + cpart);
#pragma unroll
        for (int t = 0; t < 8; t++) d0[t] = s0[t];
    } else {
        // E=2: f32 out channel-major
        float* C = (float*)Cout + (size_t)batch * sC;
#pragma unroll
        for (int mt = 0; mt < 4; mt++) {
            int r0 = m0 + wm + mt * 16 + g;
#pragma unroll
            for (int nt = 0; nt < 4; nt++) {
                int cb = n0 + wn + nt * 8 + 2 * t4;
#pragma unroll
                for (int half = 0; half < 2; half++) {
                    int r = r0 + half * 8;
                    float bv = bias[r];
                    C[(size_t)r * N + cb]     = acc[mt][nt][half * 2 + 0] + bv;
                    C[(size_t)r * N + cb + 1] = acc[mt][nt][half * 2 + 1] + bv;
                }
            }
        }
    }
}

// ---------------- q/k transpose: projH rows 0-63 -> qkT[i][64] ----------------
__global__ void __launch_bounds__(256) qkT_k(
    const __half* __restrict__ projH, __half* __restrict__ qkT)
{
    __shared__ __half smt[64][72];
    int mod = blockIdx.z, b = blockIdx.y, i0 = blockIdx.x * 64;
    const __half* src = projH + (size_t)(mod * NB + b) * MPROJ * HWP;
    __half* dst = qkT + (size_t)(mod * NB + b) * HWP * 64;
    int tid = threadIdx.x;
#pragma unroll
    for (int t = 0; t < 16; t++) {
        int e = tid + t * 256;
        int r = e >> 6, ii = e & 63;
        smt[ii][r] = src[(size_t)r * HWP + i0 + ii];
    }
    __syncthreads();
#pragma unroll
    for (int t = 0; t < 16; t++) {
        int e = tid + t * 256;
        int ii = e >> 6, r = e & 63;
        dst[(size_t)(i0 + ii) * 64 + r] = smt[ii][r];
    }
}

// ---------------- z pass (fp16 mma): invZ[i] = 1/sum_j exp(S[i,j]) ----------------
#define ZSH 40
__global__ void __launch_bounds__(256) attn_z_k(
    const __half* __restrict__ qkT, float* __restrict__ invZ)
{
    __shared__ __half qT[64 * ZSH];
    __shared__ __half kT[2][128 * ZSH];
    __shared__ float zred[4][64];

    const int sel = blockIdx.z, b = blockIdx.y;
    const __half* QK = qkT + (size_t)((1 - sel) * NB + b) * HWP * 64;
    invZ += (size_t)(sel * NB + b) * HWP;

    const int i0 = blockIdx.x * 64;
    const int tid = threadIdx.x;
    const int lane = tid & 31, warp = tid >> 5;
    const int g = lane >> 2, t4 = lane & 3;
    const uint32_t qbase = (uint32_t)__cvta_generic_to_shared(qT);
    const uint32_t kbase = (uint32_t)__cvta_generic_to_shared(kT);

    {
        int r = tid >> 2, ig = tid & 3;
        cp16(qbase + (uint32_t)((r * ZSH + ig * 8) * 2), QK + (size_t)(i0 + r) * 64 + ig * 8, true);
    }
    auto loadK = [&](int buf, int j0) {
#pragma unroll
        for (int rep = 0; rep < 2; rep++) {
            int c = tid + rep * 256;
            int r = c >> 2, ig = c & 3;
            cp16(kbase + (uint32_t)((buf * 128 * ZSH + r * ZSH + ig * 8) * 2),
                 QK + (size_t)(j0 + r) * 64 + 32 + ig * 8, true);
        }
    };
    loadK(0, 0);
    asm volatile("cp.async.commit_group;\n");

    float zacc[2][2] = {{0.f, 0.f}, {0.f, 0.f}};
    const int wm = (warp >> 2) * 32, wn = (warp & 3) * 32;

    for (int jc = 0; jc < 32; jc++) {
        int cur = jc & 1;
        asm volatile("cp.async.wait_group 0;\n");
        __syncthreads();
        if (jc + 1 < 32) {
            loadK(cur ^ 1, (jc + 1) * 128);
            asm volatile("cp.async.commit_group;\n");
        }
        const __half* kk_ = kT[cur];
        float sacc[2][4][4];
#pragma unroll
        for (int mt = 0; mt < 2; mt++)
#pragma unroll
            for (int nt = 0; nt < 4; nt++)
#pragma unroll
                for (int e = 0; e < 4; e++) sacc[mt][nt][e] = 0.f;
#pragma unroll
        for (int ks = 0; ks < 2; ks++) {
            int k0 = ks * 16;
            uint32_t a[2][4];
#pragma unroll
            for (int mt = 0; mt < 2; mt++) {
                int r0 = wm + mt * 16 + g;
                a[mt][0] = lds32h(qT + r0 * ZSH + k0 + 2 * t4);
                a[mt][1] = lds32h(qT + (r0 + 8) * ZSH + k0 + 2 * t4);
                a[mt][2] = lds32h(qT + r0 * ZSH + k0 + 2 * t4 + 8);
                a[mt][3] = lds32h(qT + (r0 + 8) * ZSH + k0 + 2 * t4 + 8);
            }
#pragma unroll
            for (int nt = 0; nt < 4; nt++) {
                int cb = wn + nt * 8 + g;
                uint32_t b0 = lds32h(kk_ + cb * ZSH + k0 + 2 * t4);
                uint32_t b1 = lds32h(kk_ + cb * ZSH + k0 + 2 * t4 + 8);
#pragma unroll
                for (int mt = 0; mt < 2; mt++) mma16h(sacc[mt][nt], a[mt], b0, b1);
            }
        }
#pragma unroll
        for (int mt = 0; mt < 2; mt++)
#pragma unroll
            for (int nt = 0; nt < 4; nt++) {
                zacc[mt][0] += __expf(sacc[mt][nt][0]) + __expf(sacc[mt][nt][1]);
                zacc[mt][1] += __expf(sacc[mt][nt][2]) + __expf(sacc[mt][nt][3]);
            }
    }
#pragma unroll
    for (int mt = 0; mt < 2; mt++)
#pragma unroll
        for (int h = 0; h < 2; h++) {
            float v = zacc[mt][h];
            v += __shfl_xor_sync(0xffffffffu, v, 1);
            v += __shfl_xor_sync(0xffffffffu, v, 2);
            if (t4 == 0) zred[warp & 3][wm + mt * 16 + h * 8 + g] = v;
        }
    __syncthreads();
    if (tid < 64) {
        float s = zred[0][tid] + zred[1][tid] + zred[2][tid] + zred[3][tid];
        invZ[i0 + tid] = 1.f / s;
    }
}

// ---------------- fused attention apply (fp16 mma, recompute S in smem) ----------------
#define ASH 40
#define AP_DKT 0
#define AP_DQ  (128 * ASH)
#define AP_RV  (AP_DQ + 2 * 32 * ASH)
#define AP_ES  (AP_RV + 2 * 128 * ASH)
#define AP_TOT (AP_ES + 128 * ASH)         // 23040 halfs = 46080 B

__global__ void __launch_bounds__(256, 2) attn_apply_k(
    const __half* __restrict__ qkT, const __half* __restrict__ projH,
    const float* __restrict__ invZg,
    const float* __restrict__ res0, const float* __restrict__ res1,
    float* __restrict__ out)
{
    __shared__ __half sm[AP_TOT];

    const int bz = blockIdx.z;
    const int sel = bz >> 1, b = bz & 1;
    const int j0 = blockIdx.x * 128;
    const int c0 = blockIdx.y * 128;
    const size_t sX = (size_t)CC * HWP;
    const size_t sF = (size_t)C2 * HWP;

    const __half* QK = qkT + (size_t)((1 - sel) * NB + b) * HWP * 64;
    const __half* V  = projH + (size_t)(sel * NB + b) * MPROJ * HWP
                     + (size_t)(64 + c0) * HWP;
    const float* invZ = invZg + (size_t)(sel * NB + b) * HWP;
    const float* res  = (sel ? res1 : res0) + (size_t)b * sX + (size_t)c0 * HWP;
    out += (size_t)b * sF + (size_t)sel * sX + (size_t)c0 * HWP;

    const int tid = threadIdx.x;
    const int lane = tid & 31, warp = tid >> 5;
    const int g = lane >> 2, t4 = lane & 3;
    const uint32_t sbase = (uint32_t)__cvta_generic_to_shared(sm);

#pragma unroll
    for (int rep = 0; rep < 2; rep++) {
        int c = tid + rep * 256;
        int r = c >> 2, ig = c & 3;
        cp16(sbase + (uint32_t)((AP_DKT + r * ASH + ig * 8) * 2),
             QK + (size_t)(j0 + r) * 64 + 32 + ig * 8, true);
    }
    auto loadQ = [&](int buf, int i0c) {
        if (tid < 128) {
            int r = tid >> 2, ig = tid & 3;
            cp16(sbase + (uint32_t)((AP_DQ + buf * 32 * ASH + r * ASH + ig * 8) * 2),
                 QK + (size_t)(i0c + r) * 64 + ig * 8, true);
        }
    };
    auto loadV = [&](int buf, int i0c) {
#pragma unroll
        for (int rep = 0; rep < 2; rep++) {
            int c = tid + rep * 256;
            int row = c >> 2, ig = c & 3;
            cp16(sbase + (uint32_t)((AP_RV + buf * 128 * ASH + row * ASH + ig * 8) * 2),
                 V + (size_t)row * HWP + i0c + ig * 8, true);
        }
    };
    loadQ(0, 0);
    loadV(0, 0);
    asm volatile("cp.async.commit_group;\n");

    float acc[4][4][4];
#pragma unroll
    for (int mt = 0; mt < 4; mt++)
#pragma unroll
        for (int nt = 0; nt < 4; nt++)
#pragma unroll
            for (int e = 0; e < 4; e++) acc[mt][nt][e] = 0.f;

    const int wj = warp * 16;
    const int wm = (warp >> 2) * 64, wn = (warp & 3) * 32;

    for (int ic = 0; ic < 128; ic++) {
        const int i0c = ic * 32;
        const int cur = ic & 1;
        asm volatile("cp.async.wait_group 0;\n");
        __syncthreads();
        if (ic + 1 < 128) {
            loadQ(cur ^ 1, i0c + 32);
            loadV(cur ^ 1, i0c + 32);
            asm volatile("cp.async.commit_group;\n");
        }
        const __half* dq = sm + AP_DQ + cur * 32 * ASH;
        float sacc[4][4];
#pragma unroll
        for (int nt = 0; nt < 4; nt++)
#pragma unroll
            for (int e = 0; e < 4; e++) sacc[nt][e] = 0.f;
#pragma unroll
        for (int ks = 0; ks < 2; ks++) {
            int k0 = ks * 16;
            uint32_t a[4];
            a[0] = lds32h(sm + AP_DKT + (wj + g) * ASH + k0 + 2 * t4);
            a[1] = lds32h(sm + AP_DKT + (wj + g + 8) * ASH + k0 + 2 * t4);
            a[2] = lds32h(sm + AP_DKT + (wj + g) * ASH + k0 + 2 * t4 + 8);
            a[3] = lds32h(sm + AP_DKT + (wj + g + 8) * ASH + k0 + 2 * t4 + 8);
#pragma unroll
            for (int nt = 0; nt < 4; nt++) {
                int ci = nt * 8 + g;
                uint32_t b0 = lds32h(dq + ci * ASH + k0 + 2 * t4);
                uint32_t b1 = lds32h(dq + ci * ASH + k0 + 2 * t4 + 8);
                mma16h(sacc[nt], a, b0, b1);
            }
        }
#pragma unroll
        for (int nt = 0; nt < 4; nt++) {
            int il = nt * 8 + 2 * t4;
            float iz0 = invZ[i0c + il];
            float iz1 = invZ[i0c + il + 1];
            __half2 h0 = __floats2half2_rn(__expf(sacc[nt][0]) * iz0,
                                           __expf(sacc[nt][1]) * iz1);
            __half2 h1 = __floats2half2_rn(__expf(sacc[nt][2]) * iz0,
                                           __expf(sacc[nt][3]) * iz1);
            *(__half2*)(sm + AP_ES + (wj + g) * ASH + il) = h0;
            *(__half2*)(sm + AP_ES + (wj + g + 8) * ASH + il) = h1;
        }
        __syncthreads();
        const __half* rv = sm + AP_RV + cur * 128 * ASH;
#pragma unroll
        for (int ks = 0; ks < 2; ks++) {
            int k0 = ks * 16;
            uint32_t af[4][4];
#pragma unroll
            for (int mt = 0; mt < 4; mt++) {
                int r0 = wm + mt * 16 + g;
                af[mt][0] = lds32h(rv + r0 * ASH + k0 + 2 * t4);
                af[mt][1] = lds32h(rv + (r0 + 8) * ASH + k0 + 2 * t4);
                af[mt][2] = lds32h(rv + r0 * ASH + k0 + 2 * t4 + 8);
                af[mt][3] = lds32h(rv + (r0 + 8) * ASH + k0 + 2 * t4 + 8);
            }
#pragma unroll
            for (int nt = 0; nt < 4; nt++) {
                int cb = wn + nt * 8 + g;
                uint32_t b0 = lds32h(sm + AP_ES + cb * ASH + k0 + 2 * t4);
                uint32_t b1 = lds32h(sm + AP_ES + cb * ASH + k0 + 2 * t4 + 8);
#pragma unroll
                for (int mt = 0; mt < 4; mt++) mma16h(acc[mt][nt], af[mt], b0, b1);
            }
        }
    }
#pragma unroll
    for (int mt = 0; mt < 4; mt++)
#pragma unroll
        for (int nt = 0; nt < 4; nt++)
#pragma unroll
            for (int e = 0; e < 4; e++) {
                int row = wm + mt * 16 + g + (e >> 1) * 8;
                int col = j0 + wn + nt * 8 + 2 * t4 + (e & 1);
                size_t o = (size_t)row * HWP + col;
                out[o] = tf32f(acc[mt][nt][e] + res[o]);
            }
}

// ---------------- host launcher ----------------
extern "C" void kernel_launch(void* const* d_in, const int* in_sizes, int n_in,
                              void* d_out, int out_size)
{
    const float* rgb  = (const float*)d_in[0];
    const float* chm  = (const float*)d_in[1];
    float* out = (float*)d_out;

    float *invZ, *cat;
    float *wR, *wD, *bR, *bD, *wGate, *bHead;
    __half *projH, *qkT, *y1P, *wF1h, *wF2h, *wHeadH, *fyP;
    cudaGetSymbolAddress((void**)&projH, g_projH);
    cudaGetSymbolAddress((void**)&qkT, g_qkT);
    cudaGetSymbolAddress((void**)&invZ, g_invZ);
    cudaGetSymbolAddress((void**)&cat, g_cat);
    cudaGetSymbolAddress((void**)&fyP, g_fyP);
    cudaGetSymbolAddress((void**)&y1P, g_y1P);
    cudaGetSymbolAddress((void**)&wR, g_wR);
    cudaGetSymbolAddress((void**)&wD, g_wD);
    cudaGetSymbolAddress((void**)&bR, g_bR);
    cudaGetSymbolAddress((void**)&bD, g_bD);
    cudaGetSymbolAddress((void**)&wGate, g_wGate);
    cudaGetSymbolAddress((void**)&wF1h, g_wF1h);
    cudaGetSymbolAddress((void**)&wF2h, g_wF2h);
    cudaGetSymbolAddress((void**)&wHeadH, g_wHeadH);
    cudaGetSymbolAddress((void**)&bHead, g_bHead);

    cudaFuncSetAttribute(tgemm_k<P_PROJ>,  cudaFuncAttributeMaxDynamicSharedMemorySize, SMEM_BYTES);
    cudaFuncSetAttribute(tgemm_k<P_GATET>, cudaFuncAttributeMaxDynamicSharedMemorySize, SMEM_BYTES);

    dim3 blk(256);
    const size_t sX = (size_t)CC * HWP;
    const size_t sF = (size_t)C2 * HWP;
    const size_t sPH = (size_t)MPROJ * HWP;          // half units
    const size_t sFy = (size_t)HWP * 1024;           // half units
    const size_t sY1P = (size_t)PADN * C2;           // half units

    // --- prep + border zero ---
    PrepPtrs pp;
    pp.rq_w = (const float*)d_in[2];  pp.rq_b = (const float*)d_in[3];
    pp.rk_w = (const float*)d_in[4];  pp.rk_b = (const float*)d_in[5];
    pp.rv_w = (const float*)d_in[6];  pp.rv_b = (const float*)d_in[7];
    pp.dq_w = (const float*)d_in[8];  pp.dq_b = (const float*)d_in[9];
    pp.dk_w = (const float*)d_in[10]; pp.dk_b = (const float*)d_in[11];
    pp.dv_w = (const float*)d_in[12]; pp.dv_b = (const float*)d_in[13];
    pp.gate_w = (const float*)d_in[14];
    pp.fus1_w = (const float*)d_in[16];
    pp.fus2_w = (const float*)d_in[18];
    pp.fus3_w = (const float*)d_in[20]; pp.fus3_b = (const float*)d_in[21];
    pp.skip_w = (const float*)d_in[22]; pp.skip_b = (const float*)d_in[23];
    pp.wR = wR; pp.wD = wD; pp.wGate = wGate;
    pp.wF1h = wF1h; pp.wF2h = wF2h; pp.wHeadH = wHeadH;
    pp.bR = bR; pp.bD = bD; pp.bHead = bHead;
    prep_k<<<(PREP_TOT + 255) / 256, blk>>>(pp);
    zeroborder_k<<<(ZB_TOT + 255) / 256, blk>>>(y1P);

    const float* gate_b = (const float*)d_in[15];
    const float* fus1_b = (const float*)d_in[17];
    const float* fus2_b = (const float*)d_in[19];

    // --- projections (both modalities, fp16 output) ---
    tgemm_k<P_PROJ><<<dim3(32, 3, 4), blk, SMEM_BYTES>>>(
        wR, wD, CC, 0, rgb, chm, HWP, sX,
        (float*)projH, sPH, (size_t)NB * sPH, bR, bD, nullptr, 0, MPROJ, HWP, CC);

    // --- q/k transpose ---
    qkT_k<<<dim3(64, NB, 2), blk>>>(projH, qkT);

    // --- z pass ---
    attn_z_k<<<dim3(64, NB, 2), blk>>>(qkT, invZ);

    // --- fused apply: sel0 -> cat[:,0:C]; sel1 -> cat[:,C:2C] ---
    attn_apply_k<<<dim3(32, 2, 4), blk>>>(qkT, projH, invZ, rgb, chm, cat);

    // --- gate GEMM + fused gated combine, transposed half out -> fyP[p][0:512] ---
    tgemm_k<P_GATET><<<dim3(32, 2, NB), blk, SMEM_BYTES>>>(
        wGate, nullptr, C2, 0, cat, nullptr, HWP, sF,
        (float*)fyP, sFy, 0, gate_b, nullptr, cat, sF, CC, HWP, C2);

    // --- fus1 (fp16): relu(W1 @ f + b1) -> padded pixel-major y1P ---
    hgemm_k<3><<<dim3(32, 4, NB), blk>>>(
        wF1h, fyP, 1024, sFy, y1P, sY1P, 0, fus1_b, HWP, C2);

    // --- fus2: implicit-GEMM conv (B = tap-shifted y1P), transposed out -> fyP[p][512:1024] ---
    hgemm_k<1><<<dim3(32, 4, NB), blk>>>(
        wF2h, y1P, 0, sY1P, fyP, sFy, 512, fus2_b, HWP, KCOL);

    // --- head (fp16, K=1024): out = [skip | fus3] @ [f ; y2] + (bskip + b3) ---
    hgemm_k<2><<<dim3(32, 2, NB), blk>>>(
        wHeadH, fyP, 1024, sFy, out, sX, 0, bHead, HWP, 1024);

    (void)in_sizes; (void)n_in; (void)out_size;
}

// round 17
// speedup vs baseline: 2.6244x; 1.0623x over previous
#include <cuda_runtime.h>
#include <cuda_fp16.h>
#include <cstdint>
#include <math.h>

#define NB 2
#define CC 256
#define RCQ 32
#define HH 64
#define WW 64
#define HWP 4096
#define C2 512
#define KCOL 4608
#define MPROJ 320
#define PADP 66
#define PADN (PADP * PADP)

// ---------------- scratch ----------------
__device__ __half g_projH[(size_t)2 * NB * MPROJ * HWP];
__device__ __half g_qkT[(size_t)2 * NB * HWP * 64];
__device__ float g_invZ[4 * HWP];
__device__ float g_cat[(size_t)NB * C2 * HWP];
__device__ __half g_fyP[(size_t)NB * HWP * 1024];
__device__ __half g_y1P[(size_t)NB * PADN * C2];
// weights
__device__ float g_wR[MPROJ * CC];
__device__ float g_wD[MPROJ * CC];
__device__ float g_bR[MPROJ];
__device__ float g_bD[MPROJ];
__device__ float g_wGate[CC * C2];
__device__ __half g_wF1h[C2 * C2];
__device__ __half g_wF2h[C2 * KCOL];   // k reordered: tap*512 + ci
__device__ __half g_wHeadH[CC * 1024];
__device__ float g_bHead[CC];

// ---------------- helpers ----------------
__device__ __forceinline__ void cp16(uint32_t dst, const void* src, bool v) {
    int sz = v ? 16 : 0;
    asm volatile("cp.async.cg.shared.global [%0], [%1], 16, %2;\n"
                 :: "r"(dst), "l"(src), "r"(sz));
}
__device__ __forceinline__ uint32_t cvt_tf32(float x) {
    uint32_t r;
    asm("cvt.rna.tf32.f32 %0, %1;" : "=r"(r) : "f"(x));
    return r;
}
__device__ __forceinline__ float tf32f(float x) { return __uint_as_float(cvt_tf32(x)); }
__device__ __forceinline__ void mma8(float* c, const uint32_t* a, uint32_t b0, uint32_t b1) {
    asm volatile(
        "mma.sync.aligned.m16n8k8.row.col.f32.tf32.tf32.f32 "
        "{%0,%1,%2,%3}, {%4,%5,%6,%7}, {%8,%9}, {%0,%1,%2,%3};"
        : "+f"(c[0]), "+f"(c[1]), "+f"(c[2]), "+f"(c[3])
        : "r"(a[0]), "r"(a[1]), "r"(a[2]), "r"(a[3]), "r"(b0), "r"(b1));
}
__device__ __forceinline__ void mma16h(float* c, const uint32_t* a, uint32_t b0, uint32_t b1) {
    asm volatile(
        "mma.sync.aligned.m16n8k16.row.col.f32.f16.f16.f32 "
        "{%0,%1,%2,%3}, {%4,%5,%6,%7}, {%8,%9}, {%0,%1,%2,%3};"
        : "+f"(c[0]), "+f"(c[1]), "+f"(c[2]), "+f"(c[3])
        : "r"(a[0]), "r"(a[1]), "r"(a[2]), "r"(a[3]), "r"(b0), "r"(b1));
}
__device__ __forceinline__ void ldsm4(uint32_t* r, uint32_t addr) {
    asm volatile("ldmatrix.sync.aligned.m8n8.x4.shared.b16 {%0,%1,%2,%3}, [%4];"
                 : "=r"(r[0]), "=r"(r[1]), "=r"(r[2]), "=r"(r[3]) : "r"(addr));
}
__device__ __forceinline__ void ldsm2(uint32_t& r0, uint32_t& r1, uint32_t addr) {
    asm volatile("ldmatrix.sync.aligned.m8n8.x2.shared.b16 {%0,%1}, [%2];"
                 : "=r"(r0), "=r"(r1) : "r"(addr));
}
__device__ __forceinline__ void stsm4(uint32_t addr, uint32_t r0, uint32_t r1,
                                      uint32_t r2, uint32_t r3) {
    asm volatile("stmatrix.sync.aligned.m8n8.x4.shared.b16 [%0], {%1,%2,%3,%4};"
                 :: "r"(addr), "r"(r0), "r"(r1), "r"(r2), "r"(r3) : "memory");
}

// ---------------- single prep kernel ----------------
struct PrepPtrs {
    const float *rq_w, *rk_w, *rv_w, *dq_w, *dk_w, *dv_w;
    const float *gate_w, *fus1_w, *fus2_w, *fus3_w, *skip_w;
    const float *rq_b, *rk_b, *rv_b, *dq_b, *dk_b, *dv_b, *fus3_b, *skip_b;
    float *wR, *wD, *wGate, *bR, *bD, *bHead;
    __half *wF1h, *wF2h, *wHeadH;
};
#define PREP_TOT 3179392
__global__ void __launch_bounds__(256) prep_k(PrepPtrs p) {
    int i = blockIdx.x * 256 + threadIdx.x;
    if (i >= PREP_TOT) return;
    if (i < 8192)            p.wR[i] = tf32f(p.rq_w[i]);
    else if (i < 16384)      p.wR[i] = tf32f(p.rk_w[i - 8192]);
    else if (i < 81920)      p.wR[i] = tf32f(p.rv_w[i - 16384]);
    else if (i < 90112)      p.wD[i - 81920] = tf32f(p.dq_w[i - 81920]);
    else if (i < 98304)      p.wD[i - 81920] = tf32f(p.dk_w[i - 90112]);
    else if (i < 163840)     p.wD[i - 81920] = tf32f(p.dv_w[i - 98304]);
    else if (i < 294912)     p.wGate[i - 163840] = tf32f(p.gate_w[i - 163840]);
    else if (i < 557056)     p.wF1h[i - 294912] = __float2half(p.fus1_w[i - 294912]);
    else if (i < 2916352) {
        int j = i - 557056;
        int m = j / KCOL, rem = j % KCOL;
        int ci = rem / 9, tap = rem % 9;
        p.wF2h[(size_t)m * KCOL + tap * 512 + ci] = __float2half(p.fus2_w[j]);
    }
    else if (i < 3178496) {
        int j = i - 2916352;
        int m = j >> 10, k = j & 1023;
        float v = (k < 512) ? p.skip_w[m * 512 + k] : p.fus3_w[m * 512 + k - 512];
        p.wHeadH[j] = __float2half(v);
    } else if (i < 3178816) {
        int j = i - 3178496;
        p.bR[j] = (j < 32) ? p.rq_b[j] : (j < 64) ? p.rk_b[j - 32] : p.rv_b[j - 64];
    } else if (i < 3179136) {
        int j = i - 3178816;
        p.bD[j] = (j < 32) ? p.dq_b[j] : (j < 64) ? p.dk_b[j - 32] : p.dv_b[j - 64];
    } else {
        int j = i - 3179136;
        p.bHead[j] = p.fus3_b[j] + p.skip_b[j];
    }
}

// ---------------- zero y1P border ----------------
#define ZB_TOT (NB * 260 * 64)
__global__ void __launch_bounds__(256) zeroborder_k(__half* __restrict__ y1P) {
    int idx = blockIdx.x * 256 + threadIdx.x;
    if (idx >= ZB_TOT) return;
    int b = idx / (260 * 64);
    int rem = idx % (260 * 64);
    int pi = rem / 64, q = rem % 64;
    int y, x;
    if (pi < 66)       { y = 0;  x = pi; }
    else if (pi < 132) { y = 65; x = pi - 66; }
    else if (pi < 196) { y = pi - 132 + 1; x = 0; }
    else               { y = pi - 196 + 1; x = 65; }
    uint4 z = make_uint4(0, 0, 0, 0);
    ((uint4*)(y1P + ((size_t)b * PADN + y * PADP + x) * C2))[q] = z;
}

// ---------------- TF32 GEMM (proj + gate) ----------------
#define FL_BIAS  8
#define FL_DUAL  64
#define FL_HALF  256
#define FL_GATET 512

#define ASTR 36
#define BSTR 136
#define ABUF (128 * ASTR)
#define BBUF (32 * BSTR)
#define SMEM_BYTES ((2 * ABUF + 2 * BBUF) * 4)
#define TSTRIDE 136
#define TTILE (128 * TSTRIDE)

template <int F>
__global__ void __launch_bounds__(256, 2) tgemm_k(
    const float* __restrict__ A, const float* __restrict__ A2, int lda, size_t sA,
    const float* __restrict__ B, const float* __restrict__ B2, int ldb, size_t sB,
    float* __restrict__ Cf, size_t sC, size_t cSelOff,
    const float* __restrict__ bias, const float* __restrict__ bias2,
    const float* __restrict__ res, size_t sRes,
    int M, int N, int K)
{
    extern __shared__ float sm[];
    const int bz = blockIdx.z;
    const int sel   = (F & FL_DUAL) ? (bz >> 1) : 0;
    const int batch = (F & FL_DUAL) ? (bz & 1) : bz;
    const float* Ap = (((F & FL_DUAL) && sel) ? A2 : A) + (size_t)batch * sA;
    const float* Bp = (((F & FL_DUAL) && sel) ? B2 : B) + (size_t)batch * sB;
    __half* Ch = nullptr;
    if (F & (FL_HALF | FL_GATET))
        Ch = (__half*)Cf + (size_t)batch * sC + (sel ? cSelOff : 0);
    const float* biasp = (((F & FL_DUAL) && sel) ? bias2 : bias);
    const float* resp = res ? res + (size_t)batch * sRes : nullptr;

    const int m0 = blockIdx.y * 128, n0 = blockIdx.x * 128;
    const int tid = threadIdx.x;
    const int lane = tid & 31, warp = tid >> 5;
    const int g = lane >> 2, t4 = lane & 3;
    const int wm = (warp >> 2) * 64;
    const int wn = (warp & 3) * 32;

    const uint32_t sbase = (uint32_t)__cvta_generic_to_shared(sm);

    float acc[4][4][4];
#pragma unroll
    for (int mt = 0; mt < 4; mt++)
#pragma unroll
        for (int nt = 0; nt < 4; nt++)
#pragma unroll
            for (int i = 0; i < 4; i++) acc[mt][nt][i] = 0.f;

    auto loadA = [&](int buf, int k0) {
#pragma unroll
        for (int i = 0; i < 4; i++) {
            int c = tid + i * 256;
            int m = c >> 3, kg = c & 7;
            bool v = (m0 + m) < M;
            int mm = v ? (m0 + m) : 0;
            const float* src = Ap + (size_t)mm * lda + k0 + kg * 4;
            uint32_t dst = sbase + (uint32_t)((buf * ABUF + m * ASTR + kg * 4) * 4);
            cp16(dst, src, v);
        }
    };
    auto loadB = [&](int buf, int k0) {
#pragma unroll
        for (int i = 0; i < 4; i++) {
            int c = tid + i * 256;
            int k = c >> 5, ng = c & 31;
            const float* src = Bp + (size_t)(k0 + k) * ldb + n0 + ng * 4;
            uint32_t dst = sbase + (uint32_t)((2 * ABUF + buf * BBUF + k * BSTR + ng * 4) * 4);
            cp16(dst, src, true);
        }
    };

    const int KT = K / 32;
    loadA(0, 0);
    loadB(0, 0);
    asm volatile("cp.async.commit_group;\n");

    int cur = 0;
    for (int kt = 0; kt < KT; kt++) {
        if (kt + 1 < KT) {
            loadA(cur ^ 1, (kt + 1) * 32);
            loadB(cur ^ 1, (kt + 1) * 32);
            asm volatile("cp.async.commit_group;\n");
            asm volatile("cp.async.wait_group 1;\n");
        } else {
            asm volatile("cp.async.wait_group 0;\n");
        }
        __syncthreads();

        const float* Ab = sm + cur * ABUF;
        const float* Bb = sm + 2 * ABUF + cur * BBUF;
#pragma unroll
        for (int ks = 0; ks < 4; ks++) {
            const int kk = ks * 8;
            uint32_t af[4][4];
#pragma unroll
            for (int mt = 0; mt < 4; mt++) {
                int r0 = wm + mt * 16 + g;
                af[mt][0] = __float_as_uint(Ab[r0 * ASTR + kk + t4]);
                af[mt][1] = __float_as_uint(Ab[(r0 + 8) * ASTR + kk + t4]);
                af[mt][2] = __float_as_uint(Ab[r0 * ASTR + kk + t4 + 4]);
                af[mt][3] = __float_as_uint(Ab[(r0 + 8) * ASTR + kk + t4 + 4]);
            }
#pragma unroll
            for (int nt = 0; nt < 4; nt++) {
                int cb = wn + nt * 8 + g;
                uint32_t b0 = __float_as_uint(Bb[(kk + t4) * BSTR + cb]);
                uint32_t b1 = __float_as_uint(Bb[(kk + t4 + 4) * BSTR + cb]);
#pragma unroll
                for (int mt = 0; mt < 4; mt++) mma8(acc[mt][nt], af[mt], b0, b1);
            }
        }
        __syncthreads();
        cur ^= 1;
    }

    if (F & FL_GATET) {
        __half* tsm = (__half*)sm;
#pragma unroll
        for (int mt = 0; mt < 4; mt++) {
            int cl0 = wm + mt * 16 + g;
#pragma unroll
            for (int nt = 0; nt < 4; nt++) {
                int pl0 = wn + nt * 8 + 2 * t4;
                const float* a4 = acc[mt][nt];
#pragma unroll
                for (int half = 0; half < 2; half++) {
                    int cl = cl0 + half * 8;
                    int rr = m0 + cl;
                    float bv = biasp[rr];
#pragma unroll
                    for (int j = 0; j < 2; j++) {
                        int pl = pl0 + j;
                        float v = a4[half * 2 + j] + bv;
                        size_t idx = (size_t)rr * N + n0 + pl;
                        float a = resp[idx];
                        float b2 = resp[idx + (size_t)CC * N];
                        float gg = 1.f / (1.f + __expf(-v));
                        tsm[pl * TSTRIDE + cl] = __float2half(a * gg + b2 * (1.f - gg));
                        tsm[TTILE + pl * TSTRIDE + cl] = __float2half(a * b2);
                    }
                }
            }
        }
        __syncthreads();
        int p = tid >> 1, cpart = (tid & 1) * 64;
        const uint4* s0 = (const uint4*)(tsm + p * TSTRIDE + cpart);
        uint4* d0 = (uint4*)(Ch + (size_t)(n0 + p) * 1024 + m0 + cpart);
#pragma unroll
        for (int t = 0; t < 8; t++) d0[t] = s0[t];
        const uint4* s1 = (const uint4*)(tsm + TTILE + p * TSTRIDE + cpart);
        uint4* d1 = (uint4*)(Ch + (size_t)(n0 + p) * 1024 + 256 + m0 + cpart);
#pragma unroll
        for (int t = 0; t < 8; t++) d1[t] = s1[t];
        return;
    }

#pragma unroll
    for (int mt = 0; mt < 4; mt++) {
        int r0 = m0 + wm + mt * 16 + g;
#pragma unroll
        for (int nt = 0; nt < 4; nt++) {
            int cb = n0 + wn + nt * 8 + 2 * t4;
            const float* a4 = acc[mt][nt];
#pragma unroll
            for (int half = 0; half < 2; half++) {
                int r = r0 + half * 8;
                if (r >= M) continue;
                float bv = (F & FL_BIAS) ? biasp[r] : 0.f;
                float v0 = a4[half * 2 + 0] + bv;
                float v1 = a4[half * 2 + 1] + bv;
                size_t idx = (size_t)r * N + cb;
                *(__half2*)(Ch + idx) = __floats2half2_rn(v0, v1);
            }
        }
    }
}

#define P_PROJ  (FL_BIAS | FL_DUAL | FL_HALF)
#define P_GATET (FL_BIAS | FL_GATET)

// ---------------- FP16 GEMM with ldmatrix fragment loads ----------------
// E=1: implicit-conv B (padded y1P), relu, transposed out -> fyP[p][512+c]
// E=2: normal B, f32 out (head)
// E=3: normal B, relu, transposed out -> padded y1P (fus1)
#define HSTR 40
#define HG_ABUF (128 * HSTR)
template <int E>
__global__ void __launch_bounds__(256, 2) hgemm_k(
    const __half* __restrict__ A,
    const __half* __restrict__ B, int ldb, size_t sB,
    void* __restrict__ Cout, size_t sC, int colOff,
    const float* __restrict__ bias,
    int N, int K)
{
    __shared__ __half hsm[4 * HG_ABUF];

    const int batch = blockIdx.z;
    const int m0 = blockIdx.y * 128, n0 = blockIdx.x * 128;
    B += (size_t)batch * sB;

    const int tid = threadIdx.x;
    const int lane = tid & 31, warp = tid >> 5;
    const int g = lane >> 2, t4 = lane & 3;
    const int wm = (warp >> 2) * 64, wn = (warp & 3) * 32;
    const uint32_t sbase = (uint32_t)__cvta_generic_to_shared(hsm);

    const int rowA = (lane & 7) + ((lane >> 3) & 1) * 8;
    const int kA = (lane >> 4) * 8;
    const int rowB = lane & 7;
    const int kB = ((lane >> 3) & 1) * 8;

    float acc[4][4][4];
#pragma unroll
    for (int mt = 0; mt < 4; mt++)
#pragma unroll
        for (int nt = 0; nt < 4; nt++)
#pragma unroll
            for (int e = 0; e < 4; e++) acc[mt][nt][e] = 0.f;

    auto loadA = [&](int buf, int k0) {
#pragma unroll
        for (int rep = 0; rep < 2; rep++) {
            int c = tid + rep * 256;
            int r = c >> 2, ig = c & 3;
            cp16(sbase + (uint32_t)((buf * HG_ABUF + r * HSTR + ig * 8) * 2),
                 A + (size_t)(m0 + r) * K + k0 + ig * 8, true);
        }
    };
    auto loadB = [&](int buf, int k0) {
        if (E == 1) {
            int tap = k0 >> 9, kc0 = k0 & 511;
            int ky = tap / 3, kx = tap % 3;
#pragma unroll
            for (int rep = 0; rep < 2; rep++) {
                int c = tid + rep * 256;
                int r = c >> 2, ig = c & 3;
                int p = n0 + r, y = p >> 6, x = p & 63;
                const __half* src = B + (size_t)((y + ky) * PADP + x + kx) * C2 + kc0 + ig * 8;
                cp16(sbase + (uint32_t)((2 * HG_ABUF + buf * HG_ABUF + r * HSTR + ig * 8) * 2),
                     src, true);
            }
        } else {
#pragma unroll
            for (int rep = 0; rep < 2; rep++) {
                int c = tid + rep * 256;
                int r = c >> 2, ig = c & 3;
                cp16(sbase + (uint32_t)((2 * HG_ABUF + buf * HG_ABUF + r * HSTR + ig * 8) * 2),
                     B + (size_t)(n0 + r) * ldb + k0 + ig * 8, true);
            }
        }
    };

    const int KT = K / 32;
    loadA(0, 0);
    loadB(0, 0);
    asm volatile("cp.async.commit_group;\n");

    int cur = 0;
    for (int kt = 0; kt < KT; kt++) {
        if (kt + 1 < KT) {
            loadA(cur ^ 1, (kt + 1) * 32);
            loadB(cur ^ 1, (kt + 1) * 32);
            asm volatile("cp.async.commit_group;\n");
            asm volatile("cp.async.wait_group 1;\n");
        } else {
            asm volatile("cp.async.wait_group 0;\n");
        }
        __syncthreads();

        const uint32_t uA = sbase + 2 * (cur * HG_ABUF + (wm + rowA) * HSTR + kA);
        const uint32_t uB = sbase + 2 * (2 * HG_ABUF + cur * HG_ABUF + (wn + rowB) * HSTR + kB);
#pragma unroll
        for (int ks = 0; ks < 2; ks++) {
            int k0 = ks * 16;
            uint32_t af[4][4];
#pragma unroll
            for (int mt = 0; mt < 4; mt++)
                ldsm4(af[mt], uA + 2 * (mt * 16 * HSTR + k0));
#pragma unroll
            for (int nt = 0; nt < 4; nt++) {
                uint32_t b0, b1;
                ldsm2(b0, b1, uB + 2 * (nt * 8 * HSTR + k0));
#pragma unroll
                for (int mt = 0; mt < 4; mt++) mma16h(acc[mt][nt], af[mt], b0, b1);
            }
        }
        __syncthreads();
        cur ^= 1;
    }

    if (E == 1 || E == 3) {
        __half* tsm = hsm;
#pragma unroll
        for (int mt = 0; mt < 4; mt++) {
            int cl0 = wm + mt * 16 + g;
#pragma unroll
            for (int nt = 0; nt < 4; nt++) {
                int pl0 = wn + nt * 8 + 2 * t4;
                const float* a4 = acc[mt][nt];
#pragma unroll
                for (int half = 0; half < 2; half++) {
                    int cl = cl0 + half * 8;
                    float bv = bias[m0 + cl];
#pragma unroll
                    for (int j = 0; j < 2; j++) {
                        float v = fmaxf(a4[half * 2 + j] + bv, 0.f);
                        tsm[(pl0 + j) * TSTRIDE + cl] = __float2half(v);
                    }
                }
            }
        }
        __syncthreads();
        __half* C = (__half*)Cout + (size_t)batch * sC;
        int p = tid >> 1, cpart = (tid & 1) * 64;
        int pixel = n0 + p;
        uint4* d0;
        if (E == 1) {
            d0 = (uint4*)(C + (size_t)pixel * 1024 + colOff + m0 + cpart);
        } else {
            int y = pixel >> 6, x = pixel & 63;
            d0 = (uint4*)(C + (size_t)((y + 1) * PADP + x + 1) * C2 + m0 + cpart);
        }
        const uint4* s0 = (const uint4*)(tsm + p * TSTRIDE + cpart);
#pragma unroll
        for (int t = 0; t < 8; t++) d0[t] = s0[t];
    } else {
        float* C = (float*)Cout + (size_t)batch * sC;
#pragma unroll
        for (int mt = 0; mt < 4; mt++) {
            int r0 = m0 + wm + mt * 16 + g;
#pragma unroll
            for (int nt = 0; nt < 4; nt++) {
                int cb = n0 + wn + nt * 8 + 2 * t4;
#pragma unroll
                for (int half = 0; half < 2; half++) {
                    int r = r0 + half * 8;
                    float bv = bias[r];
                    C[(size_t)r * N + cb]     = acc[mt][nt][half * 2 + 0] + bv;
                    C[(size_t)r * N + cb + 1] = acc[mt][nt][half * 2 + 1] + bv;
                }
            }
        }
    }
}

// ---------------- q/k transpose ----------------
__global__ void __launch_bounds__(256) qkT_k(
    const __half* __restrict__ projH, __half* __restrict__ qkT)
{
    __shared__ __half smt[64][72];
    int mod = blockIdx.z, b = blockIdx.y, i0 = blockIdx.x * 64;
    const __half* src = projH + (size_t)(mod * NB + b) * MPROJ * HWP;
    __half* dst = qkT + (size_t)(mod * NB + b) * HWP * 64;
    int tid = threadIdx.x;
#pragma unroll
    for (int t = 0; t < 16; t++) {
        int e = tid + t * 256;
        int r = e >> 6, ii = e & 63;
        smt[ii][r] = src[(size_t)r * HWP + i0 + ii];
    }
    __syncthreads();
#pragma unroll
    for (int t = 0; t < 16; t++) {
        int e = tid + t * 256;
        int ii = e >> 6, r = e & 63;
        dst[(size_t)(i0 + ii) * 64 + r] = smt[ii][r];
    }
}

// ---------------- z pass (fp16 mma + ldmatrix) ----------------
#define ZSH 40
__global__ void __launch_bounds__(256) attn_z_k(
    const __half* __restrict__ qkT, float* __restrict__ invZ)
{
    __shared__ __half qT[64 * ZSH];
    __shared__ __half kT[2][128 * ZSH];
    __shared__ float zred[4][64];

    const int sel = blockIdx.z, b = blockIdx.y;
    const __half* QK = qkT + (size_t)((1 - sel) * NB + b) * HWP * 64;
    invZ += (size_t)(sel * NB + b) * HWP;

    const int i0 = blockIdx.x * 64;
    const int tid = threadIdx.x;
    const int lane = tid & 31, warp = tid >> 5;
    const int g = lane >> 2, t4 = lane & 3;
    const uint32_t qbase = (uint32_t)__cvta_generic_to_shared(qT);
    const uint32_t kbase = (uint32_t)__cvta_generic_to_shared(kT);

    const int rowA = (lane & 7) + ((lane >> 3) & 1) * 8;
    const int kA = (lane >> 4) * 8;
    const int rowB = lane & 7;
    const int kB = ((lane >> 3) & 1) * 8;

    {
        int r = tid >> 2, ig = tid & 3;
        cp16(qbase + (uint32_t)((r * ZSH + ig * 8) * 2), QK + (size_t)(i0 + r) * 64 + ig * 8, true);
    }
    auto loadK = [&](int buf, int j0) {
#pragma unroll
        for (int rep = 0; rep < 2; rep++) {
            int c = tid + rep * 256;
            int r = c >> 2, ig = c & 3;
            cp16(kbase + (uint32_t)((buf * 128 * ZSH + r * ZSH + ig * 8) * 2),
                 QK + (size_t)(j0 + r) * 64 + 32 + ig * 8, true);
        }
    };
    loadK(0, 0);
    asm volatile("cp.async.commit_group;\n");

    float zacc[2][2] = {{0.f, 0.f}, {0.f, 0.f}};
    const int wm = (warp >> 2) * 32, wn = (warp & 3) * 32;
    const uint32_t uQA = qbase + 2 * ((wm + rowA) * ZSH + kA);

    for (int jc = 0; jc < 32; jc++) {
        int cur = jc & 1;
        asm volatile("cp.async.wait_group 0;\n");
        __syncthreads();
        if (jc + 1 < 32) {
            loadK(cur ^ 1, (jc + 1) * 128);
            asm volatile("cp.async.commit_group;\n");
        }
        const uint32_t uKB = kbase + 2 * (cur * 128 * ZSH + (wn + rowB) * ZSH + kB);
        float sacc[2][4][4];
#pragma unroll
        for (int mt = 0; mt < 2; mt++)
#pragma unroll
            for (int nt = 0; nt < 4; nt++)
#pragma unroll
                for (int e = 0; e < 4; e++) sacc[mt][nt][e] = 0.f;
#pragma unroll
        for (int ks = 0; ks < 2; ks++) {
            int k0 = ks * 16;
            uint32_t a[2][4];
#pragma unroll
            for (int mt = 0; mt < 2; mt++)
                ldsm4(a[mt], uQA + 2 * (mt * 16 * ZSH + k0));
#pragma unroll
            for (int nt = 0; nt < 4; nt++) {
                uint32_t b0, b1;
                ldsm2(b0, b1, uKB + 2 * (nt * 8 * ZSH + k0));
#pragma unroll
                for (int mt = 0; mt < 2; mt++) mma16h(sacc[mt][nt], a[mt], b0, b1);
            }
        }
#pragma unroll
        for (int mt = 0; mt < 2; mt++)
#pragma unroll
            for (int nt = 0; nt < 4; nt++) {
                zacc[mt][0] += __expf(sacc[mt][nt][0]) + __expf(sacc[mt][nt][1]);
                zacc[mt][1] += __expf(sacc[mt][nt][2]) + __expf(sacc[mt][nt][3]);
            }
    }
#pragma unroll
    for (int mt = 0; mt < 2; mt++)
#pragma unroll
        for (int h = 0; h < 2; h++) {
            float v = zacc[mt][h];
            v += __shfl_xor_sync(0xffffffffu, v, 1);
            v += __shfl_xor_sync(0xffffffffu, v, 2);
            if (t4 == 0) zred[warp & 3][wm + mt * 16 + h * 8 + g] = v;
        }
    __syncthreads();
    if (tid < 64) {
        float s = zred[0][tid] + zred[1][tid] + zred[2][tid] + zred[3][tid];
        invZ[i0 + tid] = 1.f / s;
    }
}

// ---------------- fused attention apply (fp16 mma + ldmatrix/stmatrix) ----------------
#define ASH 40
#define AP_DKT 0
#define AP_DQ  (128 * ASH)
#define AP_RV  (AP_DQ + 2 * 32 * ASH)
#define AP_ES  (AP_RV + 2 * 128 * ASH)
#define AP_TOT (AP_ES + 128 * ASH)

__global__ void __launch_bounds__(256, 2) attn_apply_k(
    const __half* __restrict__ qkT, const __half* __restrict__ projH,
    const float* __restrict__ invZg,
    const float* __restrict__ res0, const float* __restrict__ res1,
    float* __restrict__ out)
{
    __shared__ __half sm[AP_TOT];

    const int bz = blockIdx.z;
    const int sel = bz >> 1, b = bz & 1;
    const int j0 = blockIdx.x * 128;
    const int c0 = blockIdx.y * 128;
    const size_t sX = (size_t)CC * HWP;
    const size_t sF = (size_t)C2 * HWP;

    const __half* QK = qkT + (size_t)((1 - sel) * NB + b) * HWP * 64;
    const __half* V  = projH + (size_t)(sel * NB + b) * MPROJ * HWP
                     + (size_t)(64 + c0) * HWP;
    const float* invZ = invZg + (size_t)(sel * NB + b) * HWP;
    const float* res  = (sel ? res1 : res0) + (size_t)b * sX + (size_t)c0 * HWP;
    out += (size_t)b * sF + (size_t)sel * sX + (size_t)c0 * HWP;

    const int tid = threadIdx.x;
    const int lane = tid & 31, warp = tid >> 5;
    const int g = lane >> 2, t4 = lane & 3;
    const uint32_t sbase = (uint32_t)__cvta_generic_to_shared(sm);

    const int rowA = (lane & 7) + ((lane >> 3) & 1) * 8;
    const int kA = (lane >> 4) * 8;
    const int rowB = lane & 7;
    const int kB = ((lane >> 3) & 1) * 8;

#pragma unroll
    for (int rep = 0; rep < 2; rep++) {
        int c = tid + rep * 256;
        int r = c >> 2, ig = c & 3;
        cp16(sbase + (uint32_t)((AP_DKT + r * ASH + ig * 8) * 2),
             QK + (size_t)(j0 + r) * 64 + 32 + ig * 8, true);
    }
    auto loadQ = [&](int buf, int i0c) {
        if (tid < 128) {
            int r = tid >> 2, ig = tid & 3;
            cp16(sbase + (uint32_t)((AP_DQ + buf * 32 * ASH + r * ASH + ig * 8) * 2),
                 QK + (size_t)(i0c + r) * 64 + ig * 8, true);
        }
    };
    auto loadV = [&](int buf, int i0c) {
#pragma unroll
        for (int rep = 0; rep < 2; rep++) {
            int c = tid + rep * 256;
            int row = c >> 2, ig = c & 3;
            cp16(sbase + (uint32_t)((AP_RV + buf * 128 * ASH + row * ASH + ig * 8) * 2),
                 V + (size_t)row * HWP + i0c + ig * 8, true);
        }
    };
    loadQ(0, 0);
    loadV(0, 0);
    asm volatile("cp.async.commit_group;\n");

    float acc[4][4][4];
#pragma unroll
    for (int mt = 0; mt < 4; mt++)
#pragma unroll
        for (int nt = 0; nt < 4; nt++)
#pragma unroll
            for (int e = 0; e < 4; e++) acc[mt][nt][e] = 0.f;

    const int wj = warp * 16;
    const int wm = (warp >> 2) * 64, wn = (warp & 3) * 32;

    const uint32_t uDKT  = sbase + 2 * (AP_DKT + (wj + rowA) * ASH + kA);
    const uint32_t uESst = sbase + 2 * (AP_ES + (wj + rowA) * ASH + kA);
    const uint32_t uESld = sbase + 2 * (AP_ES + (wn + rowB) * ASH + kB);

    for (int ic = 0; ic < 128; ic++) {
        const int i0c = ic * 32;
        const int cur = ic & 1;
        asm volatile("cp.async.wait_group 0;\n");
        __syncthreads();
        if (ic + 1 < 128) {
            loadQ(cur ^ 1, i0c + 32);
            loadV(cur ^ 1, i0c + 32);
            asm volatile("cp.async.commit_group;\n");
        }
        // phase A: S'[j, i]
        const uint32_t uDQ = sbase + 2 * (AP_DQ + cur * 32 * ASH + rowB * ASH + kB);
        float sacc[4][4];
#pragma unroll
        for (int nt = 0; nt < 4; nt++)
#pragma unroll
            for (int e = 0; e < 4; e++) sacc[nt][e] = 0.f;
#pragma unroll
        for (int ks = 0; ks < 2; ks++) {
            int k0 = ks * 16;
            uint32_t a[4];
            ldsm4(a, uDKT + 2 * k0);
#pragma unroll
            for (int nt = 0; nt < 4; nt++) {
                uint32_t b0, b1;
                ldsm2(b0, b1, uDQ + 2 * (nt * 8 * ASH + k0));
                mma16h(sacc[nt], a, b0, b1);
            }
        }
        // exp * invZ -> eS via stmatrix
        uint32_t hh[4][2];
#pragma unroll
        for (int nt = 0; nt < 4; nt++) {
            int il = nt * 8 + 2 * t4;
            float iz0 = invZ[i0c + il];
            float iz1 = invZ[i0c + il + 1];
            __half2 h0 = __floats2half2_rn(__expf(sacc[nt][0]) * iz0,
                                           __expf(sacc[nt][1]) * iz1);
            __half2 h1 = __floats2half2_rn(__expf(sacc[nt][2]) * iz0,
                                           __expf(sacc[nt][3]) * iz1);
            hh[nt][0] = *(uint32_t*)&h0;
            hh[nt][1] = *(uint32_t*)&h1;
        }
        stsm4(uESst,      hh[0][0], hh[0][1], hh[1][0], hh[1][1]);
        stsm4(uESst + 32, hh[2][0], hh[2][1], hh[3][0], hh[3][1]);
        __syncthreads();
        // phase B: acc += V_tile @ eS
        const uint32_t uRV = sbase + 2 * (AP_RV + cur * 128 * ASH + (wm + rowA) * ASH + kA);
#pragma unroll
        for (int ks = 0; ks < 2; ks++) {
            int k0 = ks * 16;
            uint32_t af[4][4];
#pragma unroll
            for (int mt = 0; mt < 4; mt++)
                ldsm4(af[mt], uRV + 2 * (mt * 16 * ASH + k0));
#pragma unroll
            for (int nt = 0; nt < 4; nt++) {
                uint32_t b0, b1;
                ldsm2(b0, b1, uESld + 2 * (nt * 8 * ASH + k0));
#pragma unroll
                for (int mt = 0; mt < 4; mt++) mma16h(acc[mt][nt], af[mt], b0, b1);
            }
        }
    }
#pragma unroll
    for (int mt = 0; mt < 4; mt++)
#pragma unroll
        for (int nt = 0; nt < 4; nt++)
#pragma unroll
            for (int e = 0; e < 4; e++) {
                int row = wm + mt * 16 + g + (e >> 1) * 8;
                int col = j0 + wn + nt * 8 + 2 * t4 + (e & 1);
                size_t o = (size_t)row * HWP + col;
                out[o] = tf32f(acc[mt][nt][e] + res[o]);
            }
}

// ---------------- host launcher ----------------
extern "C" void kernel_launch(void* const* d_in, const int* in_sizes, int n_in,
                              void* d_out, int out_size)
{
    const float* rgb  = (const float*)d_in[0];
    const float* chm  = (const float*)d_in[1];
    float* out = (float*)d_out;

    float *invZ, *cat;
    float *wR, *wD, *bR, *bD, *wGate, *bHead;
    __half *projH, *qkT, *y1P, *wF1h, *wF2h, *wHeadH, *fyP;
    cudaGetSymbolAddress((void**)&projH, g_projH);
    cudaGetSymbolAddress((void**)&qkT, g_qkT);
    cudaGetSymbolAddress((void**)&invZ, g_invZ);
    cudaGetSymbolAddress((void**)&cat, g_cat);
    cudaGetSymbolAddress((void**)&fyP, g_fyP);
    cudaGetSymbolAddress((void**)&y1P, g_y1P);
    cudaGetSymbolAddress((void**)&wR, g_wR);
    cudaGetSymbolAddress((void**)&wD, g_wD);
    cudaGetSymbolAddress((void**)&bR, g_bR);
    cudaGetSymbolAddress((void**)&bD, g_bD);
    cudaGetSymbolAddress((void**)&wGate, g_wGate);
    cudaGetSymbolAddress((void**)&wF1h, g_wF1h);
    cudaGetSymbolAddress((void**)&wF2h, g_wF2h);
    cudaGetSymbolAddress((void**)&wHeadH, g_wHeadH);
    cudaGetSymbolAddress((void**)&bHead, g_bHead);

    cudaFuncSetAttribute(tgemm_k<P_PROJ>,  cudaFuncAttributeMaxDynamicSharedMemorySize, SMEM_BYTES);
    cudaFuncSetAttribute(tgemm_k<P_GATET>, cudaFuncAttributeMaxDynamicSharedMemorySize, SMEM_BYTES);

    dim3 blk(256);
    const size_t sX = (size_t)CC * HWP;
    const size_t sF = (size_t)C2 * HWP;
    const size_t sPH = (size_t)MPROJ * HWP;
    const size_t sFy = (size_t)HWP * 1024;
    const size_t sY1P = (size_t)PADN * C2;

    // --- prep + border zero ---
    PrepPtrs pp;
    pp.rq_w = (const float*)d_in[2];  pp.rq_b = (const float*)d_in[3];
    pp.rk_w = (const float*)d_in[4];  pp.rk_b = (const float*)d_in[5];
    pp.rv_w = (const float*)d_in[6];  pp.rv_b = (const float*)d_in[7];
    pp.dq_w = (const float*)d_in[8];  pp.dq_b = (const float*)d_in[9];
    pp.dk_w = (const float*)d_in[10]; pp.dk_b = (const float*)d_in[11];
    pp.dv_w = (const float*)d_in[12]; pp.dv_b = (const float*)d_in[13];
    pp.gate_w = (const float*)d_in[14];
    pp.fus1_w = (const float*)d_in[16];
    pp.fus2_w = (const float*)d_in[18];
    pp.fus3_w = (const float*)d_in[20]; pp.fus3_b = (const float*)d_in[21];
    pp.skip_w = (const float*)d_in[22]; pp.skip_b = (const float*)d_in[23];
    pp.wR = wR; pp.wD = wD; pp.wGate = wGate;
    pp.wF1h = wF1h; pp.wF2h = wF2h; pp.wHeadH = wHeadH;
    pp.bR = bR; pp.bD = bD; pp.bHead = bHead;
    prep_k<<<(PREP_TOT + 255) / 256, blk>>>(pp);
    zeroborder_k<<<(ZB_TOT + 255) / 256, blk>>>(y1P);

    const float* gate_b = (const float*)d_in[15];
    const float* fus1_b = (const float*)d_in[17];
    const float* fus2_b = (const float*)d_in[19];

    // --- projections (both modalities, fp16 output) ---
    tgemm_k<P_PROJ><<<dim3(32, 3, 4), blk, SMEM_BYTES>>>(
        wR, wD, CC, 0, rgb, chm, HWP, sX,
        (float*)projH, sPH, (size_t)NB * sPH, bR, bD, nullptr, 0, MPROJ, HWP, CC);

    // --- q/k transpose ---
    qkT_k<<<dim3(64, NB, 2), blk>>>(projH, qkT);

    // --- z pass ---
    attn_z_k<<<dim3(64, NB, 2), blk>>>(qkT, invZ);

    // --- fused apply ---
    attn_apply_k<<<dim3(32, 2, 4), blk>>>(qkT, projH, invZ, rgb, chm, cat);

    // --- gate GEMM + fused gated combine -> fyP[p][0:512] ---
    tgemm_k<P_GATET><<<dim3(32, 2, NB), blk, SMEM_BYTES>>>(
        wGate, nullptr, C2, 0, cat, nullptr, HWP, sF,
        (float*)fyP, sFy, 0, gate_b, nullptr, cat, sF, CC, HWP, C2);

    // --- fus1 -> padded pixel-major y1P ---
    hgemm_k<3><<<dim3(32, 4, NB), blk>>>(
        wF1h, fyP, 1024, sFy, y1P, sY1P, 0, fus1_b, HWP, C2);

    // --- fus2: implicit-GEMM conv -> fyP[p][512:1024] ---
    hgemm_k<1><<<dim3(32, 4, NB), blk>>>(
        wF2h, y1P, 0, sY1P, fyP, sFy, 512, fus2_b, HWP, KCOL);

    // --- head ---
    hgemm_k<2><<<dim3(32, 2, NB), blk>>>(
        wHeadH, fyP, 1024, sFy, out, sX, 0, bHead, HWP, 1024);

    (void)in_sizes; (void)n_in; (void)out_size;
}